// round 10
// baseline (speedup 1.0000x reference)
#include <cuda_runtime.h>
#include <cuda_bf16.h>
#include <cstdint>
#include <math.h>

#define NT      2048
#define DMODEL  2048
#define NHEAD   16
#define DHEAD   128
#define INNERD  2048
#define FFI     8192
#define VOCAB   32000
#define NLAYER  4
#define EPSF    1e-5f
#define MASKV   1e-10f
#define KT      32
#define ASTR    40     // [row][k] smem stride (elems)
#define BSTRN   136    // [k][n] smem stride, 128-col NN tiles
#define BSTRW   264    // [k][n] smem stride, 256-col NN tiles
#define L2E     1.4426950408889634f

typedef __nv_bfloat16 bf16;

// ---------------- scratch (static device globals; no allocations) ----------------
__device__ float g_x [NT * DMODEL];
__device__ bf16  g_hh[NT * DMODEL], g_hl[NT * DMODEL];
__device__ bf16  g_qh[NT * INNERD], g_ql[NT * INNERD];
__device__ float g_kv [NT * 256];
__device__ bf16  g_kvh[NT * 256], g_kvl[NT * 256];
__device__ float g_suf[NT * DHEAD];
__device__ float g_c  [NHEAD * NT];
__device__ float g_S [(size_t)NHEAD * NT * NT];
__device__ bf16  g_Ph[(size_t)NHEAD * NT * NT], g_Pl[(size_t)NHEAD * NT * NT];
__device__ bf16  g_aoh[NT * INNERD], g_aol[NT * INNERD];
__device__ float g_f1[NT * FFI], g_f2[NT * FFI];
__device__ bf16  g_f1h[NT * FFI], g_f1l[NT * FFI];
__device__ bf16 w_qh [NLAYER * DMODEL * INNERD], w_ql [NLAYER * DMODEL * INNERD];
__device__ bf16 w_kvh[NLAYER * DMODEL * 256],    w_kvl[NLAYER * DMODEL * 256];
__device__ bf16 w_oh [NLAYER * INNERD * DMODEL], w_ol [NLAYER * INNERD * DMODEL];
__device__ bf16 w_ih [(size_t)NLAYER * DMODEL * FFI], w_il [(size_t)NLAYER * DMODEL * FFI];
__device__ bf16 w_gh [(size_t)NLAYER * DMODEL * FFI], w_gl [(size_t)NLAYER * DMODEL * FFI];
__device__ bf16 w_foh[(size_t)NLAYER * FFI * DMODEL], w_fol[(size_t)NLAYER * FFI * DMODEL];
__device__ bf16 w_eh [(size_t)VOCAB * DMODEL], w_el [(size_t)VOCAB * DMODEL];

// ---------------- helpers ----------------
__device__ __forceinline__ void cpa16(uint32_t dst, const void* src) {
    asm volatile("cp.async.cg.shared.global [%0],[%1],16;" :: "r"(dst), "l"(src));
}
__device__ __forceinline__ void ldsm4(uint32_t* r, uint32_t a) {
    asm volatile("ldmatrix.sync.aligned.m8n8.x4.shared.b16 {%0,%1,%2,%3},[%4];"
                 : "=r"(r[0]), "=r"(r[1]), "=r"(r[2]), "=r"(r[3]) : "r"(a));
}
__device__ __forceinline__ void ldsm4t(uint32_t* r, uint32_t a) {
    asm volatile("ldmatrix.sync.aligned.m8n8.x4.trans.shared.b16 {%0,%1,%2,%3},[%4];"
                 : "=r"(r[0]), "=r"(r[1]), "=r"(r[2]), "=r"(r[3]) : "r"(a));
}
__device__ __forceinline__ void mma16816(float* c, const uint32_t* a, uint32_t b0, uint32_t b1) {
    asm volatile("mma.sync.aligned.m16n8k16.row.col.f32.bf16.bf16.f32 "
                 "{%0,%1,%2,%3},{%4,%5,%6,%7},{%8,%9},{%0,%1,%2,%3};"
                 : "+f"(c[0]), "+f"(c[1]), "+f"(c[2]), "+f"(c[3])
                 : "r"(a[0]), "r"(a[1]), "r"(a[2]), "r"(a[3]), "r"(b0), "r"(b1));
}
__device__ __forceinline__ void split1(float a, bf16& h, bf16& l) {
    h = __float2bfloat16_rn(a);
    l = __float2bfloat16_rn(a - __bfloat162float(h));
}
__device__ __forceinline__ void split2_store(bf16* hp, bf16* lp, float a, float b) {
    float ha = __bfloat162float(__float2bfloat16_rn(a));
    float hb = __bfloat162float(__float2bfloat16_rn(b));
    __nv_bfloat162 H = __floats2bfloat162_rn(a, b);
    __nv_bfloat162 L = __floats2bfloat162_rn(a - ha, b - hb);
    *(uint32_t*)hp = *(uint32_t*)&H;
    *(uint32_t*)lp = *(uint32_t*)&L;
}

// ---------------- fp32 -> bf16 pair ----------------
__global__ void __launch_bounds__(256) cvt_pair_kernel(const float* __restrict__ in,
                                                       bf16* __restrict__ ho, bf16* __restrict__ lo) {
    size_t i = (size_t)blockIdx.x * 256 + threadIdx.x;
    float4 v = ((const float4*)in)[i];
    bf16 h0, l0, h1, l1, h2, l2, h3, l3;
    split1(v.x, h0, l0); split1(v.y, h1, l1); split1(v.z, h2, l2); split1(v.w, h3, l3);
    __nv_bfloat162 ha = {h0, h1}, hb = {h2, h3}, la = {l0, l1}, lb = {l2, l3};
    uint2 H = {*(uint32_t*)&ha, *(uint32_t*)&hb};
    uint2 L = {*(uint32_t*)&la, *(uint32_t*)&lb};
    ((uint2*)ho)[i] = H;
    ((uint2*)lo)[i] = L;
}

__global__ void __launch_bounds__(256) cvt_pair_cols_kernel(const float* __restrict__ in,
                                                            bf16* __restrict__ ho, bf16* __restrict__ lo,
                                                            int colOff) {
    size_t i = (size_t)blockIdx.x * 256 + threadIdx.x;
    int row = (int)(i >> 5);
    int col = ((int)i & 31) * 4;
    float4 v = ((const float4*)in)[i];
    size_t o = (size_t)row * 256 + colOff + col;
    bf16 h0, l0, h1, l1, h2, l2, h3, l3;
    split1(v.x, h0, l0); split1(v.y, h1, l1); split1(v.z, h2, l2); split1(v.w, h3, l3);
    __nv_bfloat162 ha = {h0, h1}, hb = {h2, h3}, la = {l0, l1}, lb = {l2, l3};
    *(uint32_t*)(ho + o)     = *(uint32_t*)&ha;
    *(uint32_t*)(ho + o + 2) = *(uint32_t*)&hb;
    *(uint32_t*)(lo + o)     = *(uint32_t*)&la;
    *(uint32_t*)(lo + o + 2) = *(uint32_t*)&lb;
}

// ---------------- embedding ----------------
__global__ void embed_kernel(const int* __restrict__ tok, const float* __restrict__ emb,
                             float* __restrict__ x) {
    int n = blockIdx.x;
    const float* src = emb + (size_t)tok[n] * DMODEL;
    float* dst = x + (size_t)n * DMODEL;
    for (int d = threadIdx.x; d < DMODEL; d += blockDim.x) dst[d] = src[d];
}

// ---------------- RMSNorm -> bf16 pair ----------------
__global__ void __launch_bounds__(256) rmsnorm_pair_kernel(const float* __restrict__ x,
                                                           const float* __restrict__ gamma,
                                                           bf16* __restrict__ oh, bf16* __restrict__ ol) {
    int n = blockIdx.x;
    const float* row = x + (size_t)n * DMODEL;
    float s = 0.f;
    for (int d = threadIdx.x; d < DMODEL; d += 256) { float v = row[d]; s += v * v; }
    __shared__ float red[256];
    red[threadIdx.x] = s; __syncthreads();
    #pragma unroll
    for (int k = 128; k > 0; k >>= 1) {
        if (threadIdx.x < k) red[threadIdx.x] += red[threadIdx.x + k];
        __syncthreads();
    }
    float inv = rsqrtf(red[0] * (1.0f / DMODEL) + EPSF);
    for (int d = threadIdx.x; d < DMODEL; d += 256) {
        bf16 h, l; split1(row[d] * inv * gamma[d], h, l);
        oh[(size_t)n * DMODEL + d] = h;
        ol[(size_t)n * DMODEL + d] = l;
    }
}

// ---------------- SwiGLU -> bf16 pair ----------------
__global__ void __launch_bounds__(256) silu_pair_kernel(const float* __restrict__ a,
                                                        const float* __restrict__ b,
                                                        bf16* __restrict__ oh, bf16* __restrict__ ol) {
    size_t i = (size_t)blockIdx.x * 256 + threadIdx.x;
    float bb = b[i];
    bf16 h, l; split1(a[i] * bb / (1.f + __expf(-bb)), h, l);
    oh[i] = h; ol[i] = l;
}

// ---------------- suffixV ----------------
__global__ void __launch_bounds__(128) suffixv_kernel(const float* __restrict__ kv,
                                                      float* __restrict__ suf) {
    const int d = threadIdx.x;
    const int lo = blockIdx.x * 128, hi = lo + 128;
    float acc = 0.f;
    for (int j = NT - 1; j >= hi; --j)
        acc += kv[(size_t)j * 256 + 128 + d];
    for (int i = hi - 1; i >= lo; --i) {
        suf[(size_t)i * DHEAD + d] = acc;
        acc += kv[(size_t)i * 256 + 128 + d];
    }
}

// ------- softmax: visible region exact, masked region rank-1 -------
__global__ void __launch_bounds__(256) softmax_kernel(const float* __restrict__ S,
                                                      bf16* __restrict__ Ph, bf16* __restrict__ Pl,
                                                      float* __restrict__ C) {
    const int i = blockIdx.x, h = blockIdx.y, tid = threadIdx.x;
    const float* row = S + ((size_t)h * NT + i) * NT;
    __shared__ float sc[NT];
    __shared__ float red[256];
    const float slope = exp2f(-0.5f * (float)(h + 1));
    const float scale = 0.08838834764831845f;
    const int tileEnd = ((i >> 7) + 1) << 7;

    float mx = MASKV;
    for (int j = tid; j <= i; j += 256) {
        float v = row[j] * scale + slope * (float)j;
        sc[j] = v;
        mx = fmaxf(mx, v);
    }
    red[tid] = mx; __syncthreads();
    #pragma unroll
    for (int s = 128; s > 0; s >>= 1) {
        if (tid < s) red[tid] = fmaxf(red[tid], red[tid + s]);
        __syncthreads();
    }
    mx = red[0]; __syncthreads();

    float sum = 0.f;
    for (int j = tid; j <= i; j += 256) {
        float p = exp2f((sc[j] - mx) * L2E);
        sc[j] = p; sum += p;
    }
    red[tid] = sum; __syncthreads();
    #pragma unroll
    for (int s = 128; s > 0; s >>= 1) {
        if (tid < s) red[tid] += red[tid + s];
        __syncthreads();
    }
    const float maskexp = exp2f((MASKV - mx) * L2E);
    const float inv = 1.f / (red[0] + (float)(NT - 1 - i) * maskexp);
    const float c = maskexp * inv;
    if (tid == 0) C[(size_t)h * NT + i] = c;

    bf16* ph = Ph + ((size_t)h * NT + i) * NT;
    bf16* pl = Pl + ((size_t)h * NT + i) * NT;
    for (int j = tid; j < tileEnd; j += 256) {
        if (j <= i) {
            bf16 hh, ll; split1(sc[j] * inv, hh, ll);
            ph[j] = hh; pl[j] = ll;
        } else {
            ph[j] = __float2bfloat16_rn(0.f);
            pl[j] = __float2bfloat16_rn(0.f);
        }
    }
}

// ------- ao = pv + c*suffixV -> bf16 pair -------
__global__ void __launch_bounds__(256) ao_fix_kernel(const float* __restrict__ pv,
                                                     const float* __restrict__ C,
                                                     const float* __restrict__ suf,
                                                     bf16* __restrict__ oh, bf16* __restrict__ ol) {
    size_t idx = (size_t)blockIdx.x * 256 + threadIdx.x;
    int i = (int)(idx >> 11);
    int rem = (int)(idx & 2047);
    int h = rem >> 7, d = rem & 127;
    float v = pv[idx] + C[(size_t)h * NT + i] * suf[(size_t)i * DHEAD + d];
    bf16 hh, ll; split1(v, hh, ll);
    oh[idx] = hh; ol[idx] = ll;
}

// ================= 128x128 bf16-split GEMM (attention path) =================
// EPI: 0 store fp32, 2 atomicAdd (split-K). CAUSAL: 1 skip upper tiles; 2 cap K.
template <int TRANSB, int EPI, int CAUSAL>
__global__ void __launch_bounds__(256, 2)
gemm_bf3(const bf16* __restrict__ Ah, const bf16* __restrict__ Al,
         const bf16* __restrict__ Bh, const bf16* __restrict__ Bl,
         float* __restrict__ C, bf16* __restrict__ Ch, bf16* __restrict__ Cl,
         int M, int N, int K, int lda, int ldb, int ldc,
         int kSplit, size_t aZ, size_t bZ, size_t cZ) {
    extern __shared__ __align__(16) char smem[];
    const int tid = threadIdx.x, lane = tid & 31, warp = tid >> 5;
    const int wm = warp >> 2, wn = warp & 3;
    const int rowBase = blockIdx.y * 128, colBase = blockIdx.x * 128;
    if (CAUSAL == 1 && colBase > rowBase) return;
    const int z = blockIdx.z;
    int kStart = 0, kEnd = K;
    if (CAUSAL == 2) kEnd = rowBase + 128 < K ? rowBase + 128 : K;
    if (kSplit > 1) {
        int kl = K / kSplit; kStart = z * kl; kEnd = kStart + kl;
    } else {
        Ah += z * aZ; Al += z * aZ; Bh += z * bZ; Bl += z * bZ;
        if (EPI == 3) { Ch += z * cZ; Cl += z * cZ; } else { C += z * cZ; }
    }
    const int nk = (kEnd - kStart) / KT;
    const uint32_t sb = (uint32_t)__cvta_generic_to_shared(smem);
    const int BUFB = TRANSB ? 10240 : 8704;

    auto load_stage = [&](int s, int kt) {
        uint32_t aOff = sb + s * 20480;
        uint32_t bOff = sb + 40960 + s * 2 * BUFB;
        #pragma unroll
        for (int r = 0; r < 2; ++r) {
            int idx = tid + r * 256;
            int row = idx >> 2, kc = (idx & 3) * 8;
            uint32_t d = aOff + (row * ASTR + kc) * 2;
            const size_t ga = (size_t)(rowBase + row) * lda + kt + kc;
            cpa16(d,         Ah + ga);
            cpa16(d + 10240, Al + ga);
            if (!TRANSB) {
                int kr = idx >> 4, nc = (idx & 15) * 8;
                uint32_t db = bOff + (kr * BSTRN + nc) * 2;
                const size_t gb = (size_t)(kt + kr) * ldb + colBase + nc;
                cpa16(db,        Bh + gb);
                cpa16(db + BUFB, Bl + gb);
            } else {
                int nr = idx >> 2, kc2 = (idx & 3) * 8;
                uint32_t db = bOff + (nr * ASTR + kc2) * 2;
                const size_t gb = (size_t)(colBase + nr) * ldb + kt + kc2;
                cpa16(db,        Bh + gb);
                cpa16(db + BUFB, Bl + gb);
            }
        }
        asm volatile("cp.async.commit_group;");
    };

    float acc[4][4][4];
    #pragma unroll
    for (int i = 0; i < 4; ++i)
        #pragma unroll
        for (int j = 0; j < 4; ++j)
            #pragma unroll
            for (int v = 0; v < 4; ++v) acc[i][j][v] = 0.f;

    const int l15 = lane & 15, lhi = (lane >> 4) * 8;

    load_stage(0, kStart);

    for (int it = 0; it < nk; ++it) {
        const int s = it & 1;
        if (it + 1 < nk) {
            load_stage((it + 1) & 1, kStart + (it + 1) * KT);
            asm volatile("cp.async.wait_group 1;");
        } else {
            asm volatile("cp.async.wait_group 0;");
        }
        __syncthreads();

        const uint32_t aBase = sb + s * 20480 + ((wm * 64 + l15) * ASTR + lhi) * 2;
        const uint32_t bOff  = sb + 40960 + s * 2 * BUFB;

        #pragma unroll
        for (int ks = 0; ks < KT; ks += 16) {
            uint32_t aH[4][4], aL[4][4], bH[2][4], bL[2][4];
            #pragma unroll
            for (int mt = 0; mt < 4; ++mt)
                ldsm4(aH[mt], aBase + ks * 2 + mt * (16 * ASTR * 2));
            if (!TRANSB) {
                uint32_t bBase = bOff + ((l15 + ks) * BSTRN + wn * 32 + lhi) * 2;
                #pragma unroll
                for (int p = 0; p < 2; ++p) ldsm4t(bH[p], bBase + p * 32);
            } else {
                #pragma unroll
                for (int p = 0; p < 2; ++p)
                    ldsm4(bH[p], bOff + ((wn * 32 + p * 16 + l15) * ASTR + ks + lhi) * 2);
            }
            #pragma unroll
            for (int mt = 0; mt < 4; ++mt)
                #pragma unroll
                for (int nt = 0; nt < 4; ++nt) {
                    int p = nt >> 1, su = nt & 1;
                    uint32_t b0 = TRANSB ? bH[p][su]     : bH[p][2 * su];
                    uint32_t b1 = TRANSB ? bH[p][su + 2] : bH[p][2 * su + 1];
                    mma16816(acc[mt][nt], aH[mt], b0, b1);
                }
            if (!TRANSB) {
                uint32_t bBase = bOff + BUFB + ((l15 + ks) * BSTRN + wn * 32 + lhi) * 2;
                #pragma unroll
                for (int p = 0; p < 2; ++p) ldsm4t(bL[p], bBase + p * 32);
            } else {
                #pragma unroll
                for (int p = 0; p < 2; ++p)
                    ldsm4(bL[p], bOff + BUFB + ((wn * 32 + p * 16 + l15) * ASTR + ks + lhi) * 2);
            }
            #pragma unroll
            for (int mt = 0; mt < 4; ++mt)
                #pragma unroll
                for (int nt = 0; nt < 4; ++nt) {
                    int p = nt >> 1, su = nt & 1;
                    uint32_t b0 = TRANSB ? bL[p][su]     : bL[p][2 * su];
                    uint32_t b1 = TRANSB ? bL[p][su + 2] : bL[p][2 * su + 1];
                    mma16816(acc[mt][nt], aH[mt], b0, b1);
                }
            #pragma unroll
            for (int mt = 0; mt < 4; ++mt)
                ldsm4(aL[mt], aBase + 10240 + ks * 2 + mt * (16 * ASTR * 2));
            #pragma unroll
            for (int mt = 0; mt < 4; ++mt)
                #pragma unroll
                for (int nt = 0; nt < 4; ++nt) {
                    int p = nt >> 1, su = nt & 1;
                    uint32_t b0 = TRANSB ? bH[p][su]     : bH[p][2 * su];
                    uint32_t b1 = TRANSB ? bH[p][su + 2] : bH[p][2 * su + 1];
                    mma16816(acc[mt][nt], aL[mt], b0, b1);
                }
        }
        __syncthreads();
    }

    const int r0 = rowBase + wm * 64 + (lane >> 2);
    const int c0 = colBase + wn * 32 + (lane & 3) * 2;
    #pragma unroll
    for (int mt = 0; mt < 4; ++mt) {
        #pragma unroll
        for (int nt = 0; nt < 4; ++nt) {
            int r = r0 + mt * 16, c = c0 + nt * 8;
            if (EPI == 2) {
                atomicAdd(C + (size_t)r * ldc + c,           acc[mt][nt][0]);
                atomicAdd(C + (size_t)r * ldc + c + 1,       acc[mt][nt][1]);
                atomicAdd(C + (size_t)(r + 8) * ldc + c,     acc[mt][nt][2]);
                atomicAdd(C + (size_t)(r + 8) * ldc + c + 1, acc[mt][nt][3]);
            } else {
                *(float2*)(C + (size_t)r * ldc + c)       = make_float2(acc[mt][nt][0], acc[mt][nt][1]);
                *(float2*)(C + (size_t)(r + 8) * ldc + c) = make_float2(acc[mt][nt][2], acc[mt][nt][3]);
            }
        }
    }
}

// ================= 128x256 wide-tile GEMM (dense path, warp tile 64x64) ======
// EPI: 0 store fp32, 1 fp32 +=, 3 bf16 pair store.
template <int TRANSB, int EPI>
__global__ void __launch_bounds__(256, 1)
gemm_wide(const bf16* __restrict__ Ah, const bf16* __restrict__ Al,
          const bf16* __restrict__ Bh, const bf16* __restrict__ Bl,
          float* __restrict__ C, bf16* __restrict__ Ch, bf16* __restrict__ Cl,
          int M, int N, int K, int lda, int ldb, int ldc) {
    extern __shared__ __align__(16) char smem[];
    const int tid = threadIdx.x, lane = tid & 31, warp = tid >> 5;
    const int wm = warp >> 2, wn = warp & 3;
    const int rowBase = blockIdx.y * 128, colBase = blockIdx.x * 256;
    const uint32_t sb = (uint32_t)__cvta_generic_to_shared(smem);
    const int BUFB = TRANSB ? 20480 : 16896;    // 256 rows * 40 or 32 rows * 264 (x2B)
    const int nk = K / KT;
    const int l15 = lane & 15, lhi = (lane >> 4) * 8;

    auto load_stage = [&](int s, int kt) {
        uint32_t aOff = sb + s * 20480;
        uint32_t bOff = sb + 40960 + s * 2 * BUFB;
        #pragma unroll
        for (int r = 0; r < 2; ++r) {           // A: 512 cpa16 per half
            int idx = tid + r * 256;
            int row = idx >> 2, kc = (idx & 3) * 8;
            uint32_t d = aOff + (row * ASTR + kc) * 2;
            const size_t ga = (size_t)(rowBase + row) * lda + kt + kc;
            cpa16(d,         Ah + ga);
            cpa16(d + 10240, Al + ga);
        }
        #pragma unroll
        for (int r = 0; r < 4; ++r) {           // B: 1024 cpa16 per half
            int idx = tid + r * 256;
            if (!TRANSB) {
                int kr = idx >> 5, nc = (idx & 31) * 8;
                uint32_t db = bOff + (kr * BSTRW + nc) * 2;
                const size_t gb = (size_t)(kt + kr) * ldb + colBase + nc;
                cpa16(db,        Bh + gb);
                cpa16(db + BUFB, Bl + gb);
            } else {
                int nr = idx >> 2, kc2 = (idx & 3) * 8;
                uint32_t db = bOff + (nr * ASTR + kc2) * 2;
                const size_t gb = (size_t)(colBase + nr) * ldb + kt + kc2;
                cpa16(db,        Bh + gb);
                cpa16(db + BUFB, Bl + gb);
            }
        }
        asm volatile("cp.async.commit_group;");
    };

    float acc[4][8][4];
    #pragma unroll
    for (int i = 0; i < 4; ++i)
        #pragma unroll
        for (int j = 0; j < 8; ++j)
            #pragma unroll
            for (int v = 0; v < 4; ++v) acc[i][j][v] = 0.f;

    load_stage(0, 0);

    for (int it = 0; it < nk; ++it) {
        const int s = it & 1;
        if (it + 1 < nk) {
            load_stage((it + 1) & 1, (it + 1) * KT);
            asm volatile("cp.async.wait_group 1;");
        } else {
            asm volatile("cp.async.wait_group 0;");
        }
        __syncthreads();

        const uint32_t aBase = sb + s * 20480 + ((wm * 64 + l15) * ASTR + lhi) * 2;
        const uint32_t bOff  = sb + 40960 + s * 2 * BUFB;

        #pragma unroll
        for (int ks = 0; ks < KT; ks += 16) {
            uint32_t aH[4][4], aL[4][4], bH[4][4], bL[4][4];
            #pragma unroll
            for (int mt = 0; mt < 4; ++mt)
                ldsm4(aH[mt], aBase + ks * 2 + mt * (16 * ASTR * 2));
            if (!TRANSB) {
                uint32_t bBase = bOff + ((l15 + ks) * BSTRW + wn * 64 + lhi) * 2;
                #pragma unroll
                for (int p = 0; p < 4; ++p) ldsm4t(bH[p], bBase + p * 32);
            } else {
                #pragma unroll
                for (int p = 0; p < 4; ++p)
                    ldsm4(bH[p], bOff + ((wn * 64 + p * 16 + l15) * ASTR + ks + lhi) * 2);
            }
            #pragma unroll
            for (int mt = 0; mt < 4; ++mt)
                #pragma unroll
                for (int nt = 0; nt < 8; ++nt) {
                    int p = nt >> 1, su = nt & 1;
                    uint32_t b0 = TRANSB ? bH[p][su]     : bH[p][2 * su];
                    uint32_t b1 = TRANSB ? bH[p][su + 2] : bH[p][2 * su + 1];
                    mma16816(acc[mt][nt], aH[mt], b0, b1);
                }
            if (!TRANSB) {
                uint32_t bBase = bOff + BUFB + ((l15 + ks) * BSTRW + wn * 64 + lhi) * 2;
                #pragma unroll
                for (int p = 0; p < 4; ++p) ldsm4t(bL[p], bBase + p * 32);
            } else {
                #pragma unroll
                for (int p = 0; p < 4; ++p)
                    ldsm4(bL[p], bOff + BUFB + ((wn * 64 + p * 16 + l15) * ASTR + ks + lhi) * 2);
            }
            #pragma unroll
            for (int mt = 0; mt < 4; ++mt)
                #pragma unroll
                for (int nt = 0; nt < 8; ++nt) {
                    int p = nt >> 1, su = nt & 1;
                    uint32_t b0 = TRANSB ? bL[p][su]     : bL[p][2 * su];
                    uint32_t b1 = TRANSB ? bL[p][su + 2] : bL[p][2 * su + 1];
                    mma16816(acc[mt][nt], aH[mt], b0, b1);
                }
            #pragma unroll
            for (int mt = 0; mt < 4; ++mt)
                ldsm4(aL[mt], aBase + 10240 + ks * 2 + mt * (16 * ASTR * 2));
            #pragma unroll
            for (int mt = 0; mt < 4; ++mt)
                #pragma unroll
                for (int nt = 0; nt < 8; ++nt) {
                    int p = nt >> 1, su = nt & 1;
                    uint32_t b0 = TRANSB ? bH[p][su]     : bH[p][2 * su];
                    uint32_t b1 = TRANSB ? bH[p][su + 2] : bH[p][2 * su + 1];
                    mma16816(acc[mt][nt], aL[mt], b0, b1);
                }
        }
        __syncthreads();
    }

    const int r0 = rowBase + wm * 64 + (lane >> 2);
    const int c0 = colBase + wn * 64 + (lane & 3) * 2;
    #pragma unroll
    for (int mt = 0; mt < 4; ++mt) {
        #pragma unroll
        for (int nt = 0; nt < 8; ++nt) {
            int r = r0 + mt * 16, c = c0 + nt * 8;
            if (EPI == 3) {
                split2_store(Ch + (size_t)r * ldc + c,       Cl + (size_t)r * ldc + c,
                             acc[mt][nt][0], acc[mt][nt][1]);
                split2_store(Ch + (size_t)(r + 8) * ldc + c, Cl + (size_t)(r + 8) * ldc + c,
                             acc[mt][nt][2], acc[mt][nt][3]);
            } else {
                float2* p0 = (float2*)(C + (size_t)r * ldc + c);
                float2* p1 = (float2*)(C + (size_t)(r + 8) * ldc + c);
                if (EPI == 1) {
                    float2 t0 = *p0, t1 = *p1;
                    t0.x += acc[mt][nt][0]; t0.y += acc[mt][nt][1];
                    t1.x += acc[mt][nt][2]; t1.y += acc[mt][nt][3];
                    *p0 = t0; *p1 = t1;
                } else {
                    *p0 = make_float2(acc[mt][nt][0], acc[mt][nt][1]);
                    *p1 = make_float2(acc[mt][nt][2], acc[mt][nt][3]);
                }
            }
        }
    }
}

// ---------------- host-side dispatch ----------------
template <int TRANSB, int EPI, int CAUSAL>
static void launch_gemm(const bf16* Ah, const bf16* Al, const bf16* Bh, const bf16* Bl,
                        float* C, bf16* Ch, bf16* Cl,
                        int M, int N, int K, int lda, int ldb, int ldc,
                        int Z, int kSplit, size_t aZ, size_t bZ, size_t cZ) {
    const int smem = 40960 + 4 * (TRANSB ? 10240 : 8704);
    cudaFuncSetAttribute(gemm_bf3<TRANSB, EPI, CAUSAL>, cudaFuncAttributeMaxDynamicSharedMemorySize, smem);
    dim3 grid(N / 128, M / 128, Z);
    gemm_bf3<TRANSB, EPI, CAUSAL><<<grid, 256, smem>>>(Ah, Al, Bh, Bl, C, Ch, Cl,
                                                       M, N, K, lda, ldb, ldc, kSplit, aZ, bZ, cZ);
}

template <int TRANSB, int EPI>
static void launch_wide(const bf16* Ah, const bf16* Al, const bf16* Bh, const bf16* Bl,
                        float* C, bf16* Ch, bf16* Cl,
                        int M, int N, int K, int lda, int ldb, int ldc) {
    const int smem = 40960 + 4 * (TRANSB ? 20480 : 16896);
    cudaFuncSetAttribute(gemm_wide<TRANSB, EPI>, cudaFuncAttributeMaxDynamicSharedMemorySize, smem);
    dim3 grid(N / 256, M / 128);
    gemm_wide<TRANSB, EPI><<<grid, 256, smem>>>(Ah, Al, Bh, Bl, C, Ch, Cl, M, N, K, lda, ldb, ldc);
}

extern "C" void kernel_launch(void* const* d_in, const int* in_sizes, int n_in,
                              void* d_out, int out_size) {
    const int*   tokens      = (const int*)  d_in[0];
    const float* emb         = (const float*)d_in[1];
    const float* attn_gamma  = (const float*)d_in[2];
    const float* wq          = (const float*)d_in[3];
    const float* wk          = (const float*)d_in[4];
    const float* wv          = (const float*)d_in[5];
    const float* wo          = (const float*)d_in[6];
    const float* ff_gamma    = (const float*)d_in[7];
    const float* wi          = (const float*)d_in[8];
    const float* wg          = (const float*)d_in[9];
    const float* wfo         = (const float*)d_in[10];
    const float* final_gamma = (const float*)d_in[11];
    float* out = (float*)d_out;

    float *x, *kv, *suf, *c, *S, *f1, *f2;
    bf16 *hh, *hl, *qh, *ql, *kvh, *kvl, *Ph, *Pl, *aoh, *aol, *f1h, *f1l;
    bf16 *Wqh, *Wql, *Wkvh, *Wkvl, *Woh, *Wol, *Wih, *Wil, *Wgh, *Wgl, *Wfoh, *Wfol, *Weh, *Wel;
    cudaGetSymbolAddress((void**)&x,    g_x);
    cudaGetSymbolAddress((void**)&hh,   g_hh);  cudaGetSymbolAddress((void**)&hl,  g_hl);
    cudaGetSymbolAddress((void**)&qh,   g_qh);  cudaGetSymbolAddress((void**)&ql,  g_ql);
    cudaGetSymbolAddress((void**)&kv,   g_kv);
    cudaGetSymbolAddress((void**)&kvh,  g_kvh); cudaGetSymbolAddress((void**)&kvl, g_kvl);
    cudaGetSymbolAddress((void**)&suf,  g_suf); cudaGetSymbolAddress((void**)&c,   g_c);
    cudaGetSymbolAddress((void**)&S,    g_S);
    cudaGetSymbolAddress((void**)&Ph,   g_Ph);  cudaGetSymbolAddress((void**)&Pl,  g_Pl);
    cudaGetSymbolAddress((void**)&aoh,  g_aoh); cudaGetSymbolAddress((void**)&aol, g_aol);
    cudaGetSymbolAddress((void**)&f1,   g_f1);  cudaGetSymbolAddress((void**)&f2,  g_f2);
    cudaGetSymbolAddress((void**)&f1h,  g_f1h); cudaGetSymbolAddress((void**)&f1l, g_f1l);
    cudaGetSymbolAddress((void**)&Wqh,  w_qh);  cudaGetSymbolAddress((void**)&Wql, w_ql);
    cudaGetSymbolAddress((void**)&Wkvh, w_kvh); cudaGetSymbolAddress((void**)&Wkvl, w_kvl);
    cudaGetSymbolAddress((void**)&Woh,  w_oh);  cudaGetSymbolAddress((void**)&Wol, w_ol);
    cudaGetSymbolAddress((void**)&Wih,  w_ih);  cudaGetSymbolAddress((void**)&Wil, w_il);
    cudaGetSymbolAddress((void**)&Wgh,  w_gh);  cudaGetSymbolAddress((void**)&Wgl, w_gl);
    cudaGetSymbolAddress((void**)&Wfoh, w_foh); cudaGetSymbolAddress((void**)&Wfol, w_fol);
    cudaGetSymbolAddress((void**)&Weh,  w_eh);  cudaGetSymbolAddress((void**)&Wel, w_el);

    auto cvt = [](const float* in, bf16* h, bf16* l, size_t n) {
        cvt_pair_kernel<<<(unsigned)(n / 1024), 256>>>(in, h, l);
    };

    // ---- weight pre-split ----
    cvt(wq,  Wqh,  Wql,  (size_t)NLAYER * DMODEL * INNERD);
    cvt(wo,  Woh,  Wol,  (size_t)NLAYER * INNERD * DMODEL);
    cvt(wi,  Wih,  Wil,  (size_t)NLAYER * DMODEL * FFI);
    cvt(wg,  Wgh,  Wgl,  (size_t)NLAYER * DMODEL * FFI);
    cvt(wfo, Wfoh, Wfol, (size_t)NLAYER * FFI * DMODEL);
    cvt(emb, Weh,  Wel,  (size_t)VOCAB * DMODEL);
    for (int l = 0; l < NLAYER; ++l) {
        const size_t okv = (size_t)l * DMODEL * DHEAD;
        const size_t okvW = (size_t)l * DMODEL * 256;
        cvt_pair_cols_kernel<<<(DMODEL * DHEAD) / 1024, 256>>>(wk + okv, Wkvh + okvW, Wkvl + okvW, 0);
        cvt_pair_cols_kernel<<<(DMODEL * DHEAD) / 1024, 256>>>(wv + okv, Wkvh + okvW, Wkvl + okvW, 128);
    }

    embed_kernel<<<NT, 256>>>(tokens, emb, x);

    for (int l = 0; l < NLAYER; ++l) {
        const size_t oq   = (size_t)l * DMODEL * INNERD;
        const size_t okvW = (size_t)l * DMODEL * 256;
        const size_t oi   = (size_t)l * DMODEL * FFI;
        const size_t ofo  = (size_t)l * FFI * DMODEL;

        // --- attention ---
        rmsnorm_pair_kernel<<<NT, 256>>>(x, attn_gamma + (size_t)l * DMODEL, hh, hl);
        launch_wide<0, 3>(hh, hl, Wqh + oq, Wql + oq, nullptr, qh, ql,
                          NT, INNERD, DMODEL, DMODEL, INNERD, INNERD);
        cudaMemsetAsync(kv, 0, NT * 256 * sizeof(float));
        launch_gemm<0, 2, 0>(hh, hl, Wkvh + okvW, Wkvl + okvW, kv, nullptr, nullptr,
                             NT, 256, DMODEL, DMODEL, 256, 256, 8, 8, 0, 0, 0);
        cvt(kv, kvh, kvl, (size_t)NT * 256);
        suffixv_kernel<<<NT / 128, 128>>>(kv, suf);
        launch_gemm<1, 0, 1>(qh, ql, kvh, kvl, S, nullptr, nullptr,
                             NT, NT, DHEAD, INNERD, 256, NT,
                             NHEAD, 1, (size_t)DHEAD, 0, (size_t)NT * NT);
        softmax_kernel<<<dim3(NT, NHEAD), 256>>>(S, Ph, Pl, c);
        launch_gemm<0, 0, 2>(Ph, Pl, kvh + 128, kvl + 128, f1, nullptr, nullptr,
                             NT, DHEAD, NT, NT, 256, INNERD,
                             NHEAD, 1, (size_t)NT * NT, 0, (size_t)DHEAD);
        ao_fix_kernel<<<(NT * INNERD) / 256, 256>>>(f1, c, suf, aoh, aol);
        launch_wide<0, 1>(aoh, aol, Woh + oq, Wol + oq, x, nullptr, nullptr,
                          NT, DMODEL, INNERD, INNERD, DMODEL, DMODEL);

        // --- SwiGLU FFN ---
        rmsnorm_pair_kernel<<<NT, 256>>>(x, ff_gamma + (size_t)l * DMODEL, hh, hl);
        launch_wide<0, 0>(hh, hl, Wih + oi, Wil + oi, f1, nullptr, nullptr,
                          NT, FFI, DMODEL, DMODEL, FFI, FFI);
        launch_wide<0, 0>(hh, hl, Wgh + oi, Wgl + oi, f2, nullptr, nullptr,
                          NT, FFI, DMODEL, DMODEL, FFI, FFI);
        silu_pair_kernel<<<(NT * FFI) / 256, 256>>>(f1, f2, f1h, f1l);
        launch_wide<0, 1>(f1h, f1l, Wfoh + ofo, Wfol + ofo, x, nullptr, nullptr,
                          NT, DMODEL, FFI, FFI, DMODEL, DMODEL);
    }

    // --- final norm + tied-embedding logits ---
    rmsnorm_pair_kernel<<<NT, 256>>>(x, final_gamma, hh, hl);
    launch_wide<1, 0>(hh, hl, Weh, Wel, out, nullptr, nullptr,
                      NT, VOCAB, DMODEL, DMODEL, DMODEL, VOCAB);
}

// round 11
// speedup vs baseline: 1.0752x; 1.0752x over previous
#include <cuda_runtime.h>
#include <cuda_bf16.h>
#include <cstdint>
#include <math.h>

#define NT      2048
#define DMODEL  2048
#define NHEAD   16
#define DHEAD   128
#define INNERD  2048
#define FFI     8192
#define VOCAB   32000
#define NLAYER  4
#define EPSF    1e-5f
#define MASKV   1e-10f
#define KT      32
#define ASTR    40     // [row][k] smem stride (elems)
#define BSTRN   136    // [k][n] smem stride (elems) for NN B tiles
#define L2E     1.4426950408889634f

typedef __nv_bfloat16 bf16;

// ---------------- scratch (static device globals; no allocations) ----------------
__device__ float g_x [NT * DMODEL];
__device__ bf16  g_hh[NT * DMODEL], g_hl[NT * DMODEL];
__device__ bf16  g_qh[NT * INNERD], g_ql[NT * INNERD];
__device__ float g_kv [NT * 256];
__device__ bf16  g_kvh[NT * 256], g_kvl[NT * 256];
__device__ float g_suf[NT * DHEAD];
__device__ float g_c  [NHEAD * NT];
__device__ float g_S [(size_t)NHEAD * NT * NT];
__device__ bf16  g_Ph[(size_t)NHEAD * NT * NT], g_Pl[(size_t)NHEAD * NT * NT];
__device__ bf16  g_aoh[NT * INNERD], g_aol[NT * INNERD];
__device__ float g_f1[NT * FFI], g_f2[NT * FFI];
__device__ bf16  g_f1h[NT * FFI], g_f1l[NT * FFI];
__device__ bf16 w_qh [NLAYER * DMODEL * INNERD], w_ql [NLAYER * DMODEL * INNERD];
__device__ bf16 w_kvh[NLAYER * DMODEL * 256],    w_kvl[NLAYER * DMODEL * 256];
__device__ bf16 w_oh [NLAYER * INNERD * DMODEL], w_ol [NLAYER * INNERD * DMODEL];
__device__ bf16 w_ih [(size_t)NLAYER * DMODEL * FFI], w_il [(size_t)NLAYER * DMODEL * FFI];
__device__ bf16 w_gh [(size_t)NLAYER * DMODEL * FFI], w_gl [(size_t)NLAYER * DMODEL * FFI];
__device__ bf16 w_foh[(size_t)NLAYER * FFI * DMODEL], w_fol[(size_t)NLAYER * FFI * DMODEL];
__device__ bf16 w_eh [(size_t)VOCAB * DMODEL], w_el [(size_t)VOCAB * DMODEL];

// ---------------- helpers ----------------
__device__ __forceinline__ void cpa16(uint32_t dst, const void* src) {
    asm volatile("cp.async.cg.shared.global [%0],[%1],16;" :: "r"(dst), "l"(src));
}
__device__ __forceinline__ void ldsm4(uint32_t* r, uint32_t a) {
    asm volatile("ldmatrix.sync.aligned.m8n8.x4.shared.b16 {%0,%1,%2,%3},[%4];"
                 : "=r"(r[0]), "=r"(r[1]), "=r"(r[2]), "=r"(r[3]) : "r"(a));
}
__device__ __forceinline__ void ldsm4t(uint32_t* r, uint32_t a) {
    asm volatile("ldmatrix.sync.aligned.m8n8.x4.trans.shared.b16 {%0,%1,%2,%3},[%4];"
                 : "=r"(r[0]), "=r"(r[1]), "=r"(r[2]), "=r"(r[3]) : "r"(a));
}
__device__ __forceinline__ void mma16816(float* c, const uint32_t* a, uint32_t b0, uint32_t b1) {
    asm volatile("mma.sync.aligned.m16n8k16.row.col.f32.bf16.bf16.f32 "
                 "{%0,%1,%2,%3},{%4,%5,%6,%7},{%8,%9},{%0,%1,%2,%3};"
                 : "+f"(c[0]), "+f"(c[1]), "+f"(c[2]), "+f"(c[3])
                 : "r"(a[0]), "r"(a[1]), "r"(a[2]), "r"(a[3]), "r"(b0), "r"(b1));
}
__device__ __forceinline__ void split1(float a, bf16& h, bf16& l) {
    h = __float2bfloat16_rn(a);
    l = __float2bfloat16_rn(a - __bfloat162float(h));
}
__device__ __forceinline__ void split2_store(bf16* hp, bf16* lp, float a, float b) {
    float ha = __bfloat162float(__float2bfloat16_rn(a));
    float hb = __bfloat162float(__float2bfloat16_rn(b));
    __nv_bfloat162 H = __floats2bfloat162_rn(a, b);
    __nv_bfloat162 L = __floats2bfloat162_rn(a - ha, b - hb);
    *(uint32_t*)hp = *(uint32_t*)&H;
    *(uint32_t*)lp = *(uint32_t*)&L;
}

// ---------------- fp32 -> bf16 pair ----------------
__global__ void __launch_bounds__(256) cvt_pair_kernel(const float* __restrict__ in,
                                                       bf16* __restrict__ ho, bf16* __restrict__ lo) {
    size_t i = (size_t)blockIdx.x * 256 + threadIdx.x;
    float4 v = ((const float4*)in)[i];
    bf16 h0, l0, h1, l1, h2, l2, h3, l3;
    split1(v.x, h0, l0); split1(v.y, h1, l1); split1(v.z, h2, l2); split1(v.w, h3, l3);
    __nv_bfloat162 ha = {h0, h1}, hb = {h2, h3}, la = {l0, l1}, lb = {l2, l3};
    uint2 H = {*(uint32_t*)&ha, *(uint32_t*)&hb};
    uint2 L = {*(uint32_t*)&la, *(uint32_t*)&lb};
    ((uint2*)ho)[i] = H;
    ((uint2*)lo)[i] = L;
}

__global__ void __launch_bounds__(256) cvt_pair_cols_kernel(const float* __restrict__ in,
                                                            bf16* __restrict__ ho, bf16* __restrict__ lo,
                                                            int colOff) {
    size_t i = (size_t)blockIdx.x * 256 + threadIdx.x;
    int row = (int)(i >> 5);
    int col = ((int)i & 31) * 4;
    float4 v = ((const float4*)in)[i];
    size_t o = (size_t)row * 256 + colOff + col;
    bf16 h0, l0, h1, l1, h2, l2, h3, l3;
    split1(v.x, h0, l0); split1(v.y, h1, l1); split1(v.z, h2, l2); split1(v.w, h3, l3);
    __nv_bfloat162 ha = {h0, h1}, hb = {h2, h3}, la = {l0, l1}, lb = {l2, l3};
    *(uint32_t*)(ho + o)     = *(uint32_t*)&ha;
    *(uint32_t*)(ho + o + 2) = *(uint32_t*)&hb;
    *(uint32_t*)(lo + o)     = *(uint32_t*)&la;
    *(uint32_t*)(lo + o + 2) = *(uint32_t*)&lb;
}

// ---------------- embedding ----------------
__global__ void embed_kernel(const int* __restrict__ tok, const float* __restrict__ emb,
                             float* __restrict__ x) {
    int n = blockIdx.x;
    const float* src = emb + (size_t)tok[n] * DMODEL;
    float* dst = x + (size_t)n * DMODEL;
    for (int d = threadIdx.x; d < DMODEL; d += blockDim.x) dst[d] = src[d];
}

// ---------------- RMSNorm -> bf16 pair ----------------
__global__ void __launch_bounds__(256) rmsnorm_pair_kernel(const float* __restrict__ x,
                                                           const float* __restrict__ gamma,
                                                           bf16* __restrict__ oh, bf16* __restrict__ ol) {
    int n = blockIdx.x;
    const float* row = x + (size_t)n * DMODEL;
    float s = 0.f;
    for (int d = threadIdx.x; d < DMODEL; d += 256) { float v = row[d]; s += v * v; }
    __shared__ float red[256];
    red[threadIdx.x] = s; __syncthreads();
    #pragma unroll
    for (int k = 128; k > 0; k >>= 1) {
        if (threadIdx.x < k) red[threadIdx.x] += red[threadIdx.x + k];
        __syncthreads();
    }
    float inv = rsqrtf(red[0] * (1.0f / DMODEL) + EPSF);
    for (int d = threadIdx.x; d < DMODEL; d += 256) {
        bf16 h, l; split1(row[d] * inv * gamma[d], h, l);
        oh[(size_t)n * DMODEL + d] = h;
        ol[(size_t)n * DMODEL + d] = l;
    }
}

// ---------------- SwiGLU -> bf16 pair ----------------
__global__ void __launch_bounds__(256) silu_pair_kernel(const float* __restrict__ a,
                                                        const float* __restrict__ b,
                                                        bf16* __restrict__ oh, bf16* __restrict__ ol) {
    size_t i = (size_t)blockIdx.x * 256 + threadIdx.x;
    float bb = b[i];
    bf16 h, l; split1(a[i] * bb / (1.f + __expf(-bb)), h, l);
    oh[i] = h; ol[i] = l;
}

// ---------------- suffixV ----------------
__global__ void __launch_bounds__(128) suffixv_kernel(const float* __restrict__ kv,
                                                      float* __restrict__ suf) {
    const int d = threadIdx.x;
    const int lo = blockIdx.x * 128, hi = lo + 128;
    float acc = 0.f;
    for (int j = NT - 1; j >= hi; --j)
        acc += kv[(size_t)j * 256 + 128 + d];
    for (int i = hi - 1; i >= lo; --i) {
        suf[(size_t)i * DHEAD + d] = acc;
        acc += kv[(size_t)i * 256 + 128 + d];
    }
}

// ------- softmax: visible region exact, masked region rank-1 -------
__global__ void __launch_bounds__(256) softmax_kernel(const float* __restrict__ S,
                                                      bf16* __restrict__ Ph, bf16* __restrict__ Pl,
                                                      float* __restrict__ C) {
    const int i = blockIdx.x, h = blockIdx.y, tid = threadIdx.x;
    const float* row = S + ((size_t)h * NT + i) * NT;
    __shared__ float sc[NT];
    __shared__ float red[256];
    const float slope = exp2f(-0.5f * (float)(h + 1));
    const float scale = 0.08838834764831845f;
    const int tileEnd = ((i >> 7) + 1) << 7;

    float mx = MASKV;
    for (int j = tid; j <= i; j += 256) {
        float v = row[j] * scale + slope * (float)j;
        sc[j] = v;
        mx = fmaxf(mx, v);
    }
    red[tid] = mx; __syncthreads();
    #pragma unroll
    for (int s = 128; s > 0; s >>= 1) {
        if (tid < s) red[tid] = fmaxf(red[tid], red[tid + s]);
        __syncthreads();
    }
    mx = red[0]; __syncthreads();

    float sum = 0.f;
    for (int j = tid; j <= i; j += 256) {
        float p = exp2f((sc[j] - mx) * L2E);
        sc[j] = p; sum += p;
    }
    red[tid] = sum; __syncthreads();
    #pragma unroll
    for (int s = 128; s > 0; s >>= 1) {
        if (tid < s) red[tid] += red[tid + s];
        __syncthreads();
    }
    const float maskexp = exp2f((MASKV - mx) * L2E);
    const float inv = 1.f / (red[0] + (float)(NT - 1 - i) * maskexp);
    const float c = maskexp * inv;
    if (tid == 0) C[(size_t)h * NT + i] = c;

    bf16* ph = Ph + ((size_t)h * NT + i) * NT;
    bf16* pl = Pl + ((size_t)h * NT + i) * NT;
    for (int j = tid; j < tileEnd; j += 256) {
        if (j <= i) {
            bf16 hh, ll; split1(sc[j] * inv, hh, ll);
            ph[j] = hh; pl[j] = ll;
        } else {
            ph[j] = __float2bfloat16_rn(0.f);
            pl[j] = __float2bfloat16_rn(0.f);
        }
    }
}

// ------- ao = pv + c*suffixV -> bf16 pair -------
__global__ void __launch_bounds__(256) ao_fix_kernel(const float* __restrict__ pv,
                                                     const float* __restrict__ C,
                                                     const float* __restrict__ suf,
                                                     bf16* __restrict__ oh, bf16* __restrict__ ol) {
    size_t idx = (size_t)blockIdx.x * 256 + threadIdx.x;
    int i = (int)(idx >> 11);
    int rem = (int)(idx & 2047);
    int h = rem >> 7, d = rem & 127;
    float v = pv[idx] + C[(size_t)h * NT + i] * suf[(size_t)i * DHEAD + d];
    bf16 hh, ll; split1(v, hh, ll);
    oh[idx] = hh; ol[idx] = ll;
}

// ================= 128x128 bf16-split GEMM, 4 warps of 64x64 =================
// EPI: 0 store fp32, 1 fp32 +=, 2 atomicAdd (split-K), 3 bf16 pair store.
// CAUSAL: 0 none; 1 skip tiles with colBase>rowBase; 2 cap K at rowBase+128.
template <int TRANSB, int EPI, int CAUSAL>
__global__ void __launch_bounds__(128, 2)
gemm_bf3(const bf16* __restrict__ Ah, const bf16* __restrict__ Al,
         const bf16* __restrict__ Bh, const bf16* __restrict__ Bl,
         float* __restrict__ C, bf16* __restrict__ Ch, bf16* __restrict__ Cl,
         int M, int N, int K, int lda, int ldb, int ldc,
         int kSplit, size_t aZ, size_t bZ, size_t cZ) {
    extern __shared__ __align__(16) char smem[];
    const int tid = threadIdx.x, lane = tid & 31, warp = tid >> 5;
    const int wm = warp >> 1, wn = warp & 1;           // 2x2 warp grid, 64x64 each
    const int rowBase = blockIdx.y * 128, colBase = blockIdx.x * 128;
    if (CAUSAL == 1 && colBase > rowBase) return;
    const int z = blockIdx.z;
    int kStart = 0, kEnd = K;
    if (CAUSAL == 2) kEnd = rowBase + 128 < K ? rowBase + 128 : K;
    if (kSplit > 1) {
        int kl = K / kSplit; kStart = z * kl; kEnd = kStart + kl;
    } else {
        Ah += z * aZ; Al += z * aZ; Bh += z * bZ; Bl += z * bZ;
        if (EPI == 3) { Ch += z * cZ; Cl += z * cZ; } else { C += z * cZ; }
    }
    const int nk = (kEnd - kStart) / KT;
    const uint32_t sb = (uint32_t)__cvta_generic_to_shared(smem);
    const int BUFB = TRANSB ? 10240 : 8704;

    auto load_stage = [&](int s, int kt) {
        uint32_t aOff = sb + s * 20480;
        uint32_t bOff = sb + 40960 + s * 2 * BUFB;
        #pragma unroll
        for (int r = 0; r < 4; ++r) {
            int idx = tid + r * 128;
            int row = idx >> 2, kc = (idx & 3) * 8;
            uint32_t d = aOff + (row * ASTR + kc) * 2;
            const size_t ga = (size_t)(rowBase + row) * lda + kt + kc;
            cpa16(d,         Ah + ga);
            cpa16(d + 10240, Al + ga);
            if (!TRANSB) {
                int kr = idx >> 4, nc = (idx & 15) * 8;
                uint32_t db = bOff + (kr * BSTRN + nc) * 2;
                const size_t gb = (size_t)(kt + kr) * ldb + colBase + nc;
                cpa16(db,        Bh + gb);
                cpa16(db + BUFB, Bl + gb);
            } else {
                int nr = idx >> 2, kc2 = (idx & 3) * 8;
                uint32_t db = bOff + (nr * ASTR + kc2) * 2;
                const size_t gb = (size_t)(colBase + nr) * ldb + kt + kc2;
                cpa16(db,        Bh + gb);
                cpa16(db + BUFB, Bl + gb);
            }
        }
        asm volatile("cp.async.commit_group;");
    };

    float acc[4][8][4];
    #pragma unroll
    for (int i = 0; i < 4; ++i)
        #pragma unroll
        for (int j = 0; j < 8; ++j)
            #pragma unroll
            for (int v = 0; v < 4; ++v) acc[i][j][v] = 0.f;

    const int l15 = lane & 15, lhi = (lane >> 4) * 8;

    load_stage(0, kStart);

    for (int it = 0; it < nk; ++it) {
        const int s = it & 1;
        if (it + 1 < nk) {
            load_stage((it + 1) & 1, kStart + (it + 1) * KT);
            asm volatile("cp.async.wait_group 1;");
        } else {
            asm volatile("cp.async.wait_group 0;");
        }
        __syncthreads();

        const uint32_t aBase = sb + s * 20480 + ((wm * 64 + l15) * ASTR + lhi) * 2;
        const uint32_t bOff  = sb + 40960 + s * 2 * BUFB;

        #pragma unroll
        for (int ks = 0; ks < KT; ks += 16) {
            uint32_t aH[4][4], aL[4][4], bH[4][4], bL[4][4];
            #pragma unroll
            for (int mt = 0; mt < 4; ++mt)
                ldsm4(aH[mt], aBase + ks * 2 + mt * (16 * ASTR * 2));
            if (!TRANSB) {
                uint32_t bBase = bOff + ((l15 + ks) * BSTRN + wn * 64 + lhi) * 2;
                #pragma unroll
                for (int p = 0; p < 4; ++p) ldsm4t(bH[p], bBase + p * 32);
            } else {
                #pragma unroll
                for (int p = 0; p < 4; ++p)
                    ldsm4(bH[p], bOff + ((wn * 64 + p * 16 + l15) * ASTR + ks + lhi) * 2);
            }
            #pragma unroll
            for (int mt = 0; mt < 4; ++mt)
                #pragma unroll
                for (int nt = 0; nt < 8; ++nt) {
                    int p = nt >> 1, su = nt & 1;
                    uint32_t b0 = TRANSB ? bH[p][su]     : bH[p][2 * su];
                    uint32_t b1 = TRANSB ? bH[p][su + 2] : bH[p][2 * su + 1];
                    mma16816(acc[mt][nt], aH[mt], b0, b1);
                }
            if (!TRANSB) {
                uint32_t bBase = bOff + BUFB + ((l15 + ks) * BSTRN + wn * 64 + lhi) * 2;
                #pragma unroll
                for (int p = 0; p < 4; ++p) ldsm4t(bL[p], bBase + p * 32);
            } else {
                #pragma unroll
                for (int p = 0; p < 4; ++p)
                    ldsm4(bL[p], bOff + BUFB + ((wn * 64 + p * 16 + l15) * ASTR + ks + lhi) * 2);
            }
            #pragma unroll
            for (int mt = 0; mt < 4; ++mt)
                #pragma unroll
                for (int nt = 0; nt < 8; ++nt) {
                    int p = nt >> 1, su = nt & 1;
                    uint32_t b0 = TRANSB ? bL[p][su]     : bL[p][2 * su];
                    uint32_t b1 = TRANSB ? bL[p][su + 2] : bL[p][2 * su + 1];
                    mma16816(acc[mt][nt], aH[mt], b0, b1);
                }
            #pragma unroll
            for (int mt = 0; mt < 4; ++mt)
                ldsm4(aL[mt], aBase + 10240 + ks * 2 + mt * (16 * ASTR * 2));
            #pragma unroll
            for (int mt = 0; mt < 4; ++mt)
                #pragma unroll
                for (int nt = 0; nt < 8; ++nt) {
                    int p = nt >> 1, su = nt & 1;
                    uint32_t b0 = TRANSB ? bH[p][su]     : bH[p][2 * su];
                    uint32_t b1 = TRANSB ? bH[p][su + 2] : bH[p][2 * su + 1];
                    mma16816(acc[mt][nt], aL[mt], b0, b1);
                }
        }
        __syncthreads();
    }

    // ---------- epilogue ----------
    const int r0 = rowBase + wm * 64 + (lane >> 2);
    const int c0 = colBase + wn * 64 + (lane & 3) * 2;
    #pragma unroll
    for (int mt = 0; mt < 4; ++mt) {
        #pragma unroll
        for (int nt = 0; nt < 8; ++nt) {
            int r = r0 + mt * 16, c = c0 + nt * 8;
            if (EPI == 3) {
                split2_store(Ch + (size_t)r * ldc + c,       Cl + (size_t)r * ldc + c,
                             acc[mt][nt][0], acc[mt][nt][1]);
                split2_store(Ch + (size_t)(r + 8) * ldc + c, Cl + (size_t)(r + 8) * ldc + c,
                             acc[mt][nt][2], acc[mt][nt][3]);
            } else if (EPI == 2) {
                atomicAdd(C + (size_t)r * ldc + c,           acc[mt][nt][0]);
                atomicAdd(C + (size_t)r * ldc + c + 1,       acc[mt][nt][1]);
                atomicAdd(C + (size_t)(r + 8) * ldc + c,     acc[mt][nt][2]);
                atomicAdd(C + (size_t)(r + 8) * ldc + c + 1, acc[mt][nt][3]);
            } else {
                float2* p0 = (float2*)(C + (size_t)r * ldc + c);
                float2* p1 = (float2*)(C + (size_t)(r + 8) * ldc + c);
                if (EPI == 1) {
                    float2 t0 = *p0, t1 = *p1;
                    t0.x += acc[mt][nt][0]; t0.y += acc[mt][nt][1];
                    t1.x += acc[mt][nt][2]; t1.y += acc[mt][nt][3];
                    *p0 = t0; *p1 = t1;
                } else {
                    *p0 = make_float2(acc[mt][nt][0], acc[mt][nt][1]);
                    *p1 = make_float2(acc[mt][nt][2], acc[mt][nt][3]);
                }
            }
        }
    }
}

// ---------------- host-side dispatch ----------------
template <int TRANSB, int EPI, int CAUSAL>
static void launch_gemm(const bf16* Ah, const bf16* Al, const bf16* Bh, const bf16* Bl,
                        float* C, bf16* Ch, bf16* Cl,
                        int M, int N, int K, int lda, int ldb, int ldc,
                        int Z, int kSplit, size_t aZ, size_t bZ, size_t cZ) {
    const int smem = 40960 + 4 * (TRANSB ? 10240 : 8704);
    cudaFuncSetAttribute(gemm_bf3<TRANSB, EPI, CAUSAL>, cudaFuncAttributeMaxDynamicSharedMemorySize, smem);
    dim3 grid(N / 128, M / 128, Z);
    gemm_bf3<TRANSB, EPI, CAUSAL><<<grid, 128, smem>>>(Ah, Al, Bh, Bl, C, Ch, Cl,
                                                       M, N, K, lda, ldb, ldc, kSplit, aZ, bZ, cZ);
}

extern "C" void kernel_launch(void* const* d_in, const int* in_sizes, int n_in,
                              void* d_out, int out_size) {
    const int*   tokens      = (const int*)  d_in[0];
    const float* emb         = (const float*)d_in[1];
    const float* attn_gamma  = (const float*)d_in[2];
    const float* wq          = (const float*)d_in[3];
    const float* wk          = (const float*)d_in[4];
    const float* wv          = (const float*)d_in[5];
    const float* wo          = (const float*)d_in[6];
    const float* ff_gamma    = (const float*)d_in[7];
    const float* wi          = (const float*)d_in[8];
    const float* wg          = (const float*)d_in[9];
    const float* wfo         = (const float*)d_in[10];
    const float* final_gamma = (const float*)d_in[11];
    float* out = (float*)d_out;

    float *x, *kv, *suf, *c, *S, *f1, *f2;
    bf16 *hh, *hl, *qh, *ql, *kvh, *kvl, *Ph, *Pl, *aoh, *aol, *f1h, *f1l;
    bf16 *Wqh, *Wql, *Wkvh, *Wkvl, *Woh, *Wol, *Wih, *Wil, *Wgh, *Wgl, *Wfoh, *Wfol, *Weh, *Wel;
    cudaGetSymbolAddress((void**)&x,    g_x);
    cudaGetSymbolAddress((void**)&hh,   g_hh);  cudaGetSymbolAddress((void**)&hl,  g_hl);
    cudaGetSymbolAddress((void**)&qh,   g_qh);  cudaGetSymbolAddress((void**)&ql,  g_ql);
    cudaGetSymbolAddress((void**)&kv,   g_kv);
    cudaGetSymbolAddress((void**)&kvh,  g_kvh); cudaGetSymbolAddress((void**)&kvl, g_kvl);
    cudaGetSymbolAddress((void**)&suf,  g_suf); cudaGetSymbolAddress((void**)&c,   g_c);
    cudaGetSymbolAddress((void**)&S,    g_S);
    cudaGetSymbolAddress((void**)&Ph,   g_Ph);  cudaGetSymbolAddress((void**)&Pl,  g_Pl);
    cudaGetSymbolAddress((void**)&aoh,  g_aoh); cudaGetSymbolAddress((void**)&aol, g_aol);
    cudaGetSymbolAddress((void**)&f1,   g_f1);  cudaGetSymbolAddress((void**)&f2,  g_f2);
    cudaGetSymbolAddress((void**)&f1h,  g_f1h); cudaGetSymbolAddress((void**)&f1l, g_f1l);
    cudaGetSymbolAddress((void**)&Wqh,  w_qh);  cudaGetSymbolAddress((void**)&Wql, w_ql);
    cudaGetSymbolAddress((void**)&Wkvh, w_kvh); cudaGetSymbolAddress((void**)&Wkvl, w_kvl);
    cudaGetSymbolAddress((void**)&Woh,  w_oh);  cudaGetSymbolAddress((void**)&Wol, w_ol);
    cudaGetSymbolAddress((void**)&Wih,  w_ih);  cudaGetSymbolAddress((void**)&Wil, w_il);
    cudaGetSymbolAddress((void**)&Wgh,  w_gh);  cudaGetSymbolAddress((void**)&Wgl, w_gl);
    cudaGetSymbolAddress((void**)&Wfoh, w_foh); cudaGetSymbolAddress((void**)&Wfol, w_fol);
    cudaGetSymbolAddress((void**)&Weh,  w_eh);  cudaGetSymbolAddress((void**)&Wel, w_el);

    auto cvt = [](const float* in, bf16* h, bf16* l, size_t n) {
        cvt_pair_kernel<<<(unsigned)(n / 1024), 256>>>(in, h, l);
    };

    // ---- weight pre-split ----
    cvt(wq,  Wqh,  Wql,  (size_t)NLAYER * DMODEL * INNERD);
    cvt(wo,  Woh,  Wol,  (size_t)NLAYER * INNERD * DMODEL);
    cvt(wi,  Wih,  Wil,  (size_t)NLAYER * DMODEL * FFI);
    cvt(wg,  Wgh,  Wgl,  (size_t)NLAYER * DMODEL * FFI);
    cvt(wfo, Wfoh, Wfol, (size_t)NLAYER * FFI * DMODEL);
    cvt(emb, Weh,  Wel,  (size_t)VOCAB * DMODEL);
    for (int l = 0; l < NLAYER; ++l) {
        const size_t okv = (size_t)l * DMODEL * DHEAD;
        const size_t okvW = (size_t)l * DMODEL * 256;
        cvt_pair_cols_kernel<<<(DMODEL * DHEAD) / 1024, 256>>>(wk + okv, Wkvh + okvW, Wkvl + okvW, 0);
        cvt_pair_cols_kernel<<<(DMODEL * DHEAD) / 1024, 256>>>(wv + okv, Wkvh + okvW, Wkvl + okvW, 128);
    }

    embed_kernel<<<NT, 256>>>(tokens, emb, x);

    for (int l = 0; l < NLAYER; ++l) {
        const size_t oq   = (size_t)l * DMODEL * INNERD;
        const size_t okvW = (size_t)l * DMODEL * 256;
        const size_t oi   = (size_t)l * DMODEL * FFI;
        const size_t ofo  = (size_t)l * FFI * DMODEL;

        // --- attention ---
        rmsnorm_pair_kernel<<<NT, 256>>>(x, attn_gamma + (size_t)l * DMODEL, hh, hl);
        launch_gemm<0, 3, 0>(hh, hl, Wqh + oq, Wql + oq, nullptr, qh, ql,
                             NT, INNERD, DMODEL, DMODEL, INNERD, INNERD, 1, 1, 0, 0, 0);
        cudaMemsetAsync(kv, 0, NT * 256 * sizeof(float));
        launch_gemm<0, 2, 0>(hh, hl, Wkvh + okvW, Wkvl + okvW, kv, nullptr, nullptr,
                             NT, 256, DMODEL, DMODEL, 256, 256, 8, 8, 0, 0, 0);
        cvt(kv, kvh, kvl, (size_t)NT * 256);
        suffixv_kernel<<<NT / 128, 128>>>(kv, suf);
        launch_gemm<1, 0, 1>(qh, ql, kvh, kvl, S, nullptr, nullptr,
                             NT, NT, DHEAD, INNERD, 256, NT,
                             NHEAD, 1, (size_t)DHEAD, 0, (size_t)NT * NT);
        softmax_kernel<<<dim3(NT, NHEAD), 256>>>(S, Ph, Pl, c);
        launch_gemm<0, 0, 2>(Ph, Pl, kvh + 128, kvl + 128, f1, nullptr, nullptr,
                             NT, DHEAD, NT, NT, 256, INNERD,
                             NHEAD, 1, (size_t)NT * NT, 0, (size_t)DHEAD);
        ao_fix_kernel<<<(NT * INNERD) / 256, 256>>>(f1, c, suf, aoh, aol);
        launch_gemm<0, 1, 0>(aoh, aol, Woh + oq, Wol + oq, x, nullptr, nullptr,
                             NT, DMODEL, INNERD, INNERD, DMODEL, DMODEL, 1, 1, 0, 0, 0);

        // --- SwiGLU FFN ---
        rmsnorm_pair_kernel<<<NT, 256>>>(x, ff_gamma + (size_t)l * DMODEL, hh, hl);
        launch_gemm<0, 0, 0>(hh, hl, Wih + oi, Wil + oi, f1, nullptr, nullptr,
                             NT, FFI, DMODEL, DMODEL, FFI, FFI, 1, 1, 0, 0, 0);
        launch_gemm<0, 0, 0>(hh, hl, Wgh + oi, Wgl + oi, f2, nullptr, nullptr,
                             NT, FFI, DMODEL, DMODEL, FFI, FFI, 1, 1, 0, 0, 0);
        silu_pair_kernel<<<(NT * FFI) / 256, 256>>>(f1, f2, f1h, f1l);
        launch_gemm<0, 1, 0>(f1h, f1l, Wfoh + ofo, Wfol + ofo, x, nullptr, nullptr,
                             NT, DMODEL, FFI, FFI, DMODEL, DMODEL, 1, 1, 0, 0, 0);
    }

    // --- final norm + tied-embedding logits ---
    rmsnorm_pair_kernel<<<NT, 256>>>(x, final_gamma, hh, hl);
    launch_gemm<1, 0, 0>(hh, hl, Weh, Wel, out, nullptr, nullptr,
                         NT, VOCAB, DMODEL, DMODEL, DMODEL, VOCAB, 1, 1, 0, 0, 0);
}

// round 12
// speedup vs baseline: 1.3885x; 1.2914x over previous
#include <cuda_runtime.h>
#include <cuda_fp16.h>
#include <cstdint>
#include <math.h>

#define NT      2048
#define DMODEL  2048
#define NHEAD   16
#define DHEAD   128
#define INNERD  2048
#define FFI     8192
#define VOCAB   32000
#define NLAYER  4
#define EPSF    1e-5f
#define MASKV   1e-10f
#define KT      32
#define ASTR    40     // [row][k] smem stride (elems)
#define BSTRN   136    // [k][n] smem stride (elems) for NN B tiles
#define L2E     1.4426950408889634f
#define PSCALE  1024.0f
#define PISCALE 9.765625e-4f

typedef __half f16;

// ---------------- scratch (static device globals; no allocations) ----------------
__device__ float g_x [NT * DMODEL];
__device__ f16   g_hh[NT * DMODEL], g_hl[NT * DMODEL];
__device__ f16   g_qh[NT * INNERD], g_ql[NT * INNERD];
__device__ float g_kv [NT * 256];
__device__ f16   g_kvh[NT * 256], g_kvl[NT * 256];      // K pair; V uses hi half only
__device__ float g_suf[NT * DHEAD];
__device__ float g_c  [NHEAD * NT];
__device__ float g_S [(size_t)NHEAD * NT * NT];
__device__ f16   g_Ph[(size_t)NHEAD * NT * NT], g_Pl[(size_t)NHEAD * NT * NT];
__device__ f16   g_aoh[NT * INNERD], g_aol[NT * INNERD];
__device__ float g_f1[NT * FFI], g_f2[NT * FFI];
__device__ f16   g_f1h[NT * FFI], g_f1l[NT * FFI];
// weights: pairs for precision-critical (q, kv); singles for 2-pass path
__device__ f16 w_qh [NLAYER * DMODEL * INNERD], w_ql [NLAYER * DMODEL * INNERD];
__device__ f16 w_kvh[NLAYER * DMODEL * 256],    w_kvl[NLAYER * DMODEL * 256];
__device__ f16 w_oh [NLAYER * INNERD * DMODEL];
__device__ f16 w_ih [(size_t)NLAYER * DMODEL * FFI];
__device__ f16 w_gh [(size_t)NLAYER * DMODEL * FFI];
__device__ f16 w_foh[(size_t)NLAYER * FFI * DMODEL];
__device__ f16 w_eh [(size_t)VOCAB * DMODEL];

// ---------------- helpers ----------------
__device__ __forceinline__ void cpa16(uint32_t dst, const void* src) {
    asm volatile("cp.async.cg.shared.global [%0],[%1],16;" :: "r"(dst), "l"(src));
}
__device__ __forceinline__ void ldsm4(uint32_t* r, uint32_t a) {
    asm volatile("ldmatrix.sync.aligned.m8n8.x4.shared.b16 {%0,%1,%2,%3},[%4];"
                 : "=r"(r[0]), "=r"(r[1]), "=r"(r[2]), "=r"(r[3]) : "r"(a));
}
__device__ __forceinline__ void ldsm4t(uint32_t* r, uint32_t a) {
    asm volatile("ldmatrix.sync.aligned.m8n8.x4.trans.shared.b16 {%0,%1,%2,%3},[%4];"
                 : "=r"(r[0]), "=r"(r[1]), "=r"(r[2]), "=r"(r[3]) : "r"(a));
}
__device__ __forceinline__ void mma16816(float* c, const uint32_t* a, uint32_t b0, uint32_t b1) {
    asm volatile("mma.sync.aligned.m16n8k16.row.col.f32.f16.f16.f32 "
                 "{%0,%1,%2,%3},{%4,%5,%6,%7},{%8,%9},{%0,%1,%2,%3};"
                 : "+f"(c[0]), "+f"(c[1]), "+f"(c[2]), "+f"(c[3])
                 : "r"(a[0]), "r"(a[1]), "r"(a[2]), "r"(a[3]), "r"(b0), "r"(b1));
}
__device__ __forceinline__ void split1(float a, f16& h, f16& l) {
    h = __float2half_rn(a);
    l = __float2half_rn(a - __half2float(h));
}
__device__ __forceinline__ void split2_store(f16* hp, f16* lp, float a, float b) {
    f16 ha = __float2half_rn(a), hb = __float2half_rn(b);
    f16 la = __float2half_rn(a - __half2float(ha));
    f16 lb = __float2half_rn(b - __half2float(hb));
    __half2 H = __halves2half2(ha, hb);
    __half2 L = __halves2half2(la, lb);
    *(uint32_t*)hp = *(uint32_t*)&H;
    *(uint32_t*)lp = *(uint32_t*)&L;
}

// ---------------- fp32 -> fp16 pair ----------------
__global__ void __launch_bounds__(256) cvt_pair_kernel(const float* __restrict__ in,
                                                       f16* __restrict__ ho, f16* __restrict__ lo) {
    size_t i = (size_t)blockIdx.x * 256 + threadIdx.x;
    float4 v = ((const float4*)in)[i];
    f16 h0, l0, h1, l1, h2, l2, h3, l3;
    split1(v.x, h0, l0); split1(v.y, h1, l1); split1(v.z, h2, l2); split1(v.w, h3, l3);
    __half2 ha = __halves2half2(h0, h1), hb = __halves2half2(h2, h3);
    __half2 la = __halves2half2(l0, l1), lb = __halves2half2(l2, l3);
    uint2 H = {*(uint32_t*)&ha, *(uint32_t*)&hb};
    uint2 L = {*(uint32_t*)&la, *(uint32_t*)&lb};
    ((uint2*)ho)[i] = H;
    ((uint2*)lo)[i] = L;
}

// ---------------- fp32 -> fp16 single ----------------
__global__ void __launch_bounds__(256) cvt_half_kernel(const float* __restrict__ in,
                                                       f16* __restrict__ out) {
    size_t i = (size_t)blockIdx.x * 256 + threadIdx.x;
    float4 v = ((const float4*)in)[i];
    __half2 a = __floats2half2_rn(v.x, v.y);
    __half2 b = __floats2half2_rn(v.z, v.w);
    uint2 o = {*(uint32_t*)&a, *(uint32_t*)&b};
    ((uint2*)out)[i] = o;
}

// ---- strided pair cvt: in [R,128] -> out [R,256] at column offset ----
__global__ void __launch_bounds__(256) cvt_pair_cols_kernel(const float* __restrict__ in,
                                                            f16* __restrict__ ho, f16* __restrict__ lo,
                                                            int colOff) {
    size_t i = (size_t)blockIdx.x * 256 + threadIdx.x;
    int row = (int)(i >> 5);
    int col = ((int)i & 31) * 4;
    float4 v = ((const float4*)in)[i];
    size_t o = (size_t)row * 256 + colOff + col;
    f16 h0, l0, h1, l1, h2, l2, h3, l3;
    split1(v.x, h0, l0); split1(v.y, h1, l1); split1(v.z, h2, l2); split1(v.w, h3, l3);
    __half2 ha = __halves2half2(h0, h1), hb = __halves2half2(h2, h3);
    __half2 la = __halves2half2(l0, l1), lb = __halves2half2(l2, l3);
    *(uint32_t*)(ho + o)     = *(uint32_t*)&ha;
    *(uint32_t*)(ho + o + 2) = *(uint32_t*)&hb;
    *(uint32_t*)(lo + o)     = *(uint32_t*)&la;
    *(uint32_t*)(lo + o + 2) = *(uint32_t*)&lb;
}

// ---------------- embedding ----------------
__global__ void embed_kernel(const int* __restrict__ tok, const float* __restrict__ emb,
                             float* __restrict__ x) {
    int n = blockIdx.x;
    const float* src = emb + (size_t)tok[n] * DMODEL;
    float* dst = x + (size_t)n * DMODEL;
    for (int d = threadIdx.x; d < DMODEL; d += blockDim.x) dst[d] = src[d];
}

// ---------------- RMSNorm -> fp16 pair ----------------
__global__ void __launch_bounds__(256) rmsnorm_pair_kernel(const float* __restrict__ x,
                                                           const float* __restrict__ gamma,
                                                           f16* __restrict__ oh, f16* __restrict__ ol) {
    int n = blockIdx.x;
    const float* row = x + (size_t)n * DMODEL;
    float s = 0.f;
    for (int d = threadIdx.x; d < DMODEL; d += 256) { float v = row[d]; s += v * v; }
    __shared__ float red[256];
    red[threadIdx.x] = s; __syncthreads();
    #pragma unroll
    for (int k = 128; k > 0; k >>= 1) {
        if (threadIdx.x < k) red[threadIdx.x] += red[threadIdx.x + k];
        __syncthreads();
    }
    float inv = rsqrtf(red[0] * (1.0f / DMODEL) + EPSF);
    for (int d = threadIdx.x; d < DMODEL; d += 256) {
        f16 h, l; split1(row[d] * inv * gamma[d], h, l);
        oh[(size_t)n * DMODEL + d] = h;
        ol[(size_t)n * DMODEL + d] = l;
    }
}

// ---------------- SwiGLU -> fp16 pair ----------------
__global__ void __launch_bounds__(256) silu_pair_kernel(const float* __restrict__ a,
                                                        const float* __restrict__ b,
                                                        f16* __restrict__ oh, f16* __restrict__ ol) {
    size_t i = (size_t)blockIdx.x * 256 + threadIdx.x;
    float bb = b[i];
    f16 h, l; split1(a[i] * bb / (1.f + __expf(-bb)), h, l);
    oh[i] = h; ol[i] = l;
}

// ---------------- suffixV ----------------
__global__ void __launch_bounds__(128) suffixv_kernel(const float* __restrict__ kv,
                                                      float* __restrict__ suf) {
    const int d = threadIdx.x;
    const int lo = blockIdx.x * 128, hi = lo + 128;
    float acc = 0.f;
    for (int j = NT - 1; j >= hi; --j)
        acc += kv[(size_t)j * 256 + 128 + d];
    for (int i = hi - 1; i >= lo; --i) {
        suf[(size_t)i * DHEAD + d] = acc;
        acc += kv[(size_t)i * 256 + 128 + d];
    }
}

// ------- softmax: visible region exact, masked region rank-1; P scaled x1024 -------
__global__ void __launch_bounds__(256) softmax_kernel(const float* __restrict__ S,
                                                      f16* __restrict__ Ph, f16* __restrict__ Pl,
                                                      float* __restrict__ C) {
    const int i = blockIdx.x, h = blockIdx.y, tid = threadIdx.x;
    const float* row = S + ((size_t)h * NT + i) * NT;
    __shared__ float sc[NT];
    __shared__ float red[256];
    const float slope = exp2f(-0.5f * (float)(h + 1));
    const float scale = 0.08838834764831845f;
    const int tileEnd = ((i >> 7) + 1) << 7;

    float mx = MASKV;
    for (int j = tid; j <= i; j += 256) {
        float v = row[j] * scale + slope * (float)j;
        sc[j] = v;
        mx = fmaxf(mx, v);
    }
    red[tid] = mx; __syncthreads();
    #pragma unroll
    for (int s = 128; s > 0; s >>= 1) {
        if (tid < s) red[tid] = fmaxf(red[tid], red[tid + s]);
        __syncthreads();
    }
    mx = red[0]; __syncthreads();

    float sum = 0.f;
    for (int j = tid; j <= i; j += 256) {
        float p = exp2f((sc[j] - mx) * L2E);
        sc[j] = p; sum += p;
    }
    red[tid] = sum; __syncthreads();
    #pragma unroll
    for (int s = 128; s > 0; s >>= 1) {
        if (tid < s) red[tid] += red[tid + s];
        __syncthreads();
    }
    const float maskexp = exp2f((MASKV - mx) * L2E);
    const float inv = 1.f / (red[0] + (float)(NT - 1 - i) * maskexp);
    const float c = maskexp * inv;
    if (tid == 0) C[(size_t)h * NT + i] = c;

    const float pw = inv * PSCALE;
    f16* ph = Ph + ((size_t)h * NT + i) * NT;
    f16* pl = Pl + ((size_t)h * NT + i) * NT;
    for (int j = tid; j < tileEnd; j += 256) {
        if (j <= i) {
            f16 hh, ll; split1(sc[j] * pw, hh, ll);
            ph[j] = hh; pl[j] = ll;
        } else {
            ph[j] = __float2half_rn(0.f);
            pl[j] = __float2half_rn(0.f);
        }
    }
}

// ------- ao = pv/1024 + c*suffixV -> fp16 pair -------
__global__ void __launch_bounds__(256) ao_fix_kernel(const float* __restrict__ pv,
                                                     const float* __restrict__ C,
                                                     const float* __restrict__ suf,
                                                     f16* __restrict__ oh, f16* __restrict__ ol) {
    size_t idx = (size_t)blockIdx.x * 256 + threadIdx.x;
    int i = (int)(idx >> 11);
    int rem = (int)(idx & 2047);
    int h = rem >> 7, d = rem & 127;
    float v = pv[idx] * PISCALE + C[(size_t)h * NT + i] * suf[(size_t)i * DHEAD + d];
    f16 hh, ll; split1(v, hh, ll);
    oh[idx] = hh; ol[idx] = ll;
}

// ================= pipelined fp16-split tensor-core GEMM =================
// PASSES=3: (aH+aL)xbH + aHxbL (full split, err ~2^-22).
// PASSES=2: (aH+aL)xbH = a x bH exactly (err = a x bL ~ 2^-12; B single, no Bl tile).
// EPI: 0 store fp32, 1 fp32 +=, 2 atomicAdd (split-K), 3 fp16 pair store.
// CAUSAL: 0 none; 1 skip tiles with colBase>rowBase; 2 cap K at rowBase+128.
template <int TRANSB, int EPI, int CAUSAL, int PASSES>
__global__ void __launch_bounds__(256, 2)
gemm_hs(const f16* __restrict__ Ah, const f16* __restrict__ Al,
        const f16* __restrict__ Bh, const f16* __restrict__ Bl,
        float* __restrict__ C, f16* __restrict__ Ch, f16* __restrict__ Cl,
        int M, int N, int K, int lda, int ldb, int ldc,
        int kSplit, size_t aZ, size_t bZ, size_t cZ) {
    extern __shared__ __align__(16) char smem[];
    const int tid = threadIdx.x, lane = tid & 31, warp = tid >> 5;
    const int wm = warp >> 2, wn = warp & 3;
    const int rowBase = blockIdx.y * 128, colBase = blockIdx.x * 128;
    if (CAUSAL == 1 && colBase > rowBase) return;
    const int z = blockIdx.z;
    int kStart = 0, kEnd = K;
    if (CAUSAL == 2) kEnd = rowBase + 128 < K ? rowBase + 128 : K;
    if (kSplit > 1) {
        int kl = K / kSplit; kStart = z * kl; kEnd = kStart + kl;
    } else {
        Ah += z * aZ; Al += z * aZ; Bh += z * bZ; if (PASSES == 3) Bl += z * bZ;
        if (EPI == 3) { Ch += z * cZ; Cl += z * cZ; } else { C += z * cZ; }
    }
    const int nk = (kEnd - kStart) / KT;
    const uint32_t sb = (uint32_t)__cvta_generic_to_shared(smem);
    const int BUFB = TRANSB ? 10240 : 8704;
    const int NB = PASSES - 1;    // B halves per stage

    auto load_stage = [&](int s, int kt) {
        uint32_t aOff = sb + s * 20480;
        uint32_t bOff = sb + 40960 + s * NB * BUFB;
        #pragma unroll
        for (int r = 0; r < 2; ++r) {
            int idx = tid + r * 256;
            int row = idx >> 2, kc = (idx & 3) * 8;
            uint32_t d = aOff + (row * ASTR + kc) * 2;
            const size_t ga = (size_t)(rowBase + row) * lda + kt + kc;
            cpa16(d,         Ah + ga);
            cpa16(d + 10240, Al + ga);
            if (!TRANSB) {
                int kr = idx >> 4, nc = (idx & 15) * 8;
                uint32_t db = bOff + (kr * BSTRN + nc) * 2;
                const size_t gb = (size_t)(kt + kr) * ldb + colBase + nc;
                cpa16(db, Bh + gb);
                if (PASSES == 3) cpa16(db + BUFB, Bl + gb);
            } else {
                int nr = idx >> 2, kc2 = (idx & 3) * 8;
                uint32_t db = bOff + (nr * ASTR + kc2) * 2;
                const size_t gb = (size_t)(colBase + nr) * ldb + kt + kc2;
                cpa16(db, Bh + gb);
                if (PASSES == 3) cpa16(db + BUFB, Bl + gb);
            }
        }
        asm volatile("cp.async.commit_group;");
    };

    float acc[4][4][4];
    #pragma unroll
    for (int i = 0; i < 4; ++i)
        #pragma unroll
        for (int j = 0; j < 4; ++j)
            #pragma unroll
            for (int v = 0; v < 4; ++v) acc[i][j][v] = 0.f;

    const int l15 = lane & 15, lhi = (lane >> 4) * 8;

    load_stage(0, kStart);

    for (int it = 0; it < nk; ++it) {
        const int s = it & 1;
        if (it + 1 < nk) {
            load_stage((it + 1) & 1, kStart + (it + 1) * KT);
            asm volatile("cp.async.wait_group 1;");
        } else {
            asm volatile("cp.async.wait_group 0;");
        }
        __syncthreads();

        const uint32_t aBase = sb + s * 20480 + ((wm * 64 + l15) * ASTR + lhi) * 2;
        const uint32_t bOff  = sb + 40960 + s * NB * BUFB;

        #pragma unroll
        for (int ks = 0; ks < KT; ks += 16) {
            uint32_t aH[4][4], aL[4][4], bH[2][4], bL[2][4];
            #pragma unroll
            for (int mt = 0; mt < 4; ++mt)
                ldsm4(aH[mt], aBase + ks * 2 + mt * (16 * ASTR * 2));
            if (!TRANSB) {
                uint32_t bBase = bOff + ((l15 + ks) * BSTRN + wn * 32 + lhi) * 2;
                #pragma unroll
                for (int p = 0; p < 2; ++p) ldsm4t(bH[p], bBase + p * 32);
            } else {
                #pragma unroll
                for (int p = 0; p < 2; ++p)
                    ldsm4(bH[p], bOff + ((wn * 32 + p * 16 + l15) * ASTR + ks + lhi) * 2);
            }
            #pragma unroll
            for (int mt = 0; mt < 4; ++mt)
                #pragma unroll
                for (int nt = 0; nt < 4; ++nt) {
                    int p = nt >> 1, su = nt & 1;
                    uint32_t b0 = TRANSB ? bH[p][su]     : bH[p][2 * su];
                    uint32_t b1 = TRANSB ? bH[p][su + 2] : bH[p][2 * su + 1];
                    mma16816(acc[mt][nt], aH[mt], b0, b1);
                }
            if (PASSES == 3) {
                if (!TRANSB) {
                    uint32_t bBase = bOff + BUFB + ((l15 + ks) * BSTRN + wn * 32 + lhi) * 2;
                    #pragma unroll
                    for (int p = 0; p < 2; ++p) ldsm4t(bL[p], bBase + p * 32);
                } else {
                    #pragma unroll
                    for (int p = 0; p < 2; ++p)
                        ldsm4(bL[p], bOff + BUFB + ((wn * 32 + p * 16 + l15) * ASTR + ks + lhi) * 2);
                }
                #pragma unroll
                for (int mt = 0; mt < 4; ++mt)
                    #pragma unroll
                    for (int nt = 0; nt < 4; ++nt) {
                        int p = nt >> 1, su = nt & 1;
                        uint32_t b0 = TRANSB ? bL[p][su]     : bL[p][2 * su];
                        uint32_t b1 = TRANSB ? bL[p][su + 2] : bL[p][2 * su + 1];
                        mma16816(acc[mt][nt], aH[mt], b0, b1);
                    }
            }
            #pragma unroll
            for (int mt = 0; mt < 4; ++mt)
                ldsm4(aL[mt], aBase + 10240 + ks * 2 + mt * (16 * ASTR * 2));
            #pragma unroll
            for (int mt = 0; mt < 4; ++mt)
                #pragma unroll
                for (int nt = 0; nt < 4; ++nt) {
                    int p = nt >> 1, su = nt & 1;
                    uint32_t b0 = TRANSB ? bH[p][su]     : bH[p][2 * su];
                    uint32_t b1 = TRANSB ? bH[p][su + 2] : bH[p][2 * su + 1];
                    mma16816(acc[mt][nt], aL[mt], b0, b1);
                }
        }
        __syncthreads();
    }

    // ---------- epilogue ----------
    const int r0 = rowBase + wm * 64 + (lane >> 2);
    const int c0 = colBase + wn * 32 + (lane & 3) * 2;
    #pragma unroll
    for (int mt = 0; mt < 4; ++mt) {
        #pragma unroll
        for (int nt = 0; nt < 4; ++nt) {
            int r = r0 + mt * 16, c = c0 + nt * 8;
            if (EPI == 3) {
                split2_store(Ch + (size_t)r * ldc + c,       Cl + (size_t)r * ldc + c,
                             acc[mt][nt][0], acc[mt][nt][1]);
                split2_store(Ch + (size_t)(r + 8) * ldc + c, Cl + (size_t)(r + 8) * ldc + c,
                             acc[mt][nt][2], acc[mt][nt][3]);
            } else if (EPI == 2) {
                atomicAdd(C + (size_t)r * ldc + c,           acc[mt][nt][0]);
                atomicAdd(C + (size_t)r * ldc + c + 1,       acc[mt][nt][1]);
                atomicAdd(C + (size_t)(r + 8) * ldc + c,     acc[mt][nt][2]);
                atomicAdd(C + (size_t)(r + 8) * ldc + c + 1, acc[mt][nt][3]);
            } else {
                float2* p0 = (float2*)(C + (size_t)r * ldc + c);
                float2* p1 = (float2*)(C + (size_t)(r + 8) * ldc + c);
                if (EPI == 1) {
                    float2 t0 = *p0, t1 = *p1;
                    t0.x += acc[mt][nt][0]; t0.y += acc[mt][nt][1];
                    t1.x += acc[mt][nt][2]; t1.y += acc[mt][nt][3];
                    *p0 = t0; *p1 = t1;
                } else {
                    *p0 = make_float2(acc[mt][nt][0], acc[mt][nt][1]);
                    *p1 = make_float2(acc[mt][nt][2], acc[mt][nt][3]);
                }
            }
        }
    }
}

// ---------------- host-side dispatch ----------------
template <int TRANSB, int EPI, int CAUSAL, int PASSES>
static void launch_gemm(const f16* Ah, const f16* Al, const f16* Bh, const f16* Bl,
                        float* C, f16* Ch, f16* Cl,
                        int M, int N, int K, int lda, int ldb, int ldc,
                        int Z, int kSplit, size_t aZ, size_t bZ, size_t cZ) {
    const int smem = 40960 + 2 * (PASSES - 1) * (TRANSB ? 10240 : 8704);
    cudaFuncSetAttribute(gemm_hs<TRANSB, EPI, CAUSAL, PASSES>,
                         cudaFuncAttributeMaxDynamicSharedMemorySize, smem);
    dim3 grid(N / 128, M / 128, Z);
    gemm_hs<TRANSB, EPI, CAUSAL, PASSES><<<grid, 256, smem>>>(Ah, Al, Bh, Bl, C, Ch, Cl,
                                                              M, N, K, lda, ldb, ldc,
                                                              kSplit, aZ, bZ, cZ);
}

extern "C" void kernel_launch(void* const* d_in, const int* in_sizes, int n_in,
                              void* d_out, int out_size) {
    const int*   tokens      = (const int*)  d_in[0];
    const float* emb         = (const float*)d_in[1];
    const float* attn_gamma  = (const float*)d_in[2];
    const float* wq          = (const float*)d_in[3];
    const float* wk          = (const float*)d_in[4];
    const float* wv          = (const float*)d_in[5];
    const float* wo          = (const float*)d_in[6];
    const float* ff_gamma    = (const float*)d_in[7];
    const float* wi          = (const float*)d_in[8];
    const float* wg          = (const float*)d_in[9];
    const float* wfo         = (const float*)d_in[10];
    const float* final_gamma = (const float*)d_in[11];
    float* out = (float*)d_out;

    float *x, *kv, *suf, *c, *S, *f1, *f2;
    f16 *hh, *hl, *qh, *ql, *kvh, *kvl, *Ph, *Pl, *aoh, *aol, *f1h, *f1l;
    f16 *Wqh, *Wql, *Wkvh, *Wkvl, *Woh, *Wih, *Wgh, *Wfoh, *Weh;
    cudaGetSymbolAddress((void**)&x,    g_x);
    cudaGetSymbolAddress((void**)&hh,   g_hh);  cudaGetSymbolAddress((void**)&hl,  g_hl);
    cudaGetSymbolAddress((void**)&qh,   g_qh);  cudaGetSymbolAddress((void**)&ql,  g_ql);
    cudaGetSymbolAddress((void**)&kv,   g_kv);
    cudaGetSymbolAddress((void**)&kvh,  g_kvh); cudaGetSymbolAddress((void**)&kvl, g_kvl);
    cudaGetSymbolAddress((void**)&suf,  g_suf); cudaGetSymbolAddress((void**)&c,   g_c);
    cudaGetSymbolAddress((void**)&S,    g_S);
    cudaGetSymbolAddress((void**)&Ph,   g_Ph);  cudaGetSymbolAddress((void**)&Pl,  g_Pl);
    cudaGetSymbolAddress((void**)&aoh,  g_aoh); cudaGetSymbolAddress((void**)&aol, g_aol);
    cudaGetSymbolAddress((void**)&f1,   g_f1);  cudaGetSymbolAddress((void**)&f2,  g_f2);
    cudaGetSymbolAddress((void**)&f1h,  g_f1h); cudaGetSymbolAddress((void**)&f1l, g_f1l);
    cudaGetSymbolAddress((void**)&Wqh,  w_qh);  cudaGetSymbolAddress((void**)&Wql, w_ql);
    cudaGetSymbolAddress((void**)&Wkvh, w_kvh); cudaGetSymbolAddress((void**)&Wkvl, w_kvl);
    cudaGetSymbolAddress((void**)&Woh,  w_oh);
    cudaGetSymbolAddress((void**)&Wih,  w_ih);
    cudaGetSymbolAddress((void**)&Wgh,  w_gh);
    cudaGetSymbolAddress((void**)&Wfoh, w_foh);
    cudaGetSymbolAddress((void**)&Weh,  w_eh);

    auto cvtp = [](const float* in, f16* h, f16* l, size_t n) {
        cvt_pair_kernel<<<(unsigned)(n / 1024), 256>>>(in, h, l);
    };
    auto cvts = [](const float* in, f16* h, size_t n) {
        cvt_half_kernel<<<(unsigned)(n / 1024), 256>>>(in, h);
    };

    // ---- weight pre-split (captured; runs each replay) ----
    cvtp(wq,  Wqh,  Wql, (size_t)NLAYER * DMODEL * INNERD);
    cvts(wo,  Woh,  (size_t)NLAYER * INNERD * DMODEL);
    cvts(wi,  Wih,  (size_t)NLAYER * DMODEL * FFI);
    cvts(wg,  Wgh,  (size_t)NLAYER * DMODEL * FFI);
    cvts(wfo, Wfoh, (size_t)NLAYER * FFI * DMODEL);
    cvts(emb, Weh,  (size_t)VOCAB * DMODEL);
    for (int l = 0; l < NLAYER; ++l) {
        const size_t okv = (size_t)l * DMODEL * DHEAD;
        const size_t okvW = (size_t)l * DMODEL * 256;
        cvt_pair_cols_kernel<<<(DMODEL * DHEAD) / 1024, 256>>>(wk + okv, Wkvh + okvW, Wkvl + okvW, 0);
        cvt_pair_cols_kernel<<<(DMODEL * DHEAD) / 1024, 256>>>(wv + okv, Wkvh + okvW, Wkvl + okvW, 128);
    }

    embed_kernel<<<NT, 256>>>(tokens, emb, x);

    for (int l = 0; l < NLAYER; ++l) {
        const size_t oq   = (size_t)l * DMODEL * INNERD;
        const size_t okvW = (size_t)l * DMODEL * 256;
        const size_t oi   = (size_t)l * DMODEL * FFI;
        const size_t ofo  = (size_t)l * FFI * DMODEL;

        // --- attention ---
        rmsnorm_pair_kernel<<<NT, 256>>>(x, attn_gamma + (size_t)l * DMODEL, hh, hl);
        // q projection: full 3-pass (feeds S; needs high precision)
        launch_gemm<0, 3, 0, 3>(hh, hl, Wqh + oq, Wql + oq, nullptr, qh, ql,
                                NT, INNERD, DMODEL, DMODEL, INNERD, INNERD, 1, 1, 0, 0, 0);
        cudaMemsetAsync(kv, 0, NT * 256 * sizeof(float));
        // kv projection: full 3-pass, split-K 8
        launch_gemm<0, 2, 0, 3>(hh, hl, Wkvh + okvW, Wkvl + okvW, kv, nullptr, nullptr,
                                NT, 256, DMODEL, DMODEL, 256, 256, 8, 8, 0, 0, 0);
        cvtp(kv, kvh, kvl, (size_t)NT * 256);
        suffixv_kernel<<<NT / 128, 128>>>(kv, suf);
        // S = Q K^T: 3-pass (logit precision), causal-skip upper tiles
        launch_gemm<1, 0, 1, 3>(qh, ql, kvh, kvl, S, nullptr, nullptr,
                                NT, NT, DHEAD, INNERD, 256, NT,
                                NHEAD, 1, (size_t)DHEAD, 0, (size_t)NT * NT);
        softmax_kernel<<<dim3(NT, NHEAD), 256>>>(S, Ph, Pl, c);
        // PV: 2-pass (P pair x V single), K capped at diagonal
        launch_gemm<0, 0, 2, 2>(Ph, Pl, kvh + 128, nullptr, f1, nullptr, nullptr,
                                NT, DHEAD, NT, NT, 256, INNERD,
                                NHEAD, 1, (size_t)NT * NT, 0, (size_t)DHEAD);
        ao_fix_kernel<<<(NT * INNERD) / 256, 256>>>(f1, c, suf, aoh, aol);
        // output projection: 2-pass
        launch_gemm<0, 1, 0, 2>(aoh, aol, Woh + oq, nullptr, x, nullptr, nullptr,
                                NT, DMODEL, INNERD, INNERD, DMODEL, DMODEL, 1, 1, 0, 0, 0);

        // --- SwiGLU FFN: all 2-pass ---
        rmsnorm_pair_kernel<<<NT, 256>>>(x, ff_gamma + (size_t)l * DMODEL, hh, hl);
        launch_gemm<0, 0, 0, 2>(hh, hl, Wih + oi, nullptr, f1, nullptr, nullptr,
                                NT, FFI, DMODEL, DMODEL, FFI, FFI, 1, 1, 0, 0, 0);
        launch_gemm<0, 0, 0, 2>(hh, hl, Wgh + oi, nullptr, f2, nullptr, nullptr,
                                NT, FFI, DMODEL, DMODEL, FFI, FFI, 1, 1, 0, 0, 0);
        silu_pair_kernel<<<(NT * FFI) / 256, 256>>>(f1, f2, f1h, f1l);
        launch_gemm<0, 1, 0, 2>(f1h, f1l, Wfoh + ofo, nullptr, x, nullptr, nullptr,
                                NT, DMODEL, FFI, FFI, DMODEL, DMODEL, 1, 1, 0, 0, 0);
    }

    // --- final norm + tied-embedding logits: 2-pass TN ---
    rmsnorm_pair_kernel<<<NT, 256>>>(x, final_gamma, hh, hl);
    launch_gemm<1, 0, 0, 2>(hh, hl, Weh, nullptr, out, nullptr, nullptr,
                            NT, VOCAB, DMODEL, DMODEL, DMODEL, VOCAB, 1, 1, 0, 0, 0);
}

// round 13
// speedup vs baseline: 1.3992x; 1.0077x over previous
#include <cuda_runtime.h>
#include <cuda_fp16.h>
#include <cstdint>
#include <math.h>

#define NT      2048
#define DMODEL  2048
#define NHEAD   16
#define DHEAD   128
#define INNERD  2048
#define FFI     8192
#define VOCAB   32000
#define NLAYER  4
#define EPSF    1e-5f
#define MASKV   1e-10f
#define KT      32
#define ASTR    40     // [row][k] smem stride (elems)
#define BSTRN   136    // [k][n] smem stride (elems) for NN B tiles
#define L2E     1.4426950408889634f
#define PSCALE  1024.0f
#define PISCALE 9.765625e-4f

typedef __half f16;

// ---------------- scratch (static device globals; no allocations) ----------------
__device__ float g_x [NT * DMODEL];
__device__ f16   g_hh[NT * DMODEL], g_hl[NT * DMODEL];
__device__ f16   g_qh[NT * INNERD], g_ql[NT * INNERD];
__device__ float g_kv [NT * 256];
__device__ f16   g_kvh[NT * 256], g_kvl[NT * 256];      // K pair; V uses hi half only
__device__ float g_suf[NT * DHEAD];
__device__ float g_c  [NHEAD * NT];
__device__ float g_S [(size_t)NHEAD * NT * NT];
__device__ f16   g_Ph[(size_t)NHEAD * NT * NT], g_Pl[(size_t)NHEAD * NT * NT];
__device__ f16   g_aoh[NT * INNERD], g_aol[NT * INNERD];
__device__ float g_f1[NT * FFI];
__device__ f16   g_f1h[NT * FFI], g_f1l[NT * FFI];
// weights: pairs for precision-critical (q, kv); singles for 2-pass path
__device__ f16 w_qh [NLAYER * DMODEL * INNERD], w_ql [NLAYER * DMODEL * INNERD];
__device__ f16 w_kvh[NLAYER * DMODEL * 256],    w_kvl[NLAYER * DMODEL * 256];
__device__ f16 w_oh [NLAYER * INNERD * DMODEL];
__device__ f16 w_ih [(size_t)NLAYER * DMODEL * FFI];
__device__ f16 w_gh [(size_t)NLAYER * DMODEL * FFI];
__device__ f16 w_foh[(size_t)NLAYER * FFI * DMODEL];
__device__ f16 w_eh [(size_t)VOCAB * DMODEL];

// ---------------- helpers ----------------
__device__ __forceinline__ void cpa16(uint32_t dst, const void* src) {
    asm volatile("cp.async.cg.shared.global [%0],[%1],16;" :: "r"(dst), "l"(src));
}
__device__ __forceinline__ void ldsm4(uint32_t* r, uint32_t a) {
    asm volatile("ldmatrix.sync.aligned.m8n8.x4.shared.b16 {%0,%1,%2,%3},[%4];"
                 : "=r"(r[0]), "=r"(r[1]), "=r"(r[2]), "=r"(r[3]) : "r"(a));
}
__device__ __forceinline__ void ldsm4t(uint32_t* r, uint32_t a) {
    asm volatile("ldmatrix.sync.aligned.m8n8.x4.trans.shared.b16 {%0,%1,%2,%3},[%4];"
                 : "=r"(r[0]), "=r"(r[1]), "=r"(r[2]), "=r"(r[3]) : "r"(a));
}
__device__ __forceinline__ void mma16816(float* c, const uint32_t* a, uint32_t b0, uint32_t b1) {
    asm volatile("mma.sync.aligned.m16n8k16.row.col.f32.f16.f16.f32 "
                 "{%0,%1,%2,%3},{%4,%5,%6,%7},{%8,%9},{%0,%1,%2,%3};"
                 : "+f"(c[0]), "+f"(c[1]), "+f"(c[2]), "+f"(c[3])
                 : "r"(a[0]), "r"(a[1]), "r"(a[2]), "r"(a[3]), "r"(b0), "r"(b1));
}
__device__ __forceinline__ void split1(float a, f16& h, f16& l) {
    h = __float2half_rn(a);
    l = __float2half_rn(a - __half2float(h));
}
__device__ __forceinline__ void split2_store(f16* hp, f16* lp, float a, float b) {
    f16 ha = __float2half_rn(a), hb = __float2half_rn(b);
    f16 la = __float2half_rn(a - __half2float(ha));
    f16 lb = __float2half_rn(b - __half2float(hb));
    __half2 H = __halves2half2(ha, hb);
    __half2 L = __halves2half2(la, lb);
    *(uint32_t*)hp = *(uint32_t*)&H;
    *(uint32_t*)lp = *(uint32_t*)&L;
}
__device__ __forceinline__ float silu_mul(float a, float g) {
    return a * g / (1.f + __expf(-g));
}

// ---------------- fp32 -> fp16 pair ----------------
__global__ void __launch_bounds__(256) cvt_pair_kernel(const float* __restrict__ in,
                                                       f16* __restrict__ ho, f16* __restrict__ lo) {
    size_t i = (size_t)blockIdx.x * 256 + threadIdx.x;
    float4 v = ((const float4*)in)[i];
    f16 h0, l0, h1, l1, h2, l2, h3, l3;
    split1(v.x, h0, l0); split1(v.y, h1, l1); split1(v.z, h2, l2); split1(v.w, h3, l3);
    __half2 ha = __halves2half2(h0, h1), hb = __halves2half2(h2, h3);
    __half2 la = __halves2half2(l0, l1), lb = __halves2half2(l2, l3);
    uint2 H = {*(uint32_t*)&ha, *(uint32_t*)&hb};
    uint2 L = {*(uint32_t*)&la, *(uint32_t*)&lb};
    ((uint2*)ho)[i] = H;
    ((uint2*)lo)[i] = L;
}

// ---------------- fp32 -> fp16 single ----------------
__global__ void __launch_bounds__(256) cvt_half_kernel(const float* __restrict__ in,
                                                       f16* __restrict__ out) {
    size_t i = (size_t)blockIdx.x * 256 + threadIdx.x;
    float4 v = ((const float4*)in)[i];
    __half2 a = __floats2half2_rn(v.x, v.y);
    __half2 b = __floats2half2_rn(v.z, v.w);
    uint2 o = {*(uint32_t*)&a, *(uint32_t*)&b};
    ((uint2*)out)[i] = o;
}

// ---- strided pair cvt: in [R,128] -> out [R,256] at column offset ----
__global__ void __launch_bounds__(256) cvt_pair_cols_kernel(const float* __restrict__ in,
                                                            f16* __restrict__ ho, f16* __restrict__ lo,
                                                            int colOff) {
    size_t i = (size_t)blockIdx.x * 256 + threadIdx.x;
    int row = (int)(i >> 5);
    int col = ((int)i & 31) * 4;
    float4 v = ((const float4*)in)[i];
    size_t o = (size_t)row * 256 + colOff + col;
    f16 h0, l0, h1, l1, h2, l2, h3, l3;
    split1(v.x, h0, l0); split1(v.y, h1, l1); split1(v.z, h2, l2); split1(v.w, h3, l3);
    __half2 ha = __halves2half2(h0, h1), hb = __halves2half2(h2, h3);
    __half2 la = __halves2half2(l0, l1), lb = __halves2half2(l2, l3);
    *(uint32_t*)(ho + o)     = *(uint32_t*)&ha;
    *(uint32_t*)(ho + o + 2) = *(uint32_t*)&hb;
    *(uint32_t*)(lo + o)     = *(uint32_t*)&la;
    *(uint32_t*)(lo + o + 2) = *(uint32_t*)&lb;
}

// ---------------- embedding ----------------
__global__ void embed_kernel(const int* __restrict__ tok, const float* __restrict__ emb,
                             float* __restrict__ x) {
    int n = blockIdx.x;
    const float* src = emb + (size_t)tok[n] * DMODEL;
    float* dst = x + (size_t)n * DMODEL;
    for (int d = threadIdx.x; d < DMODEL; d += blockDim.x) dst[d] = src[d];
}

// ---------------- RMSNorm -> fp16 pair ----------------
__global__ void __launch_bounds__(256) rmsnorm_pair_kernel(const float* __restrict__ x,
                                                           const float* __restrict__ gamma,
                                                           f16* __restrict__ oh, f16* __restrict__ ol) {
    int n = blockIdx.x;
    const float* row = x + (size_t)n * DMODEL;
    float s = 0.f;
    for (int d = threadIdx.x; d < DMODEL; d += 256) { float v = row[d]; s += v * v; }
    __shared__ float red[256];
    red[threadIdx.x] = s; __syncthreads();
    #pragma unroll
    for (int k = 128; k > 0; k >>= 1) {
        if (threadIdx.x < k) red[threadIdx.x] += red[threadIdx.x + k];
        __syncthreads();
    }
    float inv = rsqrtf(red[0] * (1.0f / DMODEL) + EPSF);
    for (int d = threadIdx.x; d < DMODEL; d += 256) {
        f16 h, l; split1(row[d] * inv * gamma[d], h, l);
        oh[(size_t)n * DMODEL + d] = h;
        ol[(size_t)n * DMODEL + d] = l;
    }
}

// ---------------- suffixV ----------------
__global__ void __launch_bounds__(128) suffixv_kernel(const float* __restrict__ kv,
                                                      float* __restrict__ suf) {
    const int d = threadIdx.x;
    const int lo = blockIdx.x * 128, hi = lo + 128;
    float acc = 0.f;
    for (int j = NT - 1; j >= hi; --j)
        acc += kv[(size_t)j * 256 + 128 + d];
    for (int i = hi - 1; i >= lo; --i) {
        suf[(size_t)i * DHEAD + d] = acc;
        acc += kv[(size_t)i * 256 + 128 + d];
    }
}

// ------- softmax: visible region exact, masked region rank-1; P scaled x1024 -------
__global__ void __launch_bounds__(256) softmax_kernel(const float* __restrict__ S,
                                                      f16* __restrict__ Ph, f16* __restrict__ Pl,
                                                      float* __restrict__ C) {
    const int i = blockIdx.x, h = blockIdx.y, tid = threadIdx.x;
    const float* row = S + ((size_t)h * NT + i) * NT;
    __shared__ float sc[NT];
    __shared__ float red[256];
    const float slope = exp2f(-0.5f * (float)(h + 1));
    const float scale = 0.08838834764831845f;
    const int tileEnd = ((i >> 7) + 1) << 7;

    float mx = MASKV;
    for (int j = tid; j <= i; j += 256) {
        float v = row[j] * scale + slope * (float)j;
        sc[j] = v;
        mx = fmaxf(mx, v);
    }
    red[tid] = mx; __syncthreads();
    #pragma unroll
    for (int s = 128; s > 0; s >>= 1) {
        if (tid < s) red[tid] = fmaxf(red[tid], red[tid + s]);
        __syncthreads();
    }
    mx = red[0]; __syncthreads();

    float sum = 0.f;
    for (int j = tid; j <= i; j += 256) {
        float p = exp2f((sc[j] - mx) * L2E);
        sc[j] = p; sum += p;
    }
    red[tid] = sum; __syncthreads();
    #pragma unroll
    for (int s = 128; s > 0; s >>= 1) {
        if (tid < s) red[tid] += red[tid + s];
        __syncthreads();
    }
    const float maskexp = exp2f((MASKV - mx) * L2E);
    const float inv = 1.f / (red[0] + (float)(NT - 1 - i) * maskexp);
    const float c = maskexp * inv;
    if (tid == 0) C[(size_t)h * NT + i] = c;

    const float pw = inv * PSCALE;
    f16* ph = Ph + ((size_t)h * NT + i) * NT;
    f16* pl = Pl + ((size_t)h * NT + i) * NT;
    for (int j = tid; j < tileEnd; j += 256) {
        if (j <= i) {
            f16 hh, ll; split1(sc[j] * pw, hh, ll);
            ph[j] = hh; pl[j] = ll;
        } else {
            ph[j] = __float2half_rn(0.f);
            pl[j] = __float2half_rn(0.f);
        }
    }
}

// ================= pipelined fp16-split tensor-core GEMM =================
// PASSES=3: (aH+aL)xbH + aHxbL (err ~2^-22). PASSES=2: (aH+aL)xbH (err ~2^-12).
// EPI: 0 store fp32, 1 fp32 +=, 2 atomicAdd (split-K), 3 fp16 pair store,
//      4 fused attention-out: split(acc*PISCALE + Xa[z*NT+r]*Xb[r*128+c]) -> Ch/Cl,
//      5 fused SwiGLU: split(Xa[r*ldc+c] * silu(acc)) -> Ch/Cl.
// CAUSAL: 0 none; 1 skip tiles with colBase>rowBase; 2 cap K at rowBase+128.
template <int TRANSB, int EPI, int CAUSAL, int PASSES>
__global__ void __launch_bounds__(256, 2)
gemm_hs(const f16* __restrict__ Ah, const f16* __restrict__ Al,
        const f16* __restrict__ Bh, const f16* __restrict__ Bl,
        float* __restrict__ C, f16* __restrict__ Ch, f16* __restrict__ Cl,
        const float* __restrict__ Xa, const float* __restrict__ Xb,
        int M, int N, int K, int lda, int ldb, int ldc,
        int kSplit, size_t aZ, size_t bZ, size_t cZ) {
    extern __shared__ __align__(16) char smem[];
    const int tid = threadIdx.x, lane = tid & 31, warp = tid >> 5;
    const int wm = warp >> 2, wn = warp & 3;
    const int rowBase = blockIdx.y * 128, colBase = blockIdx.x * 128;
    if (CAUSAL == 1 && colBase > rowBase) return;
    const int z = blockIdx.z;
    int kStart = 0, kEnd = K;
    if (CAUSAL == 2) kEnd = rowBase + 128 < K ? rowBase + 128 : K;
    if (kSplit > 1) {
        int kl = K / kSplit; kStart = z * kl; kEnd = kStart + kl;
    } else {
        Ah += z * aZ; Al += z * aZ; Bh += z * bZ; if (PASSES == 3) Bl += z * bZ;
        if (EPI == 3 || EPI == 4 || EPI == 5) { Ch += z * cZ; Cl += z * cZ; }
        else { C += z * cZ; }
    }
    const int nk = (kEnd - kStart) / KT;
    const uint32_t sb = (uint32_t)__cvta_generic_to_shared(smem);
    const int BUFB = TRANSB ? 10240 : 8704;
    const int NB = PASSES - 1;    // B halves per stage

    auto load_stage = [&](int s, int kt) {
        uint32_t aOff = sb + s * 20480;
        uint32_t bOff = sb + 40960 + s * NB * BUFB;
        #pragma unroll
        for (int r = 0; r < 2; ++r) {
            int idx = tid + r * 256;
            int row = idx >> 2, kc = (idx & 3) * 8;
            uint32_t d = aOff + (row * ASTR + kc) * 2;
            const size_t ga = (size_t)(rowBase + row) * lda + kt + kc;
            cpa16(d,         Ah + ga);
            cpa16(d + 10240, Al + ga);
            if (!TRANSB) {
                int kr = idx >> 4, nc = (idx & 15) * 8;
                uint32_t db = bOff + (kr * BSTRN + nc) * 2;
                const size_t gb = (size_t)(kt + kr) * ldb + colBase + nc;
                cpa16(db, Bh + gb);
                if (PASSES == 3) cpa16(db + BUFB, Bl + gb);
            } else {
                int nr = idx >> 2, kc2 = (idx & 3) * 8;
                uint32_t db = bOff + (nr * ASTR + kc2) * 2;
                const size_t gb = (size_t)(colBase + nr) * ldb + kt + kc2;
                cpa16(db, Bh + gb);
                if (PASSES == 3) cpa16(db + BUFB, Bl + gb);
            }
        }
        asm volatile("cp.async.commit_group;");
    };

    float acc[4][4][4];
    #pragma unroll
    for (int i = 0; i < 4; ++i)
        #pragma unroll
        for (int j = 0; j < 4; ++j)
            #pragma unroll
            for (int v = 0; v < 4; ++v) acc[i][j][v] = 0.f;

    const int l15 = lane & 15, lhi = (lane >> 4) * 8;

    load_stage(0, kStart);

    for (int it = 0; it < nk; ++it) {
        const int s = it & 1;
        if (it + 1 < nk) {
            load_stage((it + 1) & 1, kStart + (it + 1) * KT);
            asm volatile("cp.async.wait_group 1;");
        } else {
            asm volatile("cp.async.wait_group 0;");
        }
        __syncthreads();

        const uint32_t aBase = sb + s * 20480 + ((wm * 64 + l15) * ASTR + lhi) * 2;
        const uint32_t bOff  = sb + 40960 + s * NB * BUFB;

        #pragma unroll
        for (int ks = 0; ks < KT; ks += 16) {
            uint32_t aH[4][4], aL[4][4], bH[2][4], bL[2][4];
            #pragma unroll
            for (int mt = 0; mt < 4; ++mt)
                ldsm4(aH[mt], aBase + ks * 2 + mt * (16 * ASTR * 2));
            if (!TRANSB) {
                uint32_t bBase = bOff + ((l15 + ks) * BSTRN + wn * 32 + lhi) * 2;
                #pragma unroll
                for (int p = 0; p < 2; ++p) ldsm4t(bH[p], bBase + p * 32);
            } else {
                #pragma unroll
                for (int p = 0; p < 2; ++p)
                    ldsm4(bH[p], bOff + ((wn * 32 + p * 16 + l15) * ASTR + ks + lhi) * 2);
            }
            #pragma unroll
            for (int mt = 0; mt < 4; ++mt)
                #pragma unroll
                for (int nt = 0; nt < 4; ++nt) {
                    int p = nt >> 1, su = nt & 1;
                    uint32_t b0 = TRANSB ? bH[p][su]     : bH[p][2 * su];
                    uint32_t b1 = TRANSB ? bH[p][su + 2] : bH[p][2 * su + 1];
                    mma16816(acc[mt][nt], aH[mt], b0, b1);
                }
            if (PASSES == 3) {
                if (!TRANSB) {
                    uint32_t bBase = bOff + BUFB + ((l15 + ks) * BSTRN + wn * 32 + lhi) * 2;
                    #pragma unroll
                    for (int p = 0; p < 2; ++p) ldsm4t(bL[p], bBase + p * 32);
                } else {
                    #pragma unroll
                    for (int p = 0; p < 2; ++p)
                        ldsm4(bL[p], bOff + BUFB + ((wn * 32 + p * 16 + l15) * ASTR + ks + lhi) * 2);
                }
                #pragma unroll
                for (int mt = 0; mt < 4; ++mt)
                    #pragma unroll
                    for (int nt = 0; nt < 4; ++nt) {
                        int p = nt >> 1, su = nt & 1;
                        uint32_t b0 = TRANSB ? bL[p][su]     : bL[p][2 * su];
                        uint32_t b1 = TRANSB ? bL[p][su + 2] : bL[p][2 * su + 1];
                        mma16816(acc[mt][nt], aH[mt], b0, b1);
                    }
            }
            #pragma unroll
            for (int mt = 0; mt < 4; ++mt)
                ldsm4(aL[mt], aBase + 10240 + ks * 2 + mt * (16 * ASTR * 2));
            #pragma unroll
            for (int mt = 0; mt < 4; ++mt)
                #pragma unroll
                for (int nt = 0; nt < 4; ++nt) {
                    int p = nt >> 1, su = nt & 1;
                    uint32_t b0 = TRANSB ? bH[p][su]     : bH[p][2 * su];
                    uint32_t b1 = TRANSB ? bH[p][su + 2] : bH[p][2 * su + 1];
                    mma16816(acc[mt][nt], aL[mt], b0, b1);
                }
        }
        __syncthreads();
    }

    // ---------- epilogue ----------
    const int r0 = rowBase + wm * 64 + (lane >> 2);
    const int c0 = colBase + wn * 32 + (lane & 3) * 2;
    #pragma unroll
    for (int mt = 0; mt < 4; ++mt) {
        #pragma unroll
        for (int nt = 0; nt < 4; ++nt) {
            int r = r0 + mt * 16, c = c0 + nt * 8;
            if (EPI == 4) {
                float ca = Xa[(size_t)z * NT + r];
                float cb = Xa[(size_t)z * NT + r + 8];
                float v0 = acc[mt][nt][0] * PISCALE + ca * Xb[(size_t)r * DHEAD + c];
                float v1 = acc[mt][nt][1] * PISCALE + ca * Xb[(size_t)r * DHEAD + c + 1];
                float v2 = acc[mt][nt][2] * PISCALE + cb * Xb[(size_t)(r + 8) * DHEAD + c];
                float v3 = acc[mt][nt][3] * PISCALE + cb * Xb[(size_t)(r + 8) * DHEAD + c + 1];
                split2_store(Ch + (size_t)r * ldc + c,       Cl + (size_t)r * ldc + c,       v0, v1);
                split2_store(Ch + (size_t)(r + 8) * ldc + c, Cl + (size_t)(r + 8) * ldc + c, v2, v3);
            } else if (EPI == 5) {
                float v0 = silu_mul(Xa[(size_t)r * ldc + c],           acc[mt][nt][0]);
                float v1 = silu_mul(Xa[(size_t)r * ldc + c + 1],       acc[mt][nt][1]);
                float v2 = silu_mul(Xa[(size_t)(r + 8) * ldc + c],     acc[mt][nt][2]);
                float v3 = silu_mul(Xa[(size_t)(r + 8) * ldc + c + 1], acc[mt][nt][3]);
                split2_store(Ch + (size_t)r * ldc + c,       Cl + (size_t)r * ldc + c,       v0, v1);
                split2_store(Ch + (size_t)(r + 8) * ldc + c, Cl + (size_t)(r + 8) * ldc + c, v2, v3);
            } else if (EPI == 3) {
                split2_store(Ch + (size_t)r * ldc + c,       Cl + (size_t)r * ldc + c,
                             acc[mt][nt][0], acc[mt][nt][1]);
                split2_store(Ch + (size_t)(r + 8) * ldc + c, Cl + (size_t)(r + 8) * ldc + c,
                             acc[mt][nt][2], acc[mt][nt][3]);
            } else if (EPI == 2) {
                atomicAdd(C + (size_t)r * ldc + c,           acc[mt][nt][0]);
                atomicAdd(C + (size_t)r * ldc + c + 1,       acc[mt][nt][1]);
                atomicAdd(C + (size_t)(r + 8) * ldc + c,     acc[mt][nt][2]);
                atomicAdd(C + (size_t)(r + 8) * ldc + c + 1, acc[mt][nt][3]);
            } else {
                float2* p0 = (float2*)(C + (size_t)r * ldc + c);
                float2* p1 = (float2*)(C + (size_t)(r + 8) * ldc + c);
                if (EPI == 1) {
                    float2 t0 = *p0, t1 = *p1;
                    t0.x += acc[mt][nt][0]; t0.y += acc[mt][nt][1];
                    t1.x += acc[mt][nt][2]; t1.y += acc[mt][nt][3];
                    *p0 = t0; *p1 = t1;
                } else {
                    *p0 = make_float2(acc[mt][nt][0], acc[mt][nt][1]);
                    *p1 = make_float2(acc[mt][nt][2], acc[mt][nt][3]);
                }
            }
        }
    }
}

// ---------------- host-side dispatch ----------------
template <int TRANSB, int EPI, int CAUSAL, int PASSES>
static void launch_gemm(const f16* Ah, const f16* Al, const f16* Bh, const f16* Bl,
                        float* C, f16* Ch, f16* Cl,
                        const float* Xa, const float* Xb,
                        int M, int N, int K, int lda, int ldb, int ldc,
                        int Z, int kSplit, size_t aZ, size_t bZ, size_t cZ) {
    const int smem = 40960 + 2 * (PASSES - 1) * (TRANSB ? 10240 : 8704);
    cudaFuncSetAttribute(gemm_hs<TRANSB, EPI, CAUSAL, PASSES>,
                         cudaFuncAttributeMaxDynamicSharedMemorySize, smem);
    dim3 grid(N / 128, M / 128, Z);
    gemm_hs<TRANSB, EPI, CAUSAL, PASSES><<<grid, 256, smem>>>(Ah, Al, Bh, Bl, C, Ch, Cl,
                                                              Xa, Xb,
                                                              M, N, K, lda, ldb, ldc,
                                                              kSplit, aZ, bZ, cZ);
}

extern "C" void kernel_launch(void* const* d_in, const int* in_sizes, int n_in,
                              void* d_out, int out_size) {
    const int*   tokens      = (const int*)  d_in[0];
    const float* emb         = (const float*)d_in[1];
    const float* attn_gamma  = (const float*)d_in[2];
    const float* wq          = (const float*)d_in[3];
    const float* wk          = (const float*)d_in[4];
    const float* wv          = (const float*)d_in[5];
    const float* wo          = (const float*)d_in[6];
    const float* ff_gamma    = (const float*)d_in[7];
    const float* wi          = (const float*)d_in[8];
    const float* wg          = (const float*)d_in[9];
    const float* wfo         = (const float*)d_in[10];
    const float* final_gamma = (const float*)d_in[11];
    float* out = (float*)d_out;

    float *x, *kv, *suf, *c, *S, *f1;
    f16 *hh, *hl, *qh, *ql, *kvh, *kvl, *Ph, *Pl, *aoh, *aol, *f1h, *f1l;
    f16 *Wqh, *Wql, *Wkvh, *Wkvl, *Woh, *Wih, *Wgh, *Wfoh, *Weh;
    cudaGetSymbolAddress((void**)&x,    g_x);
    cudaGetSymbolAddress((void**)&hh,   g_hh);  cudaGetSymbolAddress((void**)&hl,  g_hl);
    cudaGetSymbolAddress((void**)&qh,   g_qh);  cudaGetSymbolAddress((void**)&ql,  g_ql);
    cudaGetSymbolAddress((void**)&kv,   g_kv);
    cudaGetSymbolAddress((void**)&kvh,  g_kvh); cudaGetSymbolAddress((void**)&kvl, g_kvl);
    cudaGetSymbolAddress((void**)&suf,  g_suf); cudaGetSymbolAddress((void**)&c,   g_c);
    cudaGetSymbolAddress((void**)&S,    g_S);
    cudaGetSymbolAddress((void**)&Ph,   g_Ph);  cudaGetSymbolAddress((void**)&Pl,  g_Pl);
    cudaGetSymbolAddress((void**)&aoh,  g_aoh); cudaGetSymbolAddress((void**)&aol, g_aol);
    cudaGetSymbolAddress((void**)&f1,   g_f1);
    cudaGetSymbolAddress((void**)&f1h,  g_f1h); cudaGetSymbolAddress((void**)&f1l, g_f1l);
    cudaGetSymbolAddress((void**)&Wqh,  w_qh);  cudaGetSymbolAddress((void**)&Wql, w_ql);
    cudaGetSymbolAddress((void**)&Wkvh, w_kvh); cudaGetSymbolAddress((void**)&Wkvl, w_kvl);
    cudaGetSymbolAddress((void**)&Woh,  w_oh);
    cudaGetSymbolAddress((void**)&Wih,  w_ih);
    cudaGetSymbolAddress((void**)&Wgh,  w_gh);
    cudaGetSymbolAddress((void**)&Wfoh, w_foh);
    cudaGetSymbolAddress((void**)&Weh,  w_eh);

    auto cvtp = [](const float* in, f16* h, f16* l, size_t n) {
        cvt_pair_kernel<<<(unsigned)(n / 1024), 256>>>(in, h, l);
    };
    auto cvts = [](const float* in, f16* h, size_t n) {
        cvt_half_kernel<<<(unsigned)(n / 1024), 256>>>(in, h);
    };

    // ---- weight pre-split (captured; runs each replay) ----
    cvtp(wq,  Wqh,  Wql, (size_t)NLAYER * DMODEL * INNERD);
    cvts(wo,  Woh,  (size_t)NLAYER * INNERD * DMODEL);
    cvts(wi,  Wih,  (size_t)NLAYER * DMODEL * FFI);
    cvts(wg,  Wgh,  (size_t)NLAYER * DMODEL * FFI);
    cvts(wfo, Wfoh, (size_t)NLAYER * FFI * DMODEL);
    cvts(emb, Weh,  (size_t)VOCAB * DMODEL);
    for (int l = 0; l < NLAYER; ++l) {
        const size_t okv = (size_t)l * DMODEL * DHEAD;
        const size_t okvW = (size_t)l * DMODEL * 256;
        cvt_pair_cols_kernel<<<(DMODEL * DHEAD) / 1024, 256>>>(wk + okv, Wkvh + okvW, Wkvl + okvW, 0);
        cvt_pair_cols_kernel<<<(DMODEL * DHEAD) / 1024, 256>>>(wv + okv, Wkvh + okvW, Wkvl + okvW, 128);
    }

    embed_kernel<<<NT, 256>>>(tokens, emb, x);

    for (int l = 0; l < NLAYER; ++l) {
        const size_t oq   = (size_t)l * DMODEL * INNERD;
        const size_t okvW = (size_t)l * DMODEL * 256;
        const size_t oi   = (size_t)l * DMODEL * FFI;
        const size_t ofo  = (size_t)l * FFI * DMODEL;

        // --- attention ---
        rmsnorm_pair_kernel<<<NT, 256>>>(x, attn_gamma + (size_t)l * DMODEL, hh, hl);
        // q projection: full 3-pass (feeds S)
        launch_gemm<0, 3, 0, 3>(hh, hl, Wqh + oq, Wql + oq, nullptr, qh, ql, nullptr, nullptr,
                                NT, INNERD, DMODEL, DMODEL, INNERD, INNERD, 1, 1, 0, 0, 0);
        cudaMemsetAsync(kv, 0, NT * 256 * sizeof(float));
        // kv projection: full 3-pass, split-K 8
        launch_gemm<0, 2, 0, 3>(hh, hl, Wkvh + okvW, Wkvl + okvW, kv, nullptr, nullptr, nullptr, nullptr,
                                NT, 256, DMODEL, DMODEL, 256, 256, 8, 8, 0, 0, 0);
        cvtp(kv, kvh, kvl, (size_t)NT * 256);
        suffixv_kernel<<<NT / 128, 128>>>(kv, suf);
        // S = Q K^T: 3-pass, causal-skip upper tiles
        launch_gemm<1, 0, 1, 3>(qh, ql, kvh, kvl, S, nullptr, nullptr, nullptr, nullptr,
                                NT, NT, DHEAD, INNERD, 256, NT,
                                NHEAD, 1, (size_t)DHEAD, 0, (size_t)NT * NT);
        softmax_kernel<<<dim3(NT, NHEAD), 256>>>(S, Ph, Pl, c);
        // PV: 2-pass, K capped at diagonal, FUSED ao-fix epilogue -> aoh/aol
        launch_gemm<0, 4, 2, 2>(Ph, Pl, kvh + 128, nullptr, nullptr, aoh, aol, c, suf,
                                NT, DHEAD, NT, NT, 256, INNERD,
                                NHEAD, 1, (size_t)NT * NT, 0, (size_t)DHEAD);
        // output projection: 2-pass, accumulate into x
        launch_gemm<0, 1, 0, 2>(aoh, aol, Woh + oq, nullptr, x, nullptr, nullptr, nullptr, nullptr,
                                NT, DMODEL, INNERD, INNERD, DMODEL, DMODEL, 1, 1, 0, 0, 0);

        // --- SwiGLU FFN: all 2-pass; silu fused into wg epilogue ---
        rmsnorm_pair_kernel<<<NT, 256>>>(x, ff_gamma + (size_t)l * DMODEL, hh, hl);
        launch_gemm<0, 0, 0, 2>(hh, hl, Wih + oi, nullptr, f1, nullptr, nullptr, nullptr, nullptr,
                                NT, FFI, DMODEL, DMODEL, FFI, FFI, 1, 1, 0, 0, 0);
        launch_gemm<0, 5, 0, 2>(hh, hl, Wgh + oi, nullptr, nullptr, f1h, f1l, f1, nullptr,
                                NT, FFI, DMODEL, DMODEL, FFI, FFI, 1, 1, 0, 0, 0);
        launch_gemm<0, 1, 0, 2>(f1h, f1l, Wfoh + ofo, nullptr, x, nullptr, nullptr, nullptr, nullptr,
                                NT, DMODEL, FFI, FFI, DMODEL, DMODEL, 1, 1, 0, 0, 0);
    }

    // --- final norm + tied-embedding logits: 2-pass TN ---
    rmsnorm_pair_kernel<<<NT, 256>>>(x, final_gamma, hh, hl);
    launch_gemm<1, 0, 0, 2>(hh, hl, Weh, nullptr, out, nullptr, nullptr, nullptr, nullptr,
                            NT, VOCAB, DMODEL, DMODEL, DMODEL, VOCAB, 1, 1, 0, 0, 0);
}

// round 14
// speedup vs baseline: 1.5233x; 1.0887x over previous
#include <cuda_runtime.h>
#include <cuda_fp16.h>
#include <cstdint>
#include <math.h>

#define NT      2048
#define DMODEL  2048
#define NHEAD   16
#define DHEAD   128
#define INNERD  2048
#define FFI     8192
#define VOCAB   32000
#define NLAYER  4
#define EPSF    1e-5f
#define MASKV   1e-10f
#define BSTRN   136    // [k][n] smem stride (elems) for NN B tiles
#define L2E     1.4426950408889634f
#define PSCALE  1024.0f
#define PISCALE 9.765625e-4f

typedef __half f16;

// ---------------- scratch (static device globals; no allocations) ----------------
__device__ float g_x [NT * DMODEL];
__device__ f16   g_hh[NT * DMODEL], g_hl[NT * DMODEL];
__device__ f16   g_qh[NT * INNERD], g_ql[NT * INNERD];
__device__ float g_kv [NT * 256];
__device__ f16   g_kvh[NT * 256], g_kvl[NT * 256];      // K pair; V uses hi half only
__device__ float g_suf[NT * DHEAD];
__device__ float g_c  [NHEAD * NT];
__device__ float g_S [(size_t)NHEAD * NT * NT];
__device__ f16   g_Ph[(size_t)NHEAD * NT * NT], g_Pl[(size_t)NHEAD * NT * NT];
__device__ f16   g_aoh[NT * INNERD], g_aol[NT * INNERD];
__device__ float g_f1[NT * FFI];
__device__ f16   g_f1h[NT * FFI], g_f1l[NT * FFI];
// weights: pairs for precision-critical (q, kv); singles for 2-pass path
__device__ f16 w_qh [NLAYER * DMODEL * INNERD], w_ql [NLAYER * DMODEL * INNERD];
__device__ f16 w_kvh[NLAYER * DMODEL * 256],    w_kvl[NLAYER * DMODEL * 256];
__device__ f16 w_oh [NLAYER * INNERD * DMODEL];
__device__ f16 w_ih [(size_t)NLAYER * DMODEL * FFI];
__device__ f16 w_gh [(size_t)NLAYER * DMODEL * FFI];
__device__ f16 w_foh[(size_t)NLAYER * FFI * DMODEL];
__device__ f16 w_eh [(size_t)VOCAB * DMODEL];

// ---------------- helpers ----------------
__device__ __forceinline__ void cpa16(uint32_t dst, const void* src) {
    asm volatile("cp.async.cg.shared.global [%0],[%1],16;" :: "r"(dst), "l"(src));
}
__device__ __forceinline__ void ldsm4(uint32_t* r, uint32_t a) {
    asm volatile("ldmatrix.sync.aligned.m8n8.x4.shared.b16 {%0,%1,%2,%3},[%4];"
                 : "=r"(r[0]), "=r"(r[1]), "=r"(r[2]), "=r"(r[3]) : "r"(a));
}
__device__ __forceinline__ void ldsm4t(uint32_t* r, uint32_t a) {
    asm volatile("ldmatrix.sync.aligned.m8n8.x4.trans.shared.b16 {%0,%1,%2,%3},[%4];"
                 : "=r"(r[0]), "=r"(r[1]), "=r"(r[2]), "=r"(r[3]) : "r"(a));
}
__device__ __forceinline__ void mma16816(float* c, const uint32_t* a, uint32_t b0, uint32_t b1) {
    asm volatile("mma.sync.aligned.m16n8k16.row.col.f32.f16.f16.f32 "
                 "{%0,%1,%2,%3},{%4,%5,%6,%7},{%8,%9},{%0,%1,%2,%3};"
                 : "+f"(c[0]), "+f"(c[1]), "+f"(c[2]), "+f"(c[3])
                 : "r"(a[0]), "r"(a[1]), "r"(a[2]), "r"(a[3]), "r"(b0), "r"(b1));
}
__device__ __forceinline__ void split1(float a, f16& h, f16& l) {
    h = __float2half_rn(a);
    l = __float2half_rn(a - __half2float(h));
}
__device__ __forceinline__ void split2_store(f16* hp, f16* lp, float a, float b) {
    f16 ha = __float2half_rn(a), hb = __float2half_rn(b);
    f16 la = __float2half_rn(a - __half2float(ha));
    f16 lb = __float2half_rn(b - __half2float(hb));
    __half2 H = __halves2half2(ha, hb);
    __half2 L = __halves2half2(la, lb);
    *(uint32_t*)hp = *(uint32_t*)&H;
    *(uint32_t*)lp = *(uint32_t*)&L;
}
__device__ __forceinline__ float silu_mul(float a, float g) {
    return a * g / (1.f + __expf(-g));
}

// ---------------- fp32 -> fp16 pair ----------------
__global__ void __launch_bounds__(256) cvt_pair_kernel(const float* __restrict__ in,
                                                       f16* __restrict__ ho, f16* __restrict__ lo) {
    size_t i = (size_t)blockIdx.x * 256 + threadIdx.x;
    float4 v = ((const float4*)in)[i];
    f16 h0, l0, h1, l1, h2, l2, h3, l3;
    split1(v.x, h0, l0); split1(v.y, h1, l1); split1(v.z, h2, l2); split1(v.w, h3, l3);
    __half2 ha = __halves2half2(h0, h1), hb = __halves2half2(h2, h3);
    __half2 la = __halves2half2(l0, l1), lb = __halves2half2(l2, l3);
    uint2 H = {*(uint32_t*)&ha, *(uint32_t*)&hb};
    uint2 L = {*(uint32_t*)&la, *(uint32_t*)&lb};
    ((uint2*)ho)[i] = H;
    ((uint2*)lo)[i] = L;
}

// ---------------- fp32 -> fp16 single ----------------
__global__ void __launch_bounds__(256) cvt_half_kernel(const float* __restrict__ in,
                                                       f16* __restrict__ out) {
    size_t i = (size_t)blockIdx.x * 256 + threadIdx.x;
    float4 v = ((const float4*)in)[i];
    __half2 a = __floats2half2_rn(v.x, v.y);
    __half2 b = __floats2half2_rn(v.z, v.w);
    uint2 o = {*(uint32_t*)&a, *(uint32_t*)&b};
    ((uint2*)out)[i] = o;
}

// ---- strided pair cvt: in [R,128] -> out [R,256] at column offset ----
__global__ void __launch_bounds__(256) cvt_pair_cols_kernel(const float* __restrict__ in,
                                                            f16* __restrict__ ho, f16* __restrict__ lo,
                                                            int colOff) {
    size_t i = (size_t)blockIdx.x * 256 + threadIdx.x;
    int row = (int)(i >> 5);
    int col = ((int)i & 31) * 4;
    float4 v = ((const float4*)in)[i];
    size_t o = (size_t)row * 256 + colOff + col;
    f16 h0, l0, h1, l1, h2, l2, h3, l3;
    split1(v.x, h0, l0); split1(v.y, h1, l1); split1(v.z, h2, l2); split1(v.w, h3, l3);
    __half2 ha = __halves2half2(h0, h1), hb = __halves2half2(h2, h3);
    __half2 la = __halves2half2(l0, l1), lb = __halves2half2(l2, l3);
    *(uint32_t*)(ho + o)     = *(uint32_t*)&ha;
    *(uint32_t*)(ho + o + 2) = *(uint32_t*)&hb;
    *(uint32_t*)(lo + o)     = *(uint32_t*)&la;
    *(uint32_t*)(lo + o + 2) = *(uint32_t*)&lb;
}

// ---------------- embedding ----------------
__global__ void embed_kernel(const int* __restrict__ tok, const float* __restrict__ emb,
                             float* __restrict__ x) {
    int n = blockIdx.x;
    const float* src = emb + (size_t)tok[n] * DMODEL;
    float* dst = x + (size_t)n * DMODEL;
    for (int d = threadIdx.x; d < DMODEL; d += blockDim.x) dst[d] = src[d];
}

// ---------------- RMSNorm -> fp16 pair ----------------
__global__ void __launch_bounds__(256) rmsnorm_pair_kernel(const float* __restrict__ x,
                                                           const float* __restrict__ gamma,
                                                           f16* __restrict__ oh, f16* __restrict__ ol) {
    int n = blockIdx.x;
    const float* row = x + (size_t)n * DMODEL;
    float s = 0.f;
    for (int d = threadIdx.x; d < DMODEL; d += 256) { float v = row[d]; s += v * v; }
    __shared__ float red[256];
    red[threadIdx.x] = s; __syncthreads();
    #pragma unroll
    for (int k = 128; k > 0; k >>= 1) {
        if (threadIdx.x < k) red[threadIdx.x] += red[threadIdx.x + k];
        __syncthreads();
    }
    float inv = rsqrtf(red[0] * (1.0f / DMODEL) + EPSF);
    for (int d = threadIdx.x; d < DMODEL; d += 256) {
        f16 h, l; split1(row[d] * inv * gamma[d], h, l);
        oh[(size_t)n * DMODEL + d] = h;
        ol[(size_t)n * DMODEL + d] = l;
    }
}

// ---------------- suffixV ----------------
__global__ void __launch_bounds__(128) suffixv_kernel(const float* __restrict__ kv,
                                                      float* __restrict__ suf) {
    const int d = threadIdx.x;
    const int lo = blockIdx.x * 128, hi = lo + 128;
    float acc = 0.f;
    for (int j = NT - 1; j >= hi; --j)
        acc += kv[(size_t)j * 256 + 128 + d];
    for (int i = hi - 1; i >= lo; --i) {
        suf[(size_t)i * DHEAD + d] = acc;
        acc += kv[(size_t)i * 256 + 128 + d];
    }
}

// ------- softmax: visible region exact, masked region rank-1; P scaled x1024 -------
__global__ void __launch_bounds__(256) softmax_kernel(const float* __restrict__ S,
                                                      f16* __restrict__ Ph, f16* __restrict__ Pl,
                                                      float* __restrict__ C) {
    const int i = blockIdx.x, h = blockIdx.y, tid = threadIdx.x;
    const float* row = S + ((size_t)h * NT + i) * NT;
    __shared__ float sc[NT];
    __shared__ float red[256];
    const float slope = exp2f(-0.5f * (float)(h + 1));
    const float scale = 0.08838834764831845f;
    const int tileEnd = ((i >> 7) + 1) << 7;

    float mx = MASKV;
    for (int j = tid; j <= i; j += 256) {
        float v = row[j] * scale + slope * (float)j;
        sc[j] = v;
        mx = fmaxf(mx, v);
    }
    red[tid] = mx; __syncthreads();
    #pragma unroll
    for (int s = 128; s > 0; s >>= 1) {
        if (tid < s) red[tid] = fmaxf(red[tid], red[tid + s]);
        __syncthreads();
    }
    mx = red[0]; __syncthreads();

    float sum = 0.f;
    for (int j = tid; j <= i; j += 256) {
        float p = exp2f((sc[j] - mx) * L2E);
        sc[j] = p; sum += p;
    }
    red[tid] = sum; __syncthreads();
    #pragma unroll
    for (int s = 128; s > 0; s >>= 1) {
        if (tid < s) red[tid] += red[tid + s];
        __syncthreads();
    }
    const float maskexp = exp2f((MASKV - mx) * L2E);
    const float inv = 1.f / (red[0] + (float)(NT - 1 - i) * maskexp);
    const float c = maskexp * inv;
    if (tid == 0) C[(size_t)h * NT + i] = c;

    const float pw = inv * PSCALE;
    f16* ph = Ph + ((size_t)h * NT + i) * NT;
    f16* pl = Pl + ((size_t)h * NT + i) * NT;
    for (int j = tid; j < tileEnd; j += 256) {
        if (j <= i) {
            f16 hh, ll; split1(sc[j] * pw, hh, ll);
            ph[j] = hh; pl[j] = ll;
        } else {
            ph[j] = __float2half_rn(0.f);
            pl[j] = __float2half_rn(0.f);
        }
    }
}

// ================= pipelined fp16-split tensor-core GEMM =================
// PASSES=3: (aH+aL)xbH + aHxbL (err ~2^-22). PASSES=2: (aH+aL)xbH (err ~2^-12).
// KTT: k-tile depth (32 or 64). EPI: 0 fp32, 1 fp32 +=, 2 atomicAdd, 3 pair,
//      4 fused attn-out (acc*PISCALE + Xa[z*NT+r]*Xb[r*128+c]), 5 fused SwiGLU.
// CAUSAL: 0 none; 1 skip tiles with colBase>rowBase; 2 cap K at rowBase+128.
template <int TRANSB, int EPI, int CAUSAL, int PASSES, int KTT>
__global__ void __launch_bounds__(256, 2)
gemm_hs(const f16* __restrict__ Ah, const f16* __restrict__ Al,
        const f16* __restrict__ Bh, const f16* __restrict__ Bl,
        float* __restrict__ C, f16* __restrict__ Ch, f16* __restrict__ Cl,
        const float* __restrict__ Xa, const float* __restrict__ Xb,
        int M, int N, int K, int lda, int ldb, int ldc,
        int kSplit, size_t aZ, size_t bZ, size_t cZ) {
    extern __shared__ __align__(16) char smem[];
    const int tid = threadIdx.x, lane = tid & 31, warp = tid >> 5;
    const int wm = warp >> 2, wn = warp & 3;
    const int rowBase = blockIdx.y * 128, colBase = blockIdx.x * 128;
    if (CAUSAL == 1 && colBase > rowBase) return;
    const int z = blockIdx.z;
    int kStart = 0, kEnd = K;
    if (CAUSAL == 2) kEnd = rowBase + 128 < K ? rowBase + 128 : K;
    if (kSplit > 1) {
        int kl = K / kSplit; kStart = z * kl; kEnd = kStart + kl;
    } else {
        Ah += z * aZ; Al += z * aZ; Bh += z * bZ; if (PASSES == 3) Bl += z * bZ;
        if (EPI == 3 || EPI == 4 || EPI == 5) { Ch += z * cZ; Cl += z * cZ; }
        else { C += z * cZ; }
    }
    const int nk = (kEnd - kStart) / KTT;
    const uint32_t sb = (uint32_t)__cvta_generic_to_shared(smem);
    constexpr int ASTRT  = KTT + 8;                 // conflict-free ldsm stride
    constexpr int AHALF  = 128 * ASTRT * 2;         // bytes, one A half-tile
    constexpr int ASTAGE = 2 * AHALF;               // Ah+Al per stage
    constexpr int BUFB   = TRANSB ? 128 * ASTRT * 2 : KTT * BSTRN * 2;
    constexpr int NB     = PASSES - 1;              // B halves per stage
    constexpr int NLD    = KTT / 16;                // cpa16 rounds per tile

    auto load_stage = [&](int s, int kt) {
        uint32_t aOff = sb + s * ASTAGE;
        uint32_t bOff = sb + 2 * ASTAGE + s * NB * BUFB;
        #pragma unroll
        for (int r = 0; r < NLD; ++r) {
            int idx = tid + r * 256;
            int row = idx / (KTT / 8), kc = (idx % (KTT / 8)) * 8;
            uint32_t d = aOff + (row * ASTRT + kc) * 2;
            const size_t ga = (size_t)(rowBase + row) * lda + kt + kc;
            cpa16(d,         Ah + ga);
            cpa16(d + AHALF, Al + ga);
            if (!TRANSB) {
                int kr = idx >> 4, nc = (idx & 15) * 8;
                uint32_t db = bOff + (kr * BSTRN + nc) * 2;
                const size_t gb = (size_t)(kt + kr) * ldb + colBase + nc;
                cpa16(db, Bh + gb);
                if (PASSES == 3) cpa16(db + BUFB, Bl + gb);
            } else {
                int nr = idx / (KTT / 8), kc2 = (idx % (KTT / 8)) * 8;
                uint32_t db = bOff + (nr * ASTRT + kc2) * 2;
                const size_t gb = (size_t)(colBase + nr) * ldb + kt + kc2;
                cpa16(db, Bh + gb);
                if (PASSES == 3) cpa16(db + BUFB, Bl + gb);
            }
        }
        asm volatile("cp.async.commit_group;");
    };

    float acc[4][4][4];
    #pragma unroll
    for (int i = 0; i < 4; ++i)
        #pragma unroll
        for (int j = 0; j < 4; ++j)
            #pragma unroll
            for (int v = 0; v < 4; ++v) acc[i][j][v] = 0.f;

    const int l15 = lane & 15, lhi = (lane >> 4) * 8;

    load_stage(0, kStart);

    for (int it = 0; it < nk; ++it) {
        const int s = it & 1;
        if (it + 1 < nk) {
            load_stage((it + 1) & 1, kStart + (it + 1) * KTT);
            asm volatile("cp.async.wait_group 1;");
        } else {
            asm volatile("cp.async.wait_group 0;");
        }
        __syncthreads();

        const uint32_t aBase = sb + s * ASTAGE + ((wm * 64 + l15) * ASTRT + lhi) * 2;
        const uint32_t bOff  = sb + 2 * ASTAGE + s * NB * BUFB;

        #pragma unroll
        for (int ks = 0; ks < KTT; ks += 16) {
            uint32_t aH[4][4], aL[4][4], bH[2][4], bL[2][4];
            #pragma unroll
            for (int mt = 0; mt < 4; ++mt)
                ldsm4(aH[mt], aBase + ks * 2 + mt * (16 * ASTRT * 2));
            if (!TRANSB) {
                uint32_t bBase = bOff + ((l15 + ks) * BSTRN + wn * 32 + lhi) * 2;
                #pragma unroll
                for (int p = 0; p < 2; ++p) ldsm4t(bH[p], bBase + p * 32);
            } else {
                #pragma unroll
                for (int p = 0; p < 2; ++p)
                    ldsm4(bH[p], bOff + ((wn * 32 + p * 16 + l15) * ASTRT + ks + lhi) * 2);
            }
            #pragma unroll
            for (int mt = 0; mt < 4; ++mt)
                #pragma unroll
                for (int nt = 0; nt < 4; ++nt) {
                    int p = nt >> 1, su = nt & 1;
                    uint32_t b0 = TRANSB ? bH[p][su]     : bH[p][2 * su];
                    uint32_t b1 = TRANSB ? bH[p][su + 2] : bH[p][2 * su + 1];
                    mma16816(acc[mt][nt], aH[mt], b0, b1);
                }
            if (PASSES == 3) {
                if (!TRANSB) {
                    uint32_t bBase = bOff + BUFB + ((l15 + ks) * BSTRN + wn * 32 + lhi) * 2;
                    #pragma unroll
                    for (int p = 0; p < 2; ++p) ldsm4t(bL[p], bBase + p * 32);
                } else {
                    #pragma unroll
                    for (int p = 0; p < 2; ++p)
                        ldsm4(bL[p], bOff + BUFB + ((wn * 32 + p * 16 + l15) * ASTRT + ks + lhi) * 2);
                }
                #pragma unroll
                for (int mt = 0; mt < 4; ++mt)
                    #pragma unroll
                    for (int nt = 0; nt < 4; ++nt) {
                        int p = nt >> 1, su = nt & 1;
                        uint32_t b0 = TRANSB ? bL[p][su]     : bL[p][2 * su];
                        uint32_t b1 = TRANSB ? bL[p][su + 2] : bL[p][2 * su + 1];
                        mma16816(acc[mt][nt], aH[mt], b0, b1);
                    }
            }
            #pragma unroll
            for (int mt = 0; mt < 4; ++mt)
                ldsm4(aL[mt], aBase + AHALF + ks * 2 + mt * (16 * ASTRT * 2));
            #pragma unroll
            for (int mt = 0; mt < 4; ++mt)
                #pragma unroll
                for (int nt = 0; nt < 4; ++nt) {
                    int p = nt >> 1, su = nt & 1;
                    uint32_t b0 = TRANSB ? bH[p][su]     : bH[p][2 * su];
                    uint32_t b1 = TRANSB ? bH[p][su + 2] : bH[p][2 * su + 1];
                    mma16816(acc[mt][nt], aL[mt], b0, b1);
                }
        }
        __syncthreads();
    }

    // ---------- epilogue ----------
    const int r0 = rowBase + wm * 64 + (lane >> 2);
    const int c0 = colBase + wn * 32 + (lane & 3) * 2;
    #pragma unroll
    for (int mt = 0; mt < 4; ++mt) {
        #pragma unroll
        for (int nt = 0; nt < 4; ++nt) {
            int r = r0 + mt * 16, c = c0 + nt * 8;
            if (EPI == 4) {
                float ca = Xa[(size_t)z * NT + r];
                float cb = Xa[(size_t)z * NT + r + 8];
                float v0 = acc[mt][nt][0] * PISCALE + ca * Xb[(size_t)r * DHEAD + c];
                float v1 = acc[mt][nt][1] * PISCALE + ca * Xb[(size_t)r * DHEAD + c + 1];
                float v2 = acc[mt][nt][2] * PISCALE + cb * Xb[(size_t)(r + 8) * DHEAD + c];
                float v3 = acc[mt][nt][3] * PISCALE + cb * Xb[(size_t)(r + 8) * DHEAD + c + 1];
                split2_store(Ch + (size_t)r * ldc + c,       Cl + (size_t)r * ldc + c,       v0, v1);
                split2_store(Ch + (size_t)(r + 8) * ldc + c, Cl + (size_t)(r + 8) * ldc + c, v2, v3);
            } else if (EPI == 5) {
                float v0 = silu_mul(Xa[(size_t)r * ldc + c],           acc[mt][nt][0]);
                float v1 = silu_mul(Xa[(size_t)r * ldc + c + 1],       acc[mt][nt][1]);
                float v2 = silu_mul(Xa[(size_t)(r + 8) * ldc + c],     acc[mt][nt][2]);
                float v3 = silu_mul(Xa[(size_t)(r + 8) * ldc + c + 1], acc[mt][nt][3]);
                split2_store(Ch + (size_t)r * ldc + c,       Cl + (size_t)r * ldc + c,       v0, v1);
                split2_store(Ch + (size_t)(r + 8) * ldc + c, Cl + (size_t)(r + 8) * ldc + c, v2, v3);
            } else if (EPI == 3) {
                split2_store(Ch + (size_t)r * ldc + c,       Cl + (size_t)r * ldc + c,
                             acc[mt][nt][0], acc[mt][nt][1]);
                split2_store(Ch + (size_t)(r + 8) * ldc + c, Cl + (size_t)(r + 8) * ldc + c,
                             acc[mt][nt][2], acc[mt][nt][3]);
            } else if (EPI == 2) {
                atomicAdd(C + (size_t)r * ldc + c,           acc[mt][nt][0]);
                atomicAdd(C + (size_t)r * ldc + c + 1,       acc[mt][nt][1]);
                atomicAdd(C + (size_t)(r + 8) * ldc + c,     acc[mt][nt][2]);
                atomicAdd(C + (size_t)(r + 8) * ldc + c + 1, acc[mt][nt][3]);
            } else {
                float2* p0 = (float2*)(C + (size_t)r * ldc + c);
                float2* p1 = (float2*)(C + (size_t)(r + 8) * ldc + c);
                if (EPI == 1) {
                    float2 t0 = *p0, t1 = *p1;
                    t0.x += acc[mt][nt][0]; t0.y += acc[mt][nt][1];
                    t1.x += acc[mt][nt][2]; t1.y += acc[mt][nt][3];
                    *p0 = t0; *p1 = t1;
                } else {
                    *p0 = make_float2(acc[mt][nt][0], acc[mt][nt][1]);
                    *p1 = make_float2(acc[mt][nt][2], acc[mt][nt][3]);
                }
            }
        }
    }
}

// ---------------- host-side dispatch ----------------
template <int TRANSB, int EPI, int CAUSAL, int PASSES, int KTT>
static void launch_gemm(const f16* Ah, const f16* Al, const f16* Bh, const f16* Bl,
                        float* C, f16* Ch, f16* Cl,
                        const float* Xa, const float* Xb,
                        int M, int N, int K, int lda, int ldb, int ldc,
                        int Z, int kSplit, size_t aZ, size_t bZ, size_t cZ) {
    const int astrt  = KTT + 8;
    const int ahalf  = 128 * astrt * 2;
    const int bufb   = TRANSB ? 128 * astrt * 2 : KTT * BSTRN * 2;
    const int smem   = 4 * ahalf + 2 * (PASSES - 1) * bufb;
    cudaFuncSetAttribute(gemm_hs<TRANSB, EPI, CAUSAL, PASSES, KTT>,
                         cudaFuncAttributeMaxDynamicSharedMemorySize, smem);
    dim3 grid(N / 128, M / 128, Z);
    gemm_hs<TRANSB, EPI, CAUSAL, PASSES, KTT><<<grid, 256, smem>>>(Ah, Al, Bh, Bl, C, Ch, Cl,
                                                                   Xa, Xb,
                                                                   M, N, K, lda, ldb, ldc,
                                                                   kSplit, aZ, bZ, cZ);
}

extern "C" void kernel_launch(void* const* d_in, const int* in_sizes, int n_in,
                              void* d_out, int out_size) {
    const int*   tokens      = (const int*)  d_in[0];
    const float* emb         = (const float*)d_in[1];
    const float* attn_gamma  = (const float*)d_in[2];
    const float* wq          = (const float*)d_in[3];
    const float* wk          = (const float*)d_in[4];
    const float* wv          = (const float*)d_in[5];
    const float* wo          = (const float*)d_in[6];
    const float* ff_gamma    = (const float*)d_in[7];
    const float* wi          = (const float*)d_in[8];
    const float* wg          = (const float*)d_in[9];
    const float* wfo         = (const float*)d_in[10];
    const float* final_gamma = (const float*)d_in[11];
    float* out = (float*)d_out;

    float *x, *kv, *suf, *c, *S, *f1;
    f16 *hh, *hl, *qh, *ql, *kvh, *kvl, *Ph, *Pl, *aoh, *aol, *f1h, *f1l;
    f16 *Wqh, *Wql, *Wkvh, *Wkvl, *Woh, *Wih, *Wgh, *Wfoh, *Weh;
    cudaGetSymbolAddress((void**)&x,    g_x);
    cudaGetSymbolAddress((void**)&hh,   g_hh);  cudaGetSymbolAddress((void**)&hl,  g_hl);
    cudaGetSymbolAddress((void**)&qh,   g_qh);  cudaGetSymbolAddress((void**)&ql,  g_ql);
    cudaGetSymbolAddress((void**)&kv,   g_kv);
    cudaGetSymbolAddress((void**)&kvh,  g_kvh); cudaGetSymbolAddress((void**)&kvl, g_kvl);
    cudaGetSymbolAddress((void**)&suf,  g_suf); cudaGetSymbolAddress((void**)&c,   g_c);
    cudaGetSymbolAddress((void**)&S,    g_S);
    cudaGetSymbolAddress((void**)&Ph,   g_Ph);  cudaGetSymbolAddress((void**)&Pl,  g_Pl);
    cudaGetSymbolAddress((void**)&aoh,  g_aoh); cudaGetSymbolAddress((void**)&aol, g_aol);
    cudaGetSymbolAddress((void**)&f1,   g_f1);
    cudaGetSymbolAddress((void**)&f1h,  g_f1h); cudaGetSymbolAddress((void**)&f1l, g_f1l);
    cudaGetSymbolAddress((void**)&Wqh,  w_qh);  cudaGetSymbolAddress((void**)&Wql, w_ql);
    cudaGetSymbolAddress((void**)&Wkvh, w_kvh); cudaGetSymbolAddress((void**)&Wkvl, w_kvl);
    cudaGetSymbolAddress((void**)&Woh,  w_oh);
    cudaGetSymbolAddress((void**)&Wih,  w_ih);
    cudaGetSymbolAddress((void**)&Wgh,  w_gh);
    cudaGetSymbolAddress((void**)&Wfoh, w_foh);
    cudaGetSymbolAddress((void**)&Weh,  w_eh);

    auto cvtp = [](const float* in, f16* h, f16* l, size_t n) {
        cvt_pair_kernel<<<(unsigned)(n / 1024), 256>>>(in, h, l);
    };
    auto cvts = [](const float* in, f16* h, size_t n) {
        cvt_half_kernel<<<(unsigned)(n / 1024), 256>>>(in, h);
    };

    // ---- weight pre-split (captured; runs each replay) ----
    cvtp(wq,  Wqh,  Wql, (size_t)NLAYER * DMODEL * INNERD);
    cvts(wo,  Woh,  (size_t)NLAYER * INNERD * DMODEL);
    cvts(wi,  Wih,  (size_t)NLAYER * DMODEL * FFI);
    cvts(wg,  Wgh,  (size_t)NLAYER * DMODEL * FFI);
    cvts(wfo, Wfoh, (size_t)NLAYER * FFI * DMODEL);
    cvts(emb, Weh,  (size_t)VOCAB * DMODEL);
    for (int l = 0; l < NLAYER; ++l) {
        const size_t okv = (size_t)l * DMODEL * DHEAD;
        const size_t okvW = (size_t)l * DMODEL * 256;
        cvt_pair_cols_kernel<<<(DMODEL * DHEAD) / 1024, 256>>>(wk + okv, Wkvh + okvW, Wkvl + okvW, 0);
        cvt_pair_cols_kernel<<<(DMODEL * DHEAD) / 1024, 256>>>(wv + okv, Wkvh + okvW, Wkvl + okvW, 128);
    }

    embed_kernel<<<NT, 256>>>(tokens, emb, x);

    for (int l = 0; l < NLAYER; ++l) {
        const size_t oq   = (size_t)l * DMODEL * INNERD;
        const size_t okvW = (size_t)l * DMODEL * 256;
        const size_t oi   = (size_t)l * DMODEL * FFI;
        const size_t ofo  = (size_t)l * FFI * DMODEL;

        // --- attention ---
        rmsnorm_pair_kernel<<<NT, 256>>>(x, attn_gamma + (size_t)l * DMODEL, hh, hl);
        // q projection: full 3-pass (feeds S), KT=32 (occ 2 at 3-pass smem)
        launch_gemm<0, 3, 0, 3, 32>(hh, hl, Wqh + oq, Wql + oq, nullptr, qh, ql, nullptr, nullptr,
                                    NT, INNERD, DMODEL, DMODEL, INNERD, INNERD, 1, 1, 0, 0, 0);
        cudaMemsetAsync(kv, 0, NT * 256 * sizeof(float));
        // kv projection: full 3-pass, split-K 8
        launch_gemm<0, 2, 0, 3, 32>(hh, hl, Wkvh + okvW, Wkvl + okvW, kv, nullptr, nullptr, nullptr, nullptr,
                                    NT, 256, DMODEL, DMODEL, 256, 256, 8, 8, 0, 0, 0);
        cvtp(kv, kvh, kvl, (size_t)NT * 256);
        suffixv_kernel<<<NT / 128, 128>>>(kv, suf);
        // S = Q K^T: 3-pass, causal-skip upper tiles
        launch_gemm<1, 0, 1, 3, 32>(qh, ql, kvh, kvl, S, nullptr, nullptr, nullptr, nullptr,
                                    NT, NT, DHEAD, INNERD, 256, NT,
                                    NHEAD, 1, (size_t)DHEAD, 0, (size_t)NT * NT);
        softmax_kernel<<<dim3(NT, NHEAD), 256>>>(S, Ph, Pl, c);
        // PV: 2-pass KT=64, K capped at diagonal, fused ao-fix epilogue -> aoh/aol
        launch_gemm<0, 4, 2, 2, 64>(Ph, Pl, kvh + 128, nullptr, nullptr, aoh, aol, c, suf,
                                    NT, DHEAD, NT, NT, 256, INNERD,
                                    NHEAD, 1, (size_t)NT * NT, 0, (size_t)DHEAD);
        // output projection: 2-pass KT=64, accumulate into x
        launch_gemm<0, 1, 0, 2, 64>(aoh, aol, Woh + oq, nullptr, x, nullptr, nullptr, nullptr, nullptr,
                                    NT, DMODEL, INNERD, INNERD, DMODEL, DMODEL, 1, 1, 0, 0, 0);

        // --- SwiGLU FFN: all 2-pass KT=64; silu fused into wg epilogue ---
        rmsnorm_pair_kernel<<<NT, 256>>>(x, ff_gamma + (size_t)l * DMODEL, hh, hl);
        launch_gemm<0, 0, 0, 2, 64>(hh, hl, Wih + oi, nullptr, f1, nullptr, nullptr, nullptr, nullptr,
                                    NT, FFI, DMODEL, DMODEL, FFI, FFI, 1, 1, 0, 0, 0);
        launch_gemm<0, 5, 0, 2, 64>(hh, hl, Wgh + oi, nullptr, nullptr, f1h, f1l, f1, nullptr,
                                    NT, FFI, DMODEL, DMODEL, FFI, FFI, 1, 1, 0, 0, 0);
        launch_gemm<0, 1, 0, 2, 64>(f1h, f1l, Wfoh + ofo, nullptr, x, nullptr, nullptr, nullptr, nullptr,
                                    NT, DMODEL, FFI, FFI, DMODEL, DMODEL, 1, 1, 0, 0, 0);
    }

    // --- final norm + tied-embedding logits: 2-pass TN KT=64 ---
    rmsnorm_pair_kernel<<<NT, 256>>>(x, final_gamma, hh, hl);
    launch_gemm<1, 0, 0, 2, 64>(hh, hl, Weh, nullptr, out, nullptr, nullptr, nullptr, nullptr,
                                NT, VOCAB, DMODEL, DMODEL, DMODEL, VOCAB, 1, 1, 0, 0, 0);
}

// round 15
// speedup vs baseline: 1.5371x; 1.0091x over previous
#include <cuda_runtime.h>
#include <cuda_fp16.h>
#include <cstdint>
#include <math.h>

#define NT      2048
#define DMODEL  2048
#define NHEAD   16
#define DHEAD   128
#define INNERD  2048
#define FFI     8192
#define VOCAB   32000
#define NLAYER  4
#define EPSF    1e-5f
#define MASKV   1e-10f
#define BSTRN   136    // [k][n] smem stride (elems) for NN B tiles
#define L2E     1.4426950408889634f
#define PSCALE  1024.0f
#define PISCALE 9.765625e-4f

typedef __half f16;

// ---------------- scratch (static device globals; no allocations) ----------------
__device__ float g_x [NT * DMODEL];
__device__ f16   g_hh[NT * DMODEL], g_hl[NT * DMODEL];
__device__ f16   g_qh[NT * INNERD], g_ql[NT * INNERD];
__device__ float g_kv [NT * 256];
__device__ f16   g_kvh[NT * 256], g_kvl[NT * 256];      // K pair; V uses hi half only
__device__ float g_suf[NT * DHEAD];
__device__ float g_c  [NHEAD * NT];
__device__ float g_S [(size_t)NHEAD * NT * NT];
__device__ f16   g_Ph[(size_t)NHEAD * NT * NT], g_Pl[(size_t)NHEAD * NT * NT];
__device__ f16   g_aoh[NT * INNERD], g_aol[NT * INNERD];
__device__ f16   g_f1h[NT * FFI], g_f1l[NT * FFI];
// weights: pairs for precision-critical (q, kv); singles for 2-pass path
__device__ f16 w_qh [NLAYER * DMODEL * INNERD], w_ql [NLAYER * DMODEL * INNERD];
__device__ f16 w_kvh[NLAYER * DMODEL * 256],    w_kvl[NLAYER * DMODEL * 256];
__device__ f16 w_oh [NLAYER * INNERD * DMODEL];
__device__ f16 w_igh[(size_t)NLAYER * DMODEL * 2 * FFI];   // wi|wg column-interleaved
__device__ f16 w_foh[(size_t)NLAYER * FFI * DMODEL];
__device__ f16 w_eh [(size_t)VOCAB * DMODEL];

// ---------------- helpers ----------------
__device__ __forceinline__ void cpa16(uint32_t dst, const void* src) {
    asm volatile("cp.async.cg.shared.global [%0],[%1],16;" :: "r"(dst), "l"(src));
}
__device__ __forceinline__ void ldsm4(uint32_t* r, uint32_t a) {
    asm volatile("ldmatrix.sync.aligned.m8n8.x4.shared.b16 {%0,%1,%2,%3},[%4];"
                 : "=r"(r[0]), "=r"(r[1]), "=r"(r[2]), "=r"(r[3]) : "r"(a));
}
__device__ __forceinline__ void ldsm4t(uint32_t* r, uint32_t a) {
    asm volatile("ldmatrix.sync.aligned.m8n8.x4.trans.shared.b16 {%0,%1,%2,%3},[%4];"
                 : "=r"(r[0]), "=r"(r[1]), "=r"(r[2]), "=r"(r[3]) : "r"(a));
}
__device__ __forceinline__ void mma16816(float* c, const uint32_t* a, uint32_t b0, uint32_t b1) {
    asm volatile("mma.sync.aligned.m16n8k16.row.col.f32.f16.f16.f32 "
                 "{%0,%1,%2,%3},{%4,%5,%6,%7},{%8,%9},{%0,%1,%2,%3};"
                 : "+f"(c[0]), "+f"(c[1]), "+f"(c[2]), "+f"(c[3])
                 : "r"(a[0]), "r"(a[1]), "r"(a[2]), "r"(a[3]), "r"(b0), "r"(b1));
}
__device__ __forceinline__ void split1(float a, f16& h, f16& l) {
    h = __float2half_rn(a);
    l = __float2half_rn(a - __half2float(h));
}
__device__ __forceinline__ void split2_store(f16* hp, f16* lp, float a, float b) {
    f16 ha = __float2half_rn(a), hb = __float2half_rn(b);
    f16 la = __float2half_rn(a - __half2float(ha));
    f16 lb = __float2half_rn(b - __half2float(hb));
    __half2 H = __halves2half2(ha, hb);
    __half2 L = __halves2half2(la, lb);
    *(uint32_t*)hp = *(uint32_t*)&H;
    *(uint32_t*)lp = *(uint32_t*)&L;
}
__device__ __forceinline__ float silu_mul(float a, float g) {
    return a * g / (1.f + __expf(-g));
}

// ---------------- fp32 -> fp16 pair ----------------
__global__ void __launch_bounds__(256) cvt_pair_kernel(const float* __restrict__ in,
                                                       f16* __restrict__ ho, f16* __restrict__ lo) {
    size_t i = (size_t)blockIdx.x * 256 + threadIdx.x;
    float4 v = ((const float4*)in)[i];
    f16 h0, l0, h1, l1, h2, l2, h3, l3;
    split1(v.x, h0, l0); split1(v.y, h1, l1); split1(v.z, h2, l2); split1(v.w, h3, l3);
    __half2 ha = __halves2half2(h0, h1), hb = __halves2half2(h2, h3);
    __half2 la = __halves2half2(l0, l1), lb = __halves2half2(l2, l3);
    uint2 H = {*(uint32_t*)&ha, *(uint32_t*)&hb};
    uint2 L = {*(uint32_t*)&la, *(uint32_t*)&lb};
    ((uint2*)ho)[i] = H;
    ((uint2*)lo)[i] = L;
}

// ---------------- fp32 -> fp16 single ----------------
__global__ void __launch_bounds__(256) cvt_half_kernel(const float* __restrict__ in,
                                                       f16* __restrict__ out) {
    size_t i = (size_t)blockIdx.x * 256 + threadIdx.x;
    float4 v = ((const float4*)in)[i];
    __half2 a = __floats2half2_rn(v.x, v.y);
    __half2 b = __floats2half2_rn(v.z, v.w);
    uint2 o = {*(uint32_t*)&a, *(uint32_t*)&b};
    ((uint2*)out)[i] = o;
}

// ---- interleave cvt: out[d][2j]=a[d][j], out[d][2j+1]=b[d][j] (fp16 singles) ----
__global__ void __launch_bounds__(256) cvt_ilv_kernel(const float* __restrict__ a,
                                                      const float* __restrict__ b,
                                                      f16* __restrict__ out) {
    size_t i = (size_t)blockIdx.x * 256 + threadIdx.x;    // over D*FFI/2 float2 pairs
    float2 va = ((const float2*)a)[i];
    float2 vb = ((const float2*)b)[i];
    __half2 p0 = __floats2half2_rn(va.x, vb.x);
    __half2 p1 = __floats2half2_rn(va.y, vb.y);
    uint2 o = {*(uint32_t*)&p0, *(uint32_t*)&p1};
    ((uint2*)out)[i] = o;
}

// ---- strided pair cvt: in [R,128] -> out [R,256] at column offset ----
__global__ void __launch_bounds__(256) cvt_pair_cols_kernel(const float* __restrict__ in,
                                                            f16* __restrict__ ho, f16* __restrict__ lo,
                                                            int colOff) {
    size_t i = (size_t)blockIdx.x * 256 + threadIdx.x;
    int row = (int)(i >> 5);
    int col = ((int)i & 31) * 4;
    float4 v = ((const float4*)in)[i];
    size_t o = (size_t)row * 256 + colOff + col;
    f16 h0, l0, h1, l1, h2, l2, h3, l3;
    split1(v.x, h0, l0); split1(v.y, h1, l1); split1(v.z, h2, l2); split1(v.w, h3, l3);
    __half2 ha = __halves2half2(h0, h1), hb = __halves2half2(h2, h3);
    __half2 la = __halves2half2(l0, l1), lb = __halves2half2(l2, l3);
    *(uint32_t*)(ho + o)     = *(uint32_t*)&ha;
    *(uint32_t*)(ho + o + 2) = *(uint32_t*)&hb;
    *(uint32_t*)(lo + o)     = *(uint32_t*)&la;
    *(uint32_t*)(lo + o + 2) = *(uint32_t*)&lb;
}

// ---------------- embedding ----------------
__global__ void embed_kernel(const int* __restrict__ tok, const float* __restrict__ emb,
                             float* __restrict__ x) {
    int n = blockIdx.x;
    const float* src = emb + (size_t)tok[n] * DMODEL;
    float* dst = x + (size_t)n * DMODEL;
    for (int d = threadIdx.x; d < DMODEL; d += blockDim.x) dst[d] = src[d];
}

// ---------------- RMSNorm -> fp16 pair ----------------
__global__ void __launch_bounds__(256) rmsnorm_pair_kernel(const float* __restrict__ x,
                                                           const float* __restrict__ gamma,
                                                           f16* __restrict__ oh, f16* __restrict__ ol) {
    int n = blockIdx.x;
    const float* row = x + (size_t)n * DMODEL;
    float s = 0.f;
    for (int d = threadIdx.x; d < DMODEL; d += 256) { float v = row[d]; s += v * v; }
    __shared__ float red[256];
    red[threadIdx.x] = s; __syncthreads();
    #pragma unroll
    for (int k = 128; k > 0; k >>= 1) {
        if (threadIdx.x < k) red[threadIdx.x] += red[threadIdx.x + k];
        __syncthreads();
    }
    float inv = rsqrtf(red[0] * (1.0f / DMODEL) + EPSF);
    for (int d = threadIdx.x; d < DMODEL; d += 256) {
        f16 h, l; split1(row[d] * inv * gamma[d], h, l);
        oh[(size_t)n * DMODEL + d] = h;
        ol[(size_t)n * DMODEL + d] = l;
    }
}

// ---------------- suffixV ----------------
__global__ void __launch_bounds__(128) suffixv_kernel(const float* __restrict__ kv,
                                                      float* __restrict__ suf) {
    const int d = threadIdx.x;
    const int lo = blockIdx.x * 128, hi = lo + 128;
    float acc = 0.f;
    for (int j = NT - 1; j >= hi; --j)
        acc += kv[(size_t)j * 256 + 128 + d];
    for (int i = hi - 1; i >= lo; --i) {
        suf[(size_t)i * DHEAD + d] = acc;
        acc += kv[(size_t)i * 256 + 128 + d];
    }
}

// ------- softmax: visible region exact, masked region rank-1; P scaled x1024 -------
__global__ void __launch_bounds__(256) softmax_kernel(const float* __restrict__ S,
                                                      f16* __restrict__ Ph, f16* __restrict__ Pl,
                                                      float* __restrict__ C) {
    const int i = blockIdx.x, h = blockIdx.y, tid = threadIdx.x;
    const float* row = S + ((size_t)h * NT + i) * NT;
    __shared__ float sc[NT];
    __shared__ float red[256];
    const float slope = exp2f(-0.5f * (float)(h + 1));
    const float scale = 0.08838834764831845f;
    const int tileEnd = ((i >> 7) + 1) << 7;

    float mx = MASKV;
    for (int j = tid; j <= i; j += 256) {
        float v = row[j] * scale + slope * (float)j;
        sc[j] = v;
        mx = fmaxf(mx, v);
    }
    red[tid] = mx; __syncthreads();
    #pragma unroll
    for (int s = 128; s > 0; s >>= 1) {
        if (tid < s) red[tid] = fmaxf(red[tid], red[tid + s]);
        __syncthreads();
    }
    mx = red[0]; __syncthreads();

    float sum = 0.f;
    for (int j = tid; j <= i; j += 256) {
        float p = exp2f((sc[j] - mx) * L2E);
        sc[j] = p; sum += p;
    }
    red[tid] = sum; __syncthreads();
    #pragma unroll
    for (int s = 128; s > 0; s >>= 1) {
        if (tid < s) red[tid] += red[tid + s];
        __syncthreads();
    }
    const float maskexp = exp2f((MASKV - mx) * L2E);
    const float inv = 1.f / (red[0] + (float)(NT - 1 - i) * maskexp);
    const float c = maskexp * inv;
    if (tid == 0) C[(size_t)h * NT + i] = c;

    const float pw = inv * PSCALE;
    f16* ph = Ph + ((size_t)h * NT + i) * NT;
    f16* pl = Pl + ((size_t)h * NT + i) * NT;
    for (int j = tid; j < tileEnd; j += 256) {
        if (j <= i) {
            f16 hh, ll; split1(sc[j] * pw, hh, ll);
            ph[j] = hh; pl[j] = ll;
        } else {
            ph[j] = __float2half_rn(0.f);
            pl[j] = __float2half_rn(0.f);
        }
    }
}

// ================= pipelined fp16-split tensor-core GEMM =================
// PASSES=3: (aH+aL)xbH + aHxbL (err ~2^-22). PASSES=2: (aH+aL)xbH (err ~2^-12).
// KTT: k-tile depth. EPI: 0 fp32, 1 fp32 +=, 2 atomicAdd, 3 pair,
//      4 fused attn-out (acc*PISCALE + Xa[z*NT+r]*Xb[r*128+c]),
//      6 fused SwiGLU on interleaved wi|wg: out[r][c/2] = split(acc_even*silu(acc_odd)).
// CAUSAL: 0 none; 1 skip tiles with colBase>rowBase; 2 cap K at rowBase+128.
template <int TRANSB, int EPI, int CAUSAL, int PASSES, int KTT>
__global__ void __launch_bounds__(256, 2)
gemm_hs(const f16* __restrict__ Ah, const f16* __restrict__ Al,
        const f16* __restrict__ Bh, const f16* __restrict__ Bl,
        float* __restrict__ C, f16* __restrict__ Ch, f16* __restrict__ Cl,
        const float* __restrict__ Xa, const float* __restrict__ Xb,
        int M, int N, int K, int lda, int ldb, int ldc,
        int kSplit, size_t aZ, size_t bZ, size_t cZ) {
    extern __shared__ __align__(16) char smem[];
    const int tid = threadIdx.x, lane = tid & 31, warp = tid >> 5;
    const int wm = warp >> 2, wn = warp & 3;
    const int rowBase = blockIdx.y * 128, colBase = blockIdx.x * 128;
    if (CAUSAL == 1 && colBase > rowBase) return;
    const int z = blockIdx.z;
    int kStart = 0, kEnd = K;
    if (CAUSAL == 2) kEnd = rowBase + 128 < K ? rowBase + 128 : K;
    if (kSplit > 1) {
        int kl = K / kSplit; kStart = z * kl; kEnd = kStart + kl;
    } else {
        Ah += z * aZ; Al += z * aZ; Bh += z * bZ; if (PASSES == 3) Bl += z * bZ;
        if (EPI == 3 || EPI == 4 || EPI == 6) { Ch += z * cZ; Cl += z * cZ; }
        else { C += z * cZ; }
    }
    const int nk = (kEnd - kStart) / KTT;
    const uint32_t sb = (uint32_t)__cvta_generic_to_shared(smem);
    constexpr int ASTRT  = KTT + 8;                 // conflict-free ldsm stride
    constexpr int AHALF  = 128 * ASTRT * 2;         // bytes, one A half-tile
    constexpr int ASTAGE = 2 * AHALF;               // Ah+Al per stage
    constexpr int BUFB   = TRANSB ? 128 * ASTRT * 2 : KTT * BSTRN * 2;
    constexpr int NB     = PASSES - 1;              // B halves per stage
    constexpr int NLD    = KTT / 16;                // cpa16 rounds per tile

    auto load_stage = [&](int s, int kt) {
        uint32_t aOff = sb + s * ASTAGE;
        uint32_t bOff = sb + 2 * ASTAGE + s * NB * BUFB;
        #pragma unroll
        for (int r = 0; r < NLD; ++r) {
            int idx = tid + r * 256;
            int row = idx / (KTT / 8), kc = (idx % (KTT / 8)) * 8;
            uint32_t d = aOff + (row * ASTRT + kc) * 2;
            const size_t ga = (size_t)(rowBase + row) * lda + kt + kc;
            cpa16(d,         Ah + ga);
            cpa16(d + AHALF, Al + ga);
            if (!TRANSB) {
                int kr = idx >> 4, nc = (idx & 15) * 8;
                uint32_t db = bOff + (kr * BSTRN + nc) * 2;
                const size_t gb = (size_t)(kt + kr) * ldb + colBase + nc;
                cpa16(db, Bh + gb);
                if (PASSES == 3) cpa16(db + BUFB, Bl + gb);
            } else {
                int nr = idx / (KTT / 8), kc2 = (idx % (KTT / 8)) * 8;
                uint32_t db = bOff + (nr * ASTRT + kc2) * 2;
                const size_t gb = (size_t)(colBase + nr) * ldb + kt + kc2;
                cpa16(db, Bh + gb);
                if (PASSES == 3) cpa16(db + BUFB, Bl + gb);
            }
        }
        asm volatile("cp.async.commit_group;");
    };

    float acc[4][4][4];
    #pragma unroll
    for (int i = 0; i < 4; ++i)
        #pragma unroll
        for (int j = 0; j < 4; ++j)
            #pragma unroll
            for (int v = 0; v < 4; ++v) acc[i][j][v] = 0.f;

    const int l15 = lane & 15, lhi = (lane >> 4) * 8;

    load_stage(0, kStart);

    for (int it = 0; it < nk; ++it) {
        const int s = it & 1;
        if (it + 1 < nk) {
            load_stage((it + 1) & 1, kStart + (it + 1) * KTT);
            asm volatile("cp.async.wait_group 1;");
        } else {
            asm volatile("cp.async.wait_group 0;");
        }
        __syncthreads();

        const uint32_t aBase = sb + s * ASTAGE + ((wm * 64 + l15) * ASTRT + lhi) * 2;
        const uint32_t bOff  = sb + 2 * ASTAGE + s * NB * BUFB;

        #pragma unroll
        for (int ks = 0; ks < KTT; ks += 16) {
            uint32_t aH[4][4], aL[4][4], bH[2][4], bL[2][4];
            #pragma unroll
            for (int mt = 0; mt < 4; ++mt)
                ldsm4(aH[mt], aBase + ks * 2 + mt * (16 * ASTRT * 2));
            if (!TRANSB) {
                uint32_t bBase = bOff + ((l15 + ks) * BSTRN + wn * 32 + lhi) * 2;
                #pragma unroll
                for (int p = 0; p < 2; ++p) ldsm4t(bH[p], bBase + p * 32);
            } else {
                #pragma unroll
                for (int p = 0; p < 2; ++p)
                    ldsm4(bH[p], bOff + ((wn * 32 + p * 16 + l15) * ASTRT + ks + lhi) * 2);
            }
            #pragma unroll
            for (int mt = 0; mt < 4; ++mt)
                #pragma unroll
                for (int nt = 0; nt < 4; ++nt) {
                    int p = nt >> 1, su = nt & 1;
                    uint32_t b0 = TRANSB ? bH[p][su]     : bH[p][2 * su];
                    uint32_t b1 = TRANSB ? bH[p][su + 2] : bH[p][2 * su + 1];
                    mma16816(acc[mt][nt], aH[mt], b0, b1);
                }
            if (PASSES == 3) {
                if (!TRANSB) {
                    uint32_t bBase = bOff + BUFB + ((l15 + ks) * BSTRN + wn * 32 + lhi) * 2;
                    #pragma unroll
                    for (int p = 0; p < 2; ++p) ldsm4t(bL[p], bBase + p * 32);
                } else {
                    #pragma unroll
                    for (int p = 0; p < 2; ++p)
                        ldsm4(bL[p], bOff + BUFB + ((wn * 32 + p * 16 + l15) * ASTRT + ks + lhi) * 2);
                }
                #pragma unroll
                for (int mt = 0; mt < 4; ++mt)
                    #pragma unroll
                    for (int nt = 0; nt < 4; ++nt) {
                        int p = nt >> 1, su = nt & 1;
                        uint32_t b0 = TRANSB ? bL[p][su]     : bL[p][2 * su];
                        uint32_t b1 = TRANSB ? bL[p][su + 2] : bL[p][2 * su + 1];
                        mma16816(acc[mt][nt], aH[mt], b0, b1);
                    }
            }
            #pragma unroll
            for (int mt = 0; mt < 4; ++mt)
                ldsm4(aL[mt], aBase + AHALF + ks * 2 + mt * (16 * ASTRT * 2));
            #pragma unroll
            for (int mt = 0; mt < 4; ++mt)
                #pragma unroll
                for (int nt = 0; nt < 4; ++nt) {
                    int p = nt >> 1, su = nt & 1;
                    uint32_t b0 = TRANSB ? bH[p][su]     : bH[p][2 * su];
                    uint32_t b1 = TRANSB ? bH[p][su + 2] : bH[p][2 * su + 1];
                    mma16816(acc[mt][nt], aL[mt], b0, b1);
                }
        }
        __syncthreads();
    }

    // ---------- epilogue ----------
    const int r0 = rowBase + wm * 64 + (lane >> 2);
    const int c0 = colBase + wn * 32 + (lane & 3) * 2;
    #pragma unroll
    for (int mt = 0; mt < 4; ++mt) {
        #pragma unroll
        for (int nt = 0; nt < 4; ++nt) {
            int r = r0 + mt * 16, c = c0 + nt * 8;
            if (EPI == 6) {
                // c even: acc[0]=wi(c), acc[1]=wg(c+1) -> out col c/2
                int j = c >> 1;
                float v0 = silu_mul(acc[mt][nt][0], acc[mt][nt][1]);
                float v1 = silu_mul(acc[mt][nt][2], acc[mt][nt][3]);
                f16 h0, l0, h1, l1;
                split1(v0, h0, l0);
                split1(v1, h1, l1);
                Ch[(size_t)r * ldc + j] = h0;       Cl[(size_t)r * ldc + j] = l0;
                Ch[(size_t)(r + 8) * ldc + j] = h1; Cl[(size_t)(r + 8) * ldc + j] = l1;
            } else if (EPI == 4) {
                float ca = Xa[(size_t)z * NT + r];
                float cb = Xa[(size_t)z * NT + r + 8];
                float v0 = acc[mt][nt][0] * PISCALE + ca * Xb[(size_t)r * DHEAD + c];
                float v1 = acc[mt][nt][1] * PISCALE + ca * Xb[(size_t)r * DHEAD + c + 1];
                float v2 = acc[mt][nt][2] * PISCALE + cb * Xb[(size_t)(r + 8) * DHEAD + c];
                float v3 = acc[mt][nt][3] * PISCALE + cb * Xb[(size_t)(r + 8) * DHEAD + c + 1];
                split2_store(Ch + (size_t)r * ldc + c,       Cl + (size_t)r * ldc + c,       v0, v1);
                split2_store(Ch + (size_t)(r + 8) * ldc + c, Cl + (size_t)(r + 8) * ldc + c, v2, v3);
            } else if (EPI == 3) {
                split2_store(Ch + (size_t)r * ldc + c,       Cl + (size_t)r * ldc + c,
                             acc[mt][nt][0], acc[mt][nt][1]);
                split2_store(Ch + (size_t)(r + 8) * ldc + c, Cl + (size_t)(r + 8) * ldc + c,
                             acc[mt][nt][2], acc[mt][nt][3]);
            } else if (EPI == 2) {
                atomicAdd(C + (size_t)r * ldc + c,           acc[mt][nt][0]);
                atomicAdd(C + (size_t)r * ldc + c + 1,       acc[mt][nt][1]);
                atomicAdd(C + (size_t)(r + 8) * ldc + c,     acc[mt][nt][2]);
                atomicAdd(C + (size_t)(r + 8) * ldc + c + 1, acc[mt][nt][3]);
            } else {
                float2* p0 = (float2*)(C + (size_t)r * ldc + c);
                float2* p1 = (float2*)(C + (size_t)(r + 8) * ldc + c);
                if (EPI == 1) {
                    float2 t0 = *p0, t1 = *p1;
                    t0.x += acc[mt][nt][0]; t0.y += acc[mt][nt][1];
                    t1.x += acc[mt][nt][2]; t1.y += acc[mt][nt][3];
                    *p0 = t0; *p1 = t1;
                } else {
                    *p0 = make_float2(acc[mt][nt][0], acc[mt][nt][1]);
                    *p1 = make_float2(acc[mt][nt][2], acc[mt][nt][3]);
                }
            }
        }
    }
}

// ---------------- host-side dispatch ----------------
template <int TRANSB, int EPI, int CAUSAL, int PASSES, int KTT>
static void launch_gemm(const f16* Ah, const f16* Al, const f16* Bh, const f16* Bl,
                        float* C, f16* Ch, f16* Cl,
                        const float* Xa, const float* Xb,
                        int M, int N, int K, int lda, int ldb, int ldc,
                        int Z, int kSplit, size_t aZ, size_t bZ, size_t cZ) {
    const int astrt  = KTT + 8;
    const int ahalf  = 128 * astrt * 2;
    const int bufb   = TRANSB ? 128 * astrt * 2 : KTT * BSTRN * 2;
    const int smem   = 4 * ahalf + 2 * (PASSES - 1) * bufb;
    cudaFuncSetAttribute(gemm_hs<TRANSB, EPI, CAUSAL, PASSES, KTT>,
                         cudaFuncAttributeMaxDynamicSharedMemorySize, smem);
    dim3 grid(N / 128, M / 128, Z);
    gemm_hs<TRANSB, EPI, CAUSAL, PASSES, KTT><<<grid, 256, smem>>>(Ah, Al, Bh, Bl, C, Ch, Cl,
                                                                   Xa, Xb,
                                                                   M, N, K, lda, ldb, ldc,
                                                                   kSplit, aZ, bZ, cZ);
}

extern "C" void kernel_launch(void* const* d_in, const int* in_sizes, int n_in,
                              void* d_out, int out_size) {
    const int*   tokens      = (const int*)  d_in[0];
    const float* emb         = (const float*)d_in[1];
    const float* attn_gamma  = (const float*)d_in[2];
    const float* wq          = (const float*)d_in[3];
    const float* wk          = (const float*)d_in[4];
    const float* wv          = (const float*)d_in[5];
    const float* wo          = (const float*)d_in[6];
    const float* ff_gamma    = (const float*)d_in[7];
    const float* wi          = (const float*)d_in[8];
    const float* wg          = (const float*)d_in[9];
    const float* wfo         = (const float*)d_in[10];
    const float* final_gamma = (const float*)d_in[11];
    float* out = (float*)d_out;

    float *x, *kv, *suf, *c, *S;
    f16 *hh, *hl, *qh, *ql, *kvh, *kvl, *Ph, *Pl, *aoh, *aol, *f1h, *f1l;
    f16 *Wqh, *Wql, *Wkvh, *Wkvl, *Woh, *Wigh, *Wfoh, *Weh;
    cudaGetSymbolAddress((void**)&x,    g_x);
    cudaGetSymbolAddress((void**)&hh,   g_hh);  cudaGetSymbolAddress((void**)&hl,  g_hl);
    cudaGetSymbolAddress((void**)&qh,   g_qh);  cudaGetSymbolAddress((void**)&ql,  g_ql);
    cudaGetSymbolAddress((void**)&kv,   g_kv);
    cudaGetSymbolAddress((void**)&kvh,  g_kvh); cudaGetSymbolAddress((void**)&kvl, g_kvl);
    cudaGetSymbolAddress((void**)&suf,  g_suf); cudaGetSymbolAddress((void**)&c,   g_c);
    cudaGetSymbolAddress((void**)&S,    g_S);
    cudaGetSymbolAddress((void**)&Ph,   g_Ph);  cudaGetSymbolAddress((void**)&Pl,  g_Pl);
    cudaGetSymbolAddress((void**)&aoh,  g_aoh); cudaGetSymbolAddress((void**)&aol, g_aol);
    cudaGetSymbolAddress((void**)&f1h,  g_f1h); cudaGetSymbolAddress((void**)&f1l, g_f1l);
    cudaGetSymbolAddress((void**)&Wqh,  w_qh);  cudaGetSymbolAddress((void**)&Wql, w_ql);
    cudaGetSymbolAddress((void**)&Wkvh, w_kvh); cudaGetSymbolAddress((void**)&Wkvl, w_kvl);
    cudaGetSymbolAddress((void**)&Woh,  w_oh);
    cudaGetSymbolAddress((void**)&Wigh, w_igh);
    cudaGetSymbolAddress((void**)&Wfoh, w_foh);
    cudaGetSymbolAddress((void**)&Weh,  w_eh);

    auto cvtp = [](const float* in, f16* h, f16* l, size_t n) {
        cvt_pair_kernel<<<(unsigned)(n / 1024), 256>>>(in, h, l);
    };
    auto cvts = [](const float* in, f16* h, size_t n) {
        cvt_half_kernel<<<(unsigned)(n / 1024), 256>>>(in, h);
    };

    // ---- weight pre-split (captured; runs each replay) ----
    cvtp(wq,  Wqh,  Wql, (size_t)NLAYER * DMODEL * INNERD);
    cvts(wo,  Woh,  (size_t)NLAYER * INNERD * DMODEL);
    cvts(wfo, Wfoh, (size_t)NLAYER * FFI * DMODEL);
    cvts(emb, Weh,  (size_t)VOCAB * DMODEL);
    for (int l = 0; l < NLAYER; ++l) {
        const size_t okv  = (size_t)l * DMODEL * DHEAD;
        const size_t okvW = (size_t)l * DMODEL * 256;
        const size_t oig  = (size_t)l * DMODEL * FFI;
        cvt_pair_cols_kernel<<<(DMODEL * DHEAD) / 1024, 256>>>(wk + okv, Wkvh + okvW, Wkvl + okvW, 0);
        cvt_pair_cols_kernel<<<(DMODEL * DHEAD) / 1024, 256>>>(wv + okv, Wkvh + okvW, Wkvl + okvW, 128);
        cvt_ilv_kernel<<<(unsigned)((size_t)DMODEL * FFI / 512), 256>>>(
            wi + oig, wg + oig, Wigh + 2 * oig);
    }

    embed_kernel<<<NT, 256>>>(tokens, emb, x);

    for (int l = 0; l < NLAYER; ++l) {
        const size_t oq   = (size_t)l * DMODEL * INNERD;
        const size_t okvW = (size_t)l * DMODEL * 256;
        const size_t oig  = (size_t)l * DMODEL * 2 * FFI;
        const size_t ofo  = (size_t)l * FFI * DMODEL;

        // --- attention ---
        rmsnorm_pair_kernel<<<NT, 256>>>(x, attn_gamma + (size_t)l * DMODEL, hh, hl);
        // q projection: full 3-pass (feeds S), KT=32 (occ 2 at 3-pass smem)
        launch_gemm<0, 3, 0, 3, 32>(hh, hl, Wqh + oq, Wql + oq, nullptr, qh, ql, nullptr, nullptr,
                                    NT, INNERD, DMODEL, DMODEL, INNERD, INNERD, 1, 1, 0, 0, 0);
        cudaMemsetAsync(kv, 0, NT * 256 * sizeof(float));
        // kv projection: full 3-pass, split-K 8
        launch_gemm<0, 2, 0, 3, 32>(hh, hl, Wkvh + okvW, Wkvl + okvW, kv, nullptr, nullptr, nullptr, nullptr,
                                    NT, 256, DMODEL, DMODEL, 256, 256, 8, 8, 0, 0, 0);
        cvtp(kv, kvh, kvl, (size_t)NT * 256);
        suffixv_kernel<<<NT / 128, 128>>>(kv, suf);
        // S = Q K^T: 3-pass, causal-skip upper tiles
        launch_gemm<1, 0, 1, 3, 32>(qh, ql, kvh, kvl, S, nullptr, nullptr, nullptr, nullptr,
                                    NT, NT, DHEAD, INNERD, 256, NT,
                                    NHEAD, 1, (size_t)DHEAD, 0, (size_t)NT * NT);
        softmax_kernel<<<dim3(NT, NHEAD), 256>>>(S, Ph, Pl, c);
        // PV: 2-pass KT=64, K capped at diagonal, fused ao-fix epilogue -> aoh/aol
        launch_gemm<0, 4, 2, 2, 64>(Ph, Pl, kvh + 128, nullptr, nullptr, aoh, aol, c, suf,
                                    NT, DHEAD, NT, NT, 256, INNERD,
                                    NHEAD, 1, (size_t)NT * NT, 0, (size_t)DHEAD);
        // output projection: 2-pass KT=64, accumulate into x
        launch_gemm<0, 1, 0, 2, 64>(aoh, aol, Woh + oq, nullptr, x, nullptr, nullptr, nullptr, nullptr,
                                    NT, DMODEL, INNERD, INNERD, DMODEL, DMODEL, 1, 1, 0, 0, 0);

        // --- SwiGLU FFN: ONE interleaved wi|wg GEMM with fused silu epilogue ---
        rmsnorm_pair_kernel<<<NT, 256>>>(x, ff_gamma + (size_t)l * DMODEL, hh, hl);
        launch_gemm<0, 6, 0, 2, 64>(hh, hl, Wigh + oig, nullptr, nullptr, f1h, f1l, nullptr, nullptr,
                                    NT, 2 * FFI, DMODEL, DMODEL, 2 * FFI, FFI, 1, 1, 0, 0, 0);
        launch_gemm<0, 1, 0, 2, 64>(f1h, f1l, Wfoh + ofo, nullptr, x, nullptr, nullptr, nullptr, nullptr,
                                    NT, DMODEL, FFI, FFI, DMODEL, DMODEL, 1, 1, 0, 0, 0);
    }

    // --- final norm + tied-embedding logits: 2-pass TN KT=64 ---
    rmsnorm_pair_kernel<<<NT, 256>>>(x, final_gamma, hh, hl);
    launch_gemm<1, 0, 0, 2, 64>(hh, hl, Weh, nullptr, out, nullptr, nullptr, nullptr, nullptr,
                                NT, VOCAB, DMODEL, DMODEL, DMODEL, VOCAB, 1, 1, 0, 0, 0);
}

// round 16
// speedup vs baseline: 1.5463x; 1.0059x over previous
#include <cuda_runtime.h>
#include <cuda_fp16.h>
#include <cstdint>
#include <math.h>

#define NT      2048
#define DMODEL  2048
#define NHEAD   16
#define DHEAD   128
#define INNERD  2048
#define FFI     8192
#define VOCAB   32000
#define NLAYER  4
#define EPSF    1e-5f
#define MASKV   1e-10f
#define BSTRN   136    // [k][n] smem stride (elems) for NN B tiles
#define L2E     1.4426950408889634f
#define PSCALE  1024.0f
#define PISCALE 9.765625e-4f

typedef __half f16;

// ---------------- scratch (static device globals; no allocations) ----------------
__device__ float g_x [NT * DMODEL];
__device__ f16   g_hh[NT * DMODEL], g_hl[NT * DMODEL];
__device__ f16   g_qh[NT * INNERD], g_ql[NT * INNERD];
__device__ float g_kv [NT * 256];
__device__ f16   g_kvh[NT * 256], g_kvl[NT * 256];      // K pair cols 0-127; V pair cols 128-255
__device__ float g_suf[NT * DHEAD];
__device__ float g_c  [NHEAD * NT];
__device__ float g_S [(size_t)NHEAD * NT * NT];
__device__ f16   g_Ph[(size_t)NHEAD * NT * NT];          // P single (hi only)
__device__ f16   g_aoh[NT * INNERD];                     // ao single
__device__ f16   g_f1h[NT * FFI];                        // f1 single
// weights
__device__ f16 w_qh [NLAYER * DMODEL * INNERD], w_ql [NLAYER * DMODEL * INNERD];
__device__ f16 w_kvh[NLAYER * DMODEL * 256],    w_kvl[NLAYER * DMODEL * 256];
__device__ f16 w_oh [NLAYER * INNERD * DMODEL], w_ol [NLAYER * INNERD * DMODEL];
__device__ f16 w_igh[(size_t)NLAYER * DMODEL * 2 * FFI];   // wi|wg column-interleaved, single
__device__ f16 w_foh[(size_t)NLAYER * FFI * DMODEL], w_fol[(size_t)NLAYER * FFI * DMODEL];
__device__ f16 w_eh [(size_t)VOCAB * DMODEL];

// ---------------- helpers ----------------
__device__ __forceinline__ void cpa16(uint32_t dst, const void* src) {
    asm volatile("cp.async.cg.shared.global [%0],[%1],16;" :: "r"(dst), "l"(src));
}
__device__ __forceinline__ void ldsm4(uint32_t* r, uint32_t a) {
    asm volatile("ldmatrix.sync.aligned.m8n8.x4.shared.b16 {%0,%1,%2,%3},[%4];"
                 : "=r"(r[0]), "=r"(r[1]), "=r"(r[2]), "=r"(r[3]) : "r"(a));
}
__device__ __forceinline__ void ldsm4t(uint32_t* r, uint32_t a) {
    asm volatile("ldmatrix.sync.aligned.m8n8.x4.trans.shared.b16 {%0,%1,%2,%3},[%4];"
                 : "=r"(r[0]), "=r"(r[1]), "=r"(r[2]), "=r"(r[3]) : "r"(a));
}
__device__ __forceinline__ void mma16816(float* c, const uint32_t* a, uint32_t b0, uint32_t b1) {
    asm volatile("mma.sync.aligned.m16n8k16.row.col.f32.f16.f16.f32 "
                 "{%0,%1,%2,%3},{%4,%5,%6,%7},{%8,%9},{%0,%1,%2,%3};"
                 : "+f"(c[0]), "+f"(c[1]), "+f"(c[2]), "+f"(c[3])
                 : "r"(a[0]), "r"(a[1]), "r"(a[2]), "r"(a[3]), "r"(b0), "r"(b1));
}
__device__ __forceinline__ void split1(float a, f16& h, f16& l) {
    h = __float2half_rn(a);
    l = __float2half_rn(a - __half2float(h));
}
__device__ __forceinline__ void split2_store(f16* hp, f16* lp, float a, float b) {
    f16 ha = __float2half_rn(a), hb = __float2half_rn(b);
    f16 la = __float2half_rn(a - __half2float(ha));
    f16 lb = __float2half_rn(b - __half2float(hb));
    __half2 H = __halves2half2(ha, hb);
    __half2 L = __halves2half2(la, lb);
    *(uint32_t*)hp = *(uint32_t*)&H;
    *(uint32_t*)lp = *(uint32_t*)&L;
}
__device__ __forceinline__ float silu_mul(float a, float g) {
    return a * g / (1.f + __expf(-g));
}

// ---------------- fp32 -> fp16 pair ----------------
__global__ void __launch_bounds__(256) cvt_pair_kernel(const float* __restrict__ in,
                                                       f16* __restrict__ ho, f16* __restrict__ lo) {
    size_t i = (size_t)blockIdx.x * 256 + threadIdx.x;
    float4 v = ((const float4*)in)[i];
    f16 h0, l0, h1, l1, h2, l2, h3, l3;
    split1(v.x, h0, l0); split1(v.y, h1, l1); split1(v.z, h2, l2); split1(v.w, h3, l3);
    __half2 ha = __halves2half2(h0, h1), hb = __halves2half2(h2, h3);
    __half2 la = __halves2half2(l0, l1), lb = __halves2half2(l2, l3);
    uint2 H = {*(uint32_t*)&ha, *(uint32_t*)&hb};
    uint2 L = {*(uint32_t*)&la, *(uint32_t*)&lb};
    ((uint2*)ho)[i] = H;
    ((uint2*)lo)[i] = L;
}

// ---------------- fp32 -> fp16 single ----------------
__global__ void __launch_bounds__(256) cvt_half_kernel(const float* __restrict__ in,
                                                       f16* __restrict__ out) {
    size_t i = (size_t)blockIdx.x * 256 + threadIdx.x;
    float4 v = ((const float4*)in)[i];
    __half2 a = __floats2half2_rn(v.x, v.y);
    __half2 b = __floats2half2_rn(v.z, v.w);
    uint2 o = {*(uint32_t*)&a, *(uint32_t*)&b};
    ((uint2*)out)[i] = o;
}

// ---- interleave cvt: out[d][2j]=a[d][j], out[d][2j+1]=b[d][j] ----
__global__ void __launch_bounds__(256) cvt_ilv_kernel(const float* __restrict__ a,
                                                      const float* __restrict__ b,
                                                      f16* __restrict__ out) {
    size_t i = (size_t)blockIdx.x * 256 + threadIdx.x;
    float2 va = ((const float2*)a)[i];
    float2 vb = ((const float2*)b)[i];
    __half2 p0 = __floats2half2_rn(va.x, vb.x);
    __half2 p1 = __floats2half2_rn(va.y, vb.y);
    uint2 o = {*(uint32_t*)&p0, *(uint32_t*)&p1};
    ((uint2*)out)[i] = o;
}

// ---- strided pair cvt: in [R,128] -> out [R,256] at column offset ----
__global__ void __launch_bounds__(256) cvt_pair_cols_kernel(const float* __restrict__ in,
                                                            f16* __restrict__ ho, f16* __restrict__ lo,
                                                            int colOff) {
    size_t i = (size_t)blockIdx.x * 256 + threadIdx.x;
    int row = (int)(i >> 5);
    int col = ((int)i & 31) * 4;
    float4 v = ((const float4*)in)[i];
    size_t o = (size_t)row * 256 + colOff + col;
    f16 h0, l0, h1, l1, h2, l2, h3, l3;
    split1(v.x, h0, l0); split1(v.y, h1, l1); split1(v.z, h2, l2); split1(v.w, h3, l3);
    __half2 ha = __halves2half2(h0, h1), hb = __halves2half2(h2, h3);
    __half2 la = __halves2half2(l0, l1), lb = __halves2half2(l2, l3);
    *(uint32_t*)(ho + o)     = *(uint32_t*)&ha;
    *(uint32_t*)(ho + o + 2) = *(uint32_t*)&hb;
    *(uint32_t*)(lo + o)     = *(uint32_t*)&la;
    *(uint32_t*)(lo + o + 2) = *(uint32_t*)&lb;
}

// ---------------- embedding ----------------
__global__ void embed_kernel(const int* __restrict__ tok, const float* __restrict__ emb,
                             float* __restrict__ x) {
    int n = blockIdx.x;
    const float* src = emb + (size_t)tok[n] * DMODEL;
    float* dst = x + (size_t)n * DMODEL;
    for (int d = threadIdx.x; d < DMODEL; d += blockDim.x) dst[d] = src[d];
}

// ---------------- RMSNorm -> fp16 pair ----------------
__global__ void __launch_bounds__(256) rmsnorm_pair_kernel(const float* __restrict__ x,
                                                           const float* __restrict__ gamma,
                                                           f16* __restrict__ oh, f16* __restrict__ ol) {
    int n = blockIdx.x;
    const float* row = x + (size_t)n * DMODEL;
    float s = 0.f;
    for (int d = threadIdx.x; d < DMODEL; d += 256) { float v = row[d]; s += v * v; }
    __shared__ float red[256];
    red[threadIdx.x] = s; __syncthreads();
    #pragma unroll
    for (int k = 128; k > 0; k >>= 1) {
        if (threadIdx.x < k) red[threadIdx.x] += red[threadIdx.x + k];
        __syncthreads();
    }
    float inv = rsqrtf(red[0] * (1.0f / DMODEL) + EPSF);
    for (int d = threadIdx.x; d < DMODEL; d += 256) {
        f16 h, l; split1(row[d] * inv * gamma[d], h, l);
        oh[(size_t)n * DMODEL + d] = h;
        ol[(size_t)n * DMODEL + d] = l;
    }
}

// ---------------- suffixV ----------------
__global__ void __launch_bounds__(128) suffixv_kernel(const float* __restrict__ kv,
                                                      float* __restrict__ suf) {
    const int d = threadIdx.x;
    const int lo = blockIdx.x * 128, hi = lo + 128;
    float acc = 0.f;
    for (int j = NT - 1; j >= hi; --j)
        acc += kv[(size_t)j * 256 + 128 + d];
    for (int i = hi - 1; i >= lo; --i) {
        suf[(size_t)i * DHEAD + d] = acc;
        acc += kv[(size_t)i * 256 + 128 + d];
    }
}

// ------- softmax: visible exact, masked rank-1; P single (hi), scaled x1024 -------
__global__ void __launch_bounds__(256) softmax_kernel(const float* __restrict__ S,
                                                      f16* __restrict__ Ph,
                                                      float* __restrict__ C) {
    const int i = blockIdx.x, h = blockIdx.y, tid = threadIdx.x;
    const float* row = S + ((size_t)h * NT + i) * NT;
    __shared__ float sc[NT];
    __shared__ float red[256];
    const float slope = exp2f(-0.5f * (float)(h + 1));
    const float scale = 0.08838834764831845f;
    const int tileEnd = ((i >> 7) + 1) << 7;

    float mx = MASKV;
    for (int j = tid; j <= i; j += 256) {
        float v = row[j] * scale + slope * (float)j;
        sc[j] = v;
        mx = fmaxf(mx, v);
    }
    red[tid] = mx; __syncthreads();
    #pragma unroll
    for (int s = 128; s > 0; s >>= 1) {
        if (tid < s) red[tid] = fmaxf(red[tid], red[tid + s]);
        __syncthreads();
    }
    mx = red[0]; __syncthreads();

    float sum = 0.f;
    for (int j = tid; j <= i; j += 256) {
        float p = exp2f((sc[j] - mx) * L2E);
        sc[j] = p; sum += p;
    }
    red[tid] = sum; __syncthreads();
    #pragma unroll
    for (int s = 128; s > 0; s >>= 1) {
        if (tid < s) red[tid] += red[tid + s];
        __syncthreads();
    }
    const float maskexp = exp2f((MASKV - mx) * L2E);
    const float inv = 1.f / (red[0] + (float)(NT - 1 - i) * maskexp);
    const float c = maskexp * inv;
    if (tid == 0) C[(size_t)h * NT + i] = c;

    const float pw = inv * PSCALE;
    f16* ph = Ph + ((size_t)h * NT + i) * NT;
    for (int j = tid; j < tileEnd; j += 256)
        ph[j] = __float2half_rn(j <= i ? sc[j] * pw : 0.f);
}

// ================= pipelined fp16-split tensor-core GEMM =================
// Passes: aH x bH always; + aH x bL if BPAIR; + aL x bH if APAIR.
//   APAIR=1,BPAIR=1: full 3-pass (err ~2^-22).
//   APAIR=1,BPAIR=0: A-pair 2-pass (err = a x bL ~2^-12).
//   APAIR=0,BPAIR=1: B-pair 2-pass (err = aL x b ~2^-12).
// KTT: k-tile depth. EPI: 0 fp32, 1 fp32 +=, 2 atomicAdd, 3 pair store,
//      4 fused attn-out single (acc*PISCALE + Xa[z*NT+r]*Xb[r*128+c]),
//      6 fused SwiGLU single on interleaved wi|wg.
// CAUSAL: 0 none; 1 skip tiles colBase>rowBase; 2 cap K at rowBase+128.
template <int TRANSB, int EPI, int CAUSAL, int APAIR, int BPAIR, int KTT>
__global__ void __launch_bounds__(256, 2)
gemm_hs(const f16* __restrict__ Ah, const f16* __restrict__ Al,
        const f16* __restrict__ Bh, const f16* __restrict__ Bl,
        float* __restrict__ C, f16* __restrict__ Ch, f16* __restrict__ Cl,
        const float* __restrict__ Xa, const float* __restrict__ Xb,
        int M, int N, int K, int lda, int ldb, int ldc,
        int kSplit, size_t aZ, size_t bZ, size_t cZ) {
    extern __shared__ __align__(16) char smem[];
    const int tid = threadIdx.x, lane = tid & 31, warp = tid >> 5;
    const int wm = warp >> 2, wn = warp & 3;
    const int rowBase = blockIdx.y * 128, colBase = blockIdx.x * 128;
    if (CAUSAL == 1 && colBase > rowBase) return;
    const int z = blockIdx.z;
    int kStart = 0, kEnd = K;
    if (CAUSAL == 2) kEnd = rowBase + 128 < K ? rowBase + 128 : K;
    if (kSplit > 1) {
        int kl = K / kSplit; kStart = z * kl; kEnd = kStart + kl;
    } else {
        Ah += z * aZ; if (APAIR) Al += z * aZ;
        Bh += z * bZ; if (BPAIR) Bl += z * bZ;
        if (EPI == 3 || EPI == 4 || EPI == 6) { Ch += z * cZ; if (EPI == 3) Cl += z * cZ; }
        else { C += z * cZ; }
    }
    const int nk = (kEnd - kStart) / KTT;
    const uint32_t sb = (uint32_t)__cvta_generic_to_shared(smem);
    constexpr int ASTRT  = KTT + 8;
    constexpr int AHALF  = 128 * ASTRT * 2;
    constexpr int ASTAGE = (1 + APAIR) * AHALF;
    constexpr int BUFB   = TRANSB ? 128 * ASTRT * 2 : KTT * BSTRN * 2;
    constexpr int BSTAGE = (1 + BPAIR) * BUFB;
    constexpr int NLD    = KTT / 16;

    auto load_stage = [&](int s, int kt) {
        uint32_t aOff = sb + s * ASTAGE;
        uint32_t bOff = sb + 2 * ASTAGE + s * BSTAGE;
        #pragma unroll
        for (int r = 0; r < NLD; ++r) {
            int idx = tid + r * 256;
            int row = idx / (KTT / 8), kc = (idx % (KTT / 8)) * 8;
            uint32_t d = aOff + (row * ASTRT + kc) * 2;
            const size_t ga = (size_t)(rowBase + row) * lda + kt + kc;
            cpa16(d, Ah + ga);
            if (APAIR) cpa16(d + AHALF, Al + ga);
            if (!TRANSB) {
                int kr = idx >> 4, nc = (idx & 15) * 8;
                uint32_t db = bOff + (kr * BSTRN + nc) * 2;
                const size_t gb = (size_t)(kt + kr) * ldb + colBase + nc;
                cpa16(db, Bh + gb);
                if (BPAIR) cpa16(db + BUFB, Bl + gb);
            } else {
                int nr = idx / (KTT / 8), kc2 = (idx % (KTT / 8)) * 8;
                uint32_t db = bOff + (nr * ASTRT + kc2) * 2;
                const size_t gb = (size_t)(colBase + nr) * ldb + kt + kc2;
                cpa16(db, Bh + gb);
                if (BPAIR) cpa16(db + BUFB, Bl + gb);
            }
        }
        asm volatile("cp.async.commit_group;");
    };

    float acc[4][4][4];
    #pragma unroll
    for (int i = 0; i < 4; ++i)
        #pragma unroll
        for (int j = 0; j < 4; ++j)
            #pragma unroll
            for (int v = 0; v < 4; ++v) acc[i][j][v] = 0.f;

    const int l15 = lane & 15, lhi = (lane >> 4) * 8;

    load_stage(0, kStart);

    for (int it = 0; it < nk; ++it) {
        const int s = it & 1;
        if (it + 1 < nk) {
            load_stage((it + 1) & 1, kStart + (it + 1) * KTT);
            asm volatile("cp.async.wait_group 1;");
        } else {
            asm volatile("cp.async.wait_group 0;");
        }
        __syncthreads();

        const uint32_t aBase = sb + s * ASTAGE + ((wm * 64 + l15) * ASTRT + lhi) * 2;
        const uint32_t bOff  = sb + 2 * ASTAGE + s * BSTAGE;

        #pragma unroll
        for (int ks = 0; ks < KTT; ks += 16) {
            uint32_t aH[4][4], aL[4][4], bH[2][4], bL[2][4];
            #pragma unroll
            for (int mt = 0; mt < 4; ++mt)
                ldsm4(aH[mt], aBase + ks * 2 + mt * (16 * ASTRT * 2));
            if (!TRANSB) {
                uint32_t bBase = bOff + ((l15 + ks) * BSTRN + wn * 32 + lhi) * 2;
                #pragma unroll
                for (int p = 0; p < 2; ++p) ldsm4t(bH[p], bBase + p * 32);
            } else {
                #pragma unroll
                for (int p = 0; p < 2; ++p)
                    ldsm4(bH[p], bOff + ((wn * 32 + p * 16 + l15) * ASTRT + ks + lhi) * 2);
            }
            #pragma unroll
            for (int mt = 0; mt < 4; ++mt)
                #pragma unroll
                for (int nt = 0; nt < 4; ++nt) {
                    int p = nt >> 1, su = nt & 1;
                    uint32_t b0 = TRANSB ? bH[p][su]     : bH[p][2 * su];
                    uint32_t b1 = TRANSB ? bH[p][su + 2] : bH[p][2 * su + 1];
                    mma16816(acc[mt][nt], aH[mt], b0, b1);
                }
            if (BPAIR) {
                if (!TRANSB) {
                    uint32_t bBase = bOff + BUFB + ((l15 + ks) * BSTRN + wn * 32 + lhi) * 2;
                    #pragma unroll
                    for (int p = 0; p < 2; ++p) ldsm4t(bL[p], bBase + p * 32);
                } else {
                    #pragma unroll
                    for (int p = 0; p < 2; ++p)
                        ldsm4(bL[p], bOff + BUFB + ((wn * 32 + p * 16 + l15) * ASTRT + ks + lhi) * 2);
                }
                #pragma unroll
                for (int mt = 0; mt < 4; ++mt)
                    #pragma unroll
                    for (int nt = 0; nt < 4; ++nt) {
                        int p = nt >> 1, su = nt & 1;
                        uint32_t b0 = TRANSB ? bL[p][su]     : bL[p][2 * su];
                        uint32_t b1 = TRANSB ? bL[p][su + 2] : bL[p][2 * su + 1];
                        mma16816(acc[mt][nt], aH[mt], b0, b1);
                    }
            }
            if (APAIR) {
                #pragma unroll
                for (int mt = 0; mt < 4; ++mt)
                    ldsm4(aL[mt], aBase + AHALF + ks * 2 + mt * (16 * ASTRT * 2));
                #pragma unroll
                for (int mt = 0; mt < 4; ++mt)
                    #pragma unroll
                    for (int nt = 0; nt < 4; ++nt) {
                        int p = nt >> 1, su = nt & 1;
                        uint32_t b0 = TRANSB ? bH[p][su]     : bH[p][2 * su];
                        uint32_t b1 = TRANSB ? bH[p][su + 2] : bH[p][2 * su + 1];
                        mma16816(acc[mt][nt], aL[mt], b0, b1);
                    }
            }
        }
        __syncthreads();
    }

    // ---------- epilogue ----------
    const int r0 = rowBase + wm * 64 + (lane >> 2);
    const int c0 = colBase + wn * 32 + (lane & 3) * 2;
    #pragma unroll
    for (int mt = 0; mt < 4; ++mt) {
        #pragma unroll
        for (int nt = 0; nt < 4; ++nt) {
            int r = r0 + mt * 16, c = c0 + nt * 8;
            if (EPI == 6) {
                int j = c >> 1;
                Ch[(size_t)r * ldc + j]       = __float2half_rn(silu_mul(acc[mt][nt][0], acc[mt][nt][1]));
                Ch[(size_t)(r + 8) * ldc + j] = __float2half_rn(silu_mul(acc[mt][nt][2], acc[mt][nt][3]));
            } else if (EPI == 4) {
                float ca = Xa[(size_t)z * NT + r];
                float cb = Xa[(size_t)z * NT + r + 8];
                float v0 = acc[mt][nt][0] * PISCALE + ca * Xb[(size_t)r * DHEAD + c];
                float v1 = acc[mt][nt][1] * PISCALE + ca * Xb[(size_t)r * DHEAD + c + 1];
                float v2 = acc[mt][nt][2] * PISCALE + cb * Xb[(size_t)(r + 8) * DHEAD + c];
                float v3 = acc[mt][nt][3] * PISCALE + cb * Xb[(size_t)(r + 8) * DHEAD + c + 1];
                __half2 H0 = __floats2half2_rn(v0, v1);
                __half2 H1 = __floats2half2_rn(v2, v3);
                *(uint32_t*)(Ch + (size_t)r * ldc + c)       = *(uint32_t*)&H0;
                *(uint32_t*)(Ch + (size_t)(r + 8) * ldc + c) = *(uint32_t*)&H1;
            } else if (EPI == 3) {
                split2_store(Ch + (size_t)r * ldc + c,       Cl + (size_t)r * ldc + c,
                             acc[mt][nt][0], acc[mt][nt][1]);
                split2_store(Ch + (size_t)(r + 8) * ldc + c, Cl + (size_t)(r + 8) * ldc + c,
                             acc[mt][nt][2], acc[mt][nt][3]);
            } else if (EPI == 2) {
                atomicAdd(C + (size_t)r * ldc + c,           acc[mt][nt][0]);
                atomicAdd(C + (size_t)r * ldc + c + 1,       acc[mt][nt][1]);
                atomicAdd(C + (size_t)(r + 8) * ldc + c,     acc[mt][nt][2]);
                atomicAdd(C + (size_t)(r + 8) * ldc + c + 1, acc[mt][nt][3]);
            } else {
                float2* p0 = (float2*)(C + (size_t)r * ldc + c);
                float2* p1 = (float2*)(C + (size_t)(r + 8) * ldc + c);
                if (EPI == 1) {
                    float2 t0 = *p0, t1 = *p1;
                    t0.x += acc[mt][nt][0]; t0.y += acc[mt][nt][1];
                    t1.x += acc[mt][nt][2]; t1.y += acc[mt][nt][3];
                    *p0 = t0; *p1 = t1;
                } else {
                    *p0 = make_float2(acc[mt][nt][0], acc[mt][nt][1]);
                    *p1 = make_float2(acc[mt][nt][2], acc[mt][nt][3]);
                }
            }
        }
    }
}

// ---------------- host-side dispatch ----------------
template <int TRANSB, int EPI, int CAUSAL, int APAIR, int BPAIR, int KTT>
static void launch_gemm(const f16* Ah, const f16* Al, const f16* Bh, const f16* Bl,
                        float* C, f16* Ch, f16* Cl,
                        const float* Xa, const float* Xb,
                        int M, int N, int K, int lda, int ldb, int ldc,
                        int Z, int kSplit, size_t aZ, size_t bZ, size_t cZ) {
    const int astrt  = KTT + 8;
    const int ahalf  = 128 * astrt * 2;
    const int bufb   = TRANSB ? 128 * astrt * 2 : KTT * BSTRN * 2;
    const int smem   = 2 * (1 + APAIR) * ahalf + 2 * (1 + BPAIR) * bufb;
    cudaFuncSetAttribute(gemm_hs<TRANSB, EPI, CAUSAL, APAIR, BPAIR, KTT>,
                         cudaFuncAttributeMaxDynamicSharedMemorySize, smem);
    dim3 grid(N / 128, M / 128, Z);
    gemm_hs<TRANSB, EPI, CAUSAL, APAIR, BPAIR, KTT><<<grid, 256, smem>>>(
        Ah, Al, Bh, Bl, C, Ch, Cl, Xa, Xb, M, N, K, lda, ldb, ldc, kSplit, aZ, bZ, cZ);
}

extern "C" void kernel_launch(void* const* d_in, const int* in_sizes, int n_in,
                              void* d_out, int out_size) {
    const int*   tokens      = (const int*)  d_in[0];
    const float* emb         = (const float*)d_in[1];
    const float* attn_gamma  = (const float*)d_in[2];
    const float* wq          = (const float*)d_in[3];
    const float* wk          = (const float*)d_in[4];
    const float* wv          = (const float*)d_in[5];
    const float* wo          = (const float*)d_in[6];
    const float* ff_gamma    = (const float*)d_in[7];
    const float* wi          = (const float*)d_in[8];
    const float* wg          = (const float*)d_in[9];
    const float* wfo         = (const float*)d_in[10];
    const float* final_gamma = (const float*)d_in[11];
    float* out = (float*)d_out;

    float *x, *kv, *suf, *c, *S;
    f16 *hh, *hl, *qh, *ql, *kvh, *kvl, *Ph, *aoh, *f1h;
    f16 *Wqh, *Wql, *Wkvh, *Wkvl, *Woh, *Wol, *Wigh, *Wfoh, *Wfol, *Weh;
    cudaGetSymbolAddress((void**)&x,    g_x);
    cudaGetSymbolAddress((void**)&hh,   g_hh);  cudaGetSymbolAddress((void**)&hl,  g_hl);
    cudaGetSymbolAddress((void**)&qh,   g_qh);  cudaGetSymbolAddress((void**)&ql,  g_ql);
    cudaGetSymbolAddress((void**)&kv,   g_kv);
    cudaGetSymbolAddress((void**)&kvh,  g_kvh); cudaGetSymbolAddress((void**)&kvl, g_kvl);
    cudaGetSymbolAddress((void**)&suf,  g_suf); cudaGetSymbolAddress((void**)&c,   g_c);
    cudaGetSymbolAddress((void**)&S,    g_S);
    cudaGetSymbolAddress((void**)&Ph,   g_Ph);
    cudaGetSymbolAddress((void**)&aoh,  g_aoh);
    cudaGetSymbolAddress((void**)&f1h,  g_f1h);
    cudaGetSymbolAddress((void**)&Wqh,  w_qh);  cudaGetSymbolAddress((void**)&Wql, w_ql);
    cudaGetSymbolAddress((void**)&Wkvh, w_kvh); cudaGetSymbolAddress((void**)&Wkvl, w_kvl);
    cudaGetSymbolAddress((void**)&Woh,  w_oh);  cudaGetSymbolAddress((void**)&Wol, w_ol);
    cudaGetSymbolAddress((void**)&Wigh, w_igh);
    cudaGetSymbolAddress((void**)&Wfoh, w_foh); cudaGetSymbolAddress((void**)&Wfol, w_fol);
    cudaGetSymbolAddress((void**)&Weh,  w_eh);

    auto cvtp = [](const float* in, f16* h, f16* l, size_t n) {
        cvt_pair_kernel<<<(unsigned)(n / 1024), 256>>>(in, h, l);
    };
    auto cvts = [](const float* in, f16* h, size_t n) {
        cvt_half_kernel<<<(unsigned)(n / 1024), 256>>>(in, h);
    };

    // ---- weight pre-split (captured; runs each replay) ----
    cvtp(wq,  Wqh,  Wql,  (size_t)NLAYER * DMODEL * INNERD);
    cvtp(wo,  Woh,  Wol,  (size_t)NLAYER * INNERD * DMODEL);
    cvtp(wfo, Wfoh, Wfol, (size_t)NLAYER * FFI * DMODEL);
    cvts(emb, Weh,  (size_t)VOCAB * DMODEL);
    for (int l = 0; l < NLAYER; ++l) {
        const size_t okv  = (size_t)l * DMODEL * DHEAD;
        const size_t okvW = (size_t)l * DMODEL * 256;
        const size_t oig  = (size_t)l * DMODEL * FFI;
        cvt_pair_cols_kernel<<<(DMODEL * DHEAD) / 1024, 256>>>(wk + okv, Wkvh + okvW, Wkvl + okvW, 0);
        cvt_pair_cols_kernel<<<(DMODEL * DHEAD) / 1024, 256>>>(wv + okv, Wkvh + okvW, Wkvl + okvW, 128);
        cvt_ilv_kernel<<<(unsigned)((size_t)DMODEL * FFI / 512), 256>>>(
            wi + oig, wg + oig, Wigh + 2 * oig);
    }

    embed_kernel<<<NT, 256>>>(tokens, emb, x);

    for (int l = 0; l < NLAYER; ++l) {
        const size_t oq   = (size_t)l * DMODEL * INNERD;
        const size_t okvW = (size_t)l * DMODEL * 256;
        const size_t oig  = (size_t)l * DMODEL * 2 * FFI;
        const size_t ofo  = (size_t)l * FFI * DMODEL;

        // --- attention ---
        rmsnorm_pair_kernel<<<NT, 256>>>(x, attn_gamma + (size_t)l * DMODEL, hh, hl);
        // q projection: full 3-pass -> q pair
        launch_gemm<0, 3, 0, 1, 1, 32>(hh, hl, Wqh + oq, Wql + oq, nullptr, qh, ql, nullptr, nullptr,
                                       NT, INNERD, DMODEL, DMODEL, INNERD, INNERD, 1, 1, 0, 0, 0);
        cudaMemsetAsync(kv, 0, NT * 256 * sizeof(float));
        // kv projection: full 3-pass, split-K 8
        launch_gemm<0, 2, 0, 1, 1, 32>(hh, hl, Wkvh + okvW, Wkvl + okvW, kv, nullptr, nullptr, nullptr, nullptr,
                                       NT, 256, DMODEL, DMODEL, 256, 256, 8, 8, 0, 0, 0);
        cvtp(kv, kvh, kvl, (size_t)NT * 256);
        suffixv_kernel<<<NT / 128, 128>>>(kv, suf);
        // S = Q K^T: 3-pass, causal-skip upper tiles
        launch_gemm<1, 0, 1, 1, 1, 32>(qh, ql, kvh, kvl, S, nullptr, nullptr, nullptr, nullptr,
                                       NT, NT, DHEAD, INNERD, 256, NT,
                                       NHEAD, 1, (size_t)DHEAD, 0, (size_t)NT * NT);
        softmax_kernel<<<dim3(NT, NHEAD), 256>>>(S, Ph, c);
        // PV: P single x V pair, K capped at diagonal, fused ao-fix -> aoh single
        launch_gemm<0, 4, 2, 0, 1, 64>(Ph, nullptr, kvh + 128, kvl + 128, nullptr, aoh, nullptr, c, suf,
                                       NT, DHEAD, NT, NT, 256, INNERD,
                                       NHEAD, 1, (size_t)NT * NT, 0, (size_t)DHEAD);
        // output projection: ao single x wo pair, accumulate into x
        launch_gemm<0, 1, 0, 0, 1, 64>(aoh, nullptr, Woh + oq, Wol + oq, x, nullptr, nullptr, nullptr, nullptr,
                                       NT, DMODEL, INNERD, INNERD, DMODEL, DMODEL, 1, 1, 0, 0, 0);

        // --- SwiGLU FFN: interleaved wi|wg GEMM (h pair x w single) -> f1 single ---
        rmsnorm_pair_kernel<<<NT, 256>>>(x, ff_gamma + (size_t)l * DMODEL, hh, hl);
        launch_gemm<0, 6, 0, 1, 0, 64>(hh, hl, Wigh + oig, nullptr, nullptr, f1h, nullptr, nullptr, nullptr,
                                       NT, 2 * FFI, DMODEL, DMODEL, 2 * FFI, FFI, 1, 1, 0, 0, 0);
        // down projection: f1 single x wfo pair, accumulate into x
        launch_gemm<0, 1, 0, 0, 1, 64>(f1h, nullptr, Wfoh + ofo, Wfol + ofo, x, nullptr, nullptr, nullptr, nullptr,
                                       NT, DMODEL, FFI, FFI, DMODEL, DMODEL, 1, 1, 0, 0, 0);
    }

    // --- final norm + tied-embedding logits: h pair x emb single, TN ---
    rmsnorm_pair_kernel<<<NT, 256>>>(x, final_gamma, hh, hl);
    launch_gemm<1, 0, 0, 1, 0, 64>(hh, hl, Weh, nullptr, out, nullptr, nullptr, nullptr, nullptr,
                                   NT, VOCAB, DMODEL, DMODEL, DMODEL, VOCAB, 1, 1, 0, 0, 0);
}